// round 1
// baseline (speedup 1.0000x reference)
#include <cuda_runtime.h>
#include <cuda_bf16.h>
#include <math.h>

// ---------------- problem constants ----------------
#define B_   4
#define S_   2048
#define D_   1024
#define H_   256
#define E_   4
#define F_   4096
#define M_   64
#define BS_  (B_ * S_)          // 8192
#define KSP_ 204                // int(2048*0.1)

// ---------------- scratch (device globals; no allocation allowed) ----------------
__device__ float g_qkv_loc[(size_t)BS_ * 3 * H_];     // 8192 x 768
__device__ float g_qkv_sp [(size_t)BS_ * 3 * H_];     // 8192 x 768
__device__ float g_scores [(size_t)B_ * S_ * S_];     // 4 x 2048 x 2048 (reused)
__device__ float g_memcat [(size_t)BS_ * 2 * H_];     // 8192 x 512  [xp | retrieved]
__device__ float g_mw     [(size_t)BS_ * M_];         // 8192 x 64
__device__ float g_hydra  [(size_t)BS_ * 4 * H_];     // 8192 x 1024 concat buffer
__device__ float g_x2     [(size_t)BS_ * D_];         // 8192 x 1024
__device__ float g_pp     [(size_t)BS_ * H_];         // 8192 x 256
__device__ float g_t      [(size_t)BS_ * 2 * H_];     // 8192 x 512
__device__ float g_rw     [(size_t)BS_ * E_];         // 8192 x 4
__device__ float g_h      [(size_t)BS_ * F_];         // 8192 x 4096 (per-expert, reused)

__device__ __forceinline__ float gelu_f(float x) {
    return 0.5f * x * (1.0f + erff(x * 0.7071067811865476f));
}

// ---------------- generic GEMM ----------------
// C[M,N] = epi( alpha * A[M,K] @ (B or B^T) + bias )
// EPI: 0 store, 1 store gelu, 2 C += v, 3 C += rowscale[row]*v
// Requirements met by all call sites: M % 128 == 0, K % 8 == 0, N % 4 == 0,
// 16B-aligned pointers, lda/ldb % 4 == 0.
template<bool TRANSB, int EPI>
__global__ __launch_bounds__(256, 2)
void gemm_k(const float* __restrict__ Ag, const float* __restrict__ Bg,
            float* __restrict__ Cg,
            int M, int N, int K, int lda, int ldb, int ldc,
            long long sA, long long sB, long long sC,
            const float* __restrict__ bias,
            const float* __restrict__ rowscale, int rs_stride, float alpha)
{
    __shared__ float As[8][128];
    __shared__ float Bs[8][128];
    const float* A = Ag + (long long)blockIdx.z * sA;
    const float* Bm = Bg + (long long)blockIdx.z * sB;
    float* C = Cg + (long long)blockIdx.z * sC;
    const int m0 = blockIdx.y * 128, n0 = blockIdx.x * 128;
    const int tid = threadIdx.x;
    const int tx = tid & 15, ty = tid >> 4;

    float acc[8][8];
#pragma unroll
    for (int i = 0; i < 8; i++)
#pragma unroll
        for (int j = 0; j < 8; j++) acc[i][j] = 0.f;

    const int am = tid >> 1, ak = (tid & 1) << 2;

    for (int k0 = 0; k0 < K; k0 += 8) {
        float4 av = *(const float4*)(A + (long long)(m0 + am) * lda + k0 + ak);
        As[ak + 0][am] = av.x; As[ak + 1][am] = av.y;
        As[ak + 2][am] = av.z; As[ak + 3][am] = av.w;
        if (!TRANSB) {
            int bk = tid >> 5, bn = (tid & 31) << 2;
            float4 bv = make_float4(0.f, 0.f, 0.f, 0.f);
            if (n0 + bn < N)
                bv = *(const float4*)(Bm + (long long)(k0 + bk) * ldb + n0 + bn);
            *(float4*)&Bs[bk][bn] = bv;
        } else {
            int bn = tid >> 1, bk = (tid & 1) << 2;
            float4 bv = make_float4(0.f, 0.f, 0.f, 0.f);
            if (n0 + bn < N)
                bv = *(const float4*)(Bm + (long long)(n0 + bn) * ldb + k0 + bk);
            Bs[bk + 0][bn] = bv.x; Bs[bk + 1][bn] = bv.y;
            Bs[bk + 2][bn] = bv.z; Bs[bk + 3][bn] = bv.w;
        }
        __syncthreads();
#pragma unroll
        for (int k = 0; k < 8; k++) {
            float4 a0 = *(float4*)&As[k][ty * 4];
            float4 a1 = *(float4*)&As[k][ty * 4 + 64];
            float4 b0 = *(float4*)&Bs[k][tx * 4];
            float4 b1 = *(float4*)&Bs[k][tx * 4 + 64];
            float a[8] = {a0.x, a0.y, a0.z, a0.w, a1.x, a1.y, a1.z, a1.w};
            float b[8] = {b0.x, b0.y, b0.z, b0.w, b1.x, b1.y, b1.z, b1.w};
#pragma unroll
            for (int i = 0; i < 8; i++)
#pragma unroll
                for (int j = 0; j < 8; j++) acc[i][j] += a[i] * b[j];
        }
        __syncthreads();
    }

#pragma unroll
    for (int i = 0; i < 8; i++) {
        int gr = m0 + ty * 4 + (i & 3) + ((i >> 2) << 6);
        float rs = 1.f;
        if (EPI == 3) rs = rowscale[(long long)gr * rs_stride];
        float* Crow = C + (long long)gr * ldc;
#pragma unroll
        for (int j = 0; j < 8; j++) {
            int gc = n0 + tx * 4 + (j & 3) + ((j >> 2) << 6);
            if (gc < N) {
                float v = acc[i][j] * alpha;
                if (bias) v += bias[gc];
                if (EPI == 0)      Crow[gc] = v;
                else if (EPI == 1) Crow[gc] = gelu_f(v);
                else if (EPI == 2) Crow[gc] += v;
                else               Crow[gc] += rs * v;
            }
        }
    }
}

static void gemm(bool transb, int epi,
                 const float* A, const float* Bm, float* C,
                 int M, int N, int K, int lda, int ldb, int ldc,
                 long long sA, long long sB, long long sC, int batch,
                 const float* bias, const float* rowscale, int rs_stride,
                 float alpha)
{
    dim3 g((N + 127) / 128, M / 128, batch), blk(256);
    if (!transb) {
        switch (epi) {
        case 0: gemm_k<false, 0><<<g, blk>>>(A, Bm, C, M, N, K, lda, ldb, ldc, sA, sB, sC, bias, rowscale, rs_stride, alpha); break;
        case 1: gemm_k<false, 1><<<g, blk>>>(A, Bm, C, M, N, K, lda, ldb, ldc, sA, sB, sC, bias, rowscale, rs_stride, alpha); break;
        case 2: gemm_k<false, 2><<<g, blk>>>(A, Bm, C, M, N, K, lda, ldb, ldc, sA, sB, sC, bias, rowscale, rs_stride, alpha); break;
        default: gemm_k<false, 3><<<g, blk>>>(A, Bm, C, M, N, K, lda, ldb, ldc, sA, sB, sC, bias, rowscale, rs_stride, alpha); break;
        }
    } else {
        gemm_k<true, 0><<<g, blk>>>(A, Bm, C, M, N, K, lda, ldb, ldc, sA, sB, sC, bias, rowscale, rs_stride, alpha);
    }
}

// ---------------- softmax over full rows of 2048 (local attention) ----------------
__global__ void softmax2048_k(float* __restrict__ Sc) {
    __shared__ float red[256];
    const int tid = threadIdx.x;
    float* p = Sc + (long long)blockIdx.x * 2048;
    float v[8];
    float mx = -3.4e38f;
#pragma unroll
    for (int i = 0; i < 8; i++) { v[i] = p[tid + i * 256]; mx = fmaxf(mx, v[i]); }
    red[tid] = mx; __syncthreads();
    for (int s = 128; s; s >>= 1) { if (tid < s) red[tid] = fmaxf(red[tid], red[tid + s]); __syncthreads(); }
    mx = red[0]; __syncthreads();
    float sum = 0.f;
#pragma unroll
    for (int i = 0; i < 8; i++) { v[i] = expf(v[i] - mx); sum += v[i]; }
    red[tid] = sum; __syncthreads();
    for (int s = 128; s; s >>= 1) { if (tid < s) red[tid] += red[tid + s]; __syncthreads(); }
    float inv = 1.f / red[0];
#pragma unroll
    for (int i = 0; i < 8; i++) p[tid + i * 256] = v[i] * inv;
}

// ---------------- sparse top-k threshold + masked softmax ----------------
// Exact kth largest via in-smem bitonic sort (2048 = power of 2).
__global__ void sparse_softmax_k(float* __restrict__ Sc) {
    __shared__ float sv[2048];
    __shared__ float srt[2048];
    __shared__ float red[256];
    const int tid = threadIdx.x;
    float* p = Sc + (long long)blockIdx.x * 2048;
#pragma unroll
    for (int i = 0; i < 8; i++) {
        float v = p[tid + i * 256];
        sv[tid + i * 256] = v; srt[tid + i * 256] = v;
    }
    __syncthreads();
    for (int k = 2; k <= 2048; k <<= 1) {
        for (int j = k >> 1; j > 0; j >>= 1) {
            for (int t = tid; t < 2048; t += 256) {
                int ixj = t ^ j;
                if (ixj > t) {
                    float a = srt[t], b = srt[ixj];
                    bool up = ((t & k) == 0);
                    if ((a > b) == up) { srt[t] = b; srt[ixj] = a; }
                }
            }
            __syncthreads();
        }
    }
    const float thr = srt[2048 - KSP_];   // kth largest (ascending sort)
    const float mx  = srt[2047];
    float e[8]; float sum = 0.f;
#pragma unroll
    for (int i = 0; i < 8; i++) {
        float v = sv[tid + i * 256];
        float ev = (v >= thr) ? expf(v - mx) : 0.f;  // masked -> exact 0, same as exp(-1e9)
        e[i] = ev; sum += ev;
    }
    red[tid] = sum; __syncthreads();
    for (int s = 128; s; s >>= 1) { if (tid < s) red[tid] += red[tid + s]; __syncthreads(); }
    float inv = 1.f / red[0];
#pragma unroll
    for (int i = 0; i < 8; i++) p[tid + i * 256] = e[i] * inv;
}

// ---------------- softmax over rows of 64 (memory weights), warp per row ----------------
__global__ void softmax64_k(float* __restrict__ mw, int rows) {
    int row = (blockIdx.x * blockDim.x + threadIdx.x) >> 5;
    int lane = threadIdx.x & 31;
    if (row >= rows) return;
    float* p = mw + (long long)row * 64;
    float a = p[lane], b = p[lane + 32];
    float mx = fmaxf(a, b);
    for (int o = 16; o; o >>= 1) mx = fmaxf(mx, __shfl_xor_sync(0xffffffffu, mx, o));
    float ea = expf(a - mx), eb = expf(b - mx);
    float s = ea + eb;
    for (int o = 16; o; o >>= 1) s += __shfl_xor_sync(0xffffffffu, s, o);
    float inv = 1.f / s;
    p[lane] = ea * inv; p[lane + 32] = eb * inv;
}

// ---------------- router: rw = softmax(x2 @ Wr + br), E = 4, warp per token ----------------
__global__ void router_k(const float* __restrict__ x2, const float* __restrict__ Wr,
                         const float* __restrict__ br, float* __restrict__ rw, int rows) {
    int tok = (blockIdx.x * blockDim.x + threadIdx.x) >> 5;
    int lane = threadIdx.x & 31;
    if (tok >= rows) return;
    const float* xr = x2 + (long long)tok * D_;
    float s0 = 0.f, s1 = 0.f, s2 = 0.f, s3 = 0.f;
    for (int d = lane; d < D_; d += 32) {
        float xv = xr[d];
        const float* w = Wr + d * 4;
        s0 += xv * w[0]; s1 += xv * w[1]; s2 += xv * w[2]; s3 += xv * w[3];
    }
    for (int o = 16; o; o >>= 1) {
        s0 += __shfl_xor_sync(0xffffffffu, s0, o);
        s1 += __shfl_xor_sync(0xffffffffu, s1, o);
        s2 += __shfl_xor_sync(0xffffffffu, s2, o);
        s3 += __shfl_xor_sync(0xffffffffu, s3, o);
    }
    if (lane == 0) {
        s0 += br[0]; s1 += br[1]; s2 += br[2]; s3 += br[3];
        float mx = fmaxf(fmaxf(s0, s1), fmaxf(s2, s3));
        float e0 = expf(s0 - mx), e1 = expf(s1 - mx), e2 = expf(s2 - mx), e3 = expf(s3 - mx);
        float inv = 1.f / (e0 + e1 + e2 + e3);
        float* o4 = rw + (long long)tok * 4;
        o4[0] = e0 * inv; o4[1] = e1 * inv; o4[2] = e2 * inv; o4[3] = e3 * inv;
    }
}

__global__ void copy_k(const float* __restrict__ a, float* __restrict__ b, int n) {
    int i = blockIdx.x * 256 + threadIdx.x;
    if (i < n) b[i] = a[i];
}

// ---------------- launch ----------------
extern "C" void kernel_launch(void* const* d_in, const int* in_sizes, int n_in,
                              void* d_out, int out_size) {
    const float* x    = (const float*)d_in[0];
    const float* WqkvL = (const float*)d_in[1];
    const float* WqkvS = (const float*)d_in[2];
    const float* memb  = (const float*)d_in[3];
    const float* Wm   = (const float*)d_in[4];
    const float* Wo   = (const float*)d_in[5];
    const float* bo   = (const float*)d_in[6];
    const float* Wi   = (const float*)d_in[7];
    const float* bi   = (const float*)d_in[8];
    const float* Wp1  = (const float*)d_in[9];
    const float* bp1  = (const float*)d_in[10];
    const float* Wp2  = (const float*)d_in[11];
    const float* bp2  = (const float*)d_in[12];
    const float* Wwb  = (const float*)d_in[13];
    const float* bwb  = (const float*)d_in[14];
    const float* Wr   = (const float*)d_in[15];
    const float* br   = (const float*)d_in[16];
    const float* We1  = (const float*)d_in[17];
    const float* be1  = (const float*)d_in[18];
    const float* We2  = (const float*)d_in[19];
    const float* be2  = (const float*)d_in[20];
    float* out = (float*)d_out;

    float *qkvL, *qkvS, *sc, *mc, *mw, *hy, *x2, *pp, *tt, *rw, *hh;
    cudaGetSymbolAddress((void**)&qkvL, g_qkv_loc);
    cudaGetSymbolAddress((void**)&qkvS, g_qkv_sp);
    cudaGetSymbolAddress((void**)&sc,   g_scores);
    cudaGetSymbolAddress((void**)&mc,   g_memcat);
    cudaGetSymbolAddress((void**)&mw,   g_mw);
    cudaGetSymbolAddress((void**)&hy,   g_hydra);
    cudaGetSymbolAddress((void**)&x2,   g_x2);
    cudaGetSymbolAddress((void**)&pp,   g_pp);
    cudaGetSymbolAddress((void**)&tt,   g_t);
    cudaGetSymbolAddress((void**)&rw,   g_rw);
    cudaGetSymbolAddress((void**)&hh,   g_h);

    const float scale = 0.0625f; // H^-0.5

    // ---- local attention branch ----
    gemm(false, 0, x, WqkvL, qkvL, BS_, 3 * H_, D_, D_, 3 * H_, 3 * H_, 0, 0, 0, 1, nullptr, nullptr, 0, 1.f);
    gemm(true, 0, qkvL, qkvL + H_, sc, S_, S_, H_,
         3 * H_, 3 * H_, S_, (long long)S_ * 3 * H_, (long long)S_ * 3 * H_, (long long)S_ * S_, B_,
         nullptr, nullptr, 0, scale);
    softmax2048_k<<<BS_, 256>>>(sc);
    gemm(false, 0, sc, qkvL + 2 * H_, hy, S_, H_, S_,
         S_, 3 * H_, 4 * H_, (long long)S_ * S_, (long long)S_ * 3 * H_, (long long)S_ * 4 * H_, B_,
         nullptr, nullptr, 0, 1.f);

    // ---- sparse attention branch ----
    gemm(false, 0, x, WqkvS, qkvS, BS_, 3 * H_, D_, D_, 3 * H_, 3 * H_, 0, 0, 0, 1, nullptr, nullptr, 0, 1.f);
    gemm(true, 0, qkvS, qkvS + H_, sc, S_, S_, H_,
         3 * H_, 3 * H_, S_, (long long)S_ * 3 * H_, (long long)S_ * 3 * H_, (long long)S_ * S_, B_,
         nullptr, nullptr, 0, scale);
    sparse_softmax_k<<<BS_, 256>>>(sc);
    gemm(false, 0, sc, qkvS + 2 * H_, hy + H_, S_, H_, S_,
         S_, 3 * H_, 4 * H_, (long long)S_ * S_, (long long)S_ * 3 * H_, (long long)S_ * 4 * H_, B_,
         nullptr, nullptr, 0, 1.f);

    // ---- memory branch ----
    gemm(false, 0, x, Wm, mc, BS_, H_, D_, D_, H_, 2 * H_, 0, 0, 0, 1, nullptr, nullptr, 0, 1.f);        // xp -> mc[:,0:256]
    gemm(true, 0, mc, memb, mw, BS_, M_, H_, 2 * H_, H_, M_, 0, 0, 0, 1, nullptr, nullptr, 0, 1.f);       // xp @ mem^T
    softmax64_k<<<(BS_ * 32 + 255) / 256, 256>>>(mw, BS_);
    gemm(false, 0, mw, memb, mc + H_, BS_, H_, M_, M_, H_, 2 * H_, 0, 0, 0, 1, nullptr, nullptr, 0, 1.f); // retrieved -> mc[:,256:512]
    gemm(false, 0, mc, Wo, hy + 2 * H_, BS_, H_, 2 * H_, 2 * H_, H_, 4 * H_, 0, 0, 0, 1, bo, nullptr, 0, 1.f);

    // ---- predictor branch ----
    gemm(false, 0, x, Wi, pp, BS_, H_, D_, D_, H_, H_, 0, 0, 0, 1, bi, nullptr, 0, 1.f);
    gemm(false, 1, pp, Wp1, tt, BS_, 2 * H_, H_, H_, 2 * H_, 2 * H_, 0, 0, 0, 1, bp1, nullptr, 0, 1.f);   // gelu
    gemm(false, 0, tt, Wp2, hy + 3 * H_, BS_, H_, 2 * H_, 2 * H_, H_, 4 * H_, 0, 0, 0, 1, bp2, nullptr, 0, 1.f);

    // ---- hydra combine: x2 = x + concat @ Wwb + bwb ----
    copy_k<<<(BS_ * D_ + 255) / 256, 256>>>(x, x2, BS_ * D_);
    gemm(false, 2, hy, Wwb, x2, BS_, D_, 4 * H_, 4 * H_, D_, D_, 0, 0, 0, 1, bwb, nullptr, 0, 1.f);

    // ---- router ----
    router_k<<<(BS_ * 32 + 255) / 256, 256>>>(x2, Wr, br, rw, BS_);

    // ---- MoE: out = x2 + sum_e rw_e * (gelu(x2@We1_e+be1_e)@We2_e + be2_e) ----
    copy_k<<<(BS_ * D_ + 255) / 256, 256>>>(x2, out, BS_ * D_);
    for (int e = 0; e < E_; e++) {
        gemm(false, 1, x2, We1 + (long long)e * D_ * F_, hh,
             BS_, F_, D_, D_, F_, F_, 0, 0, 0, 1, be1 + (long long)e * F_, nullptr, 0, 1.f);
        gemm(false, 3, hh, We2 + (long long)e * F_ * D_, out,
             BS_, D_, F_, F_, D_, D_, 0, 0, 0, 1, be2 + (long long)e * D_, rw + e, E_, 1.f);
    }
}

// round 3
// speedup vs baseline: 1.3855x; 1.3855x over previous
#include <cuda_runtime.h>
#include <cuda_bf16.h>
#include <math.h>
#include <stdint.h>

// ---------------- problem constants ----------------
#define B_   4
#define S_   2048
#define D_   1024
#define H_   256
#define E_   4
#define F_   4096
#define M_   64
#define BS_  (B_ * S_)          // 8192
#define KSP_ 204                // int(2048*0.1)

// ---------------- scratch (device globals; no allocation allowed) ----------------
__device__ float g_qkv_loc[(size_t)BS_ * 3 * H_];
__device__ float g_qkv_sp [(size_t)BS_ * 3 * H_];
__device__ float g_scores [(size_t)B_ * S_ * S_];
__device__ float g_memcat [(size_t)BS_ * 2 * H_];
__device__ float g_mw     [(size_t)BS_ * M_];
__device__ float g_hydra  [(size_t)BS_ * 4 * H_];
__device__ float g_x2     [(size_t)BS_ * D_];
__device__ float g_pp     [(size_t)BS_ * H_];
__device__ float g_t      [(size_t)BS_ * 2 * H_];
__device__ float g_rw     [(size_t)BS_ * E_];
__device__ float g_h      [(size_t)BS_ * F_];

__device__ __forceinline__ float gelu_f(float x) {
    return 0.5f * x * (1.0f + erff(x * 0.7071067811865476f));
}
__device__ __forceinline__ uint32_t f2tf32(float f) {
    uint32_t r; asm("cvt.rna.tf32.f32 %0, %1;" : "=r"(r) : "f"(f)); return r;
}
__device__ __forceinline__ void mma1688(float* c, const uint32_t* a, const uint32_t* b) {
    asm volatile("mma.sync.aligned.m16n8k8.row.col.f32.tf32.tf32.f32 "
                 "{%0,%1,%2,%3}, {%4,%5,%6,%7}, {%8,%9}, {%0,%1,%2,%3};"
                 : "+f"(c[0]), "+f"(c[1]), "+f"(c[2]), "+f"(c[3])
                 : "r"(a[0]), "r"(a[1]), "r"(a[2]), "r"(a[3]), "r"(b[0]), "r"(b[1]));
}

// ================= tf32 warp-MMA GEMM =================
// CTA tile 128x128, 8 warps (2m x 4n), warp tile 64x32, K-chunks of 32.
// SMEM layout: As/Bs as [128 rows][pitch 36] uint32 (tf32 bits), double-buffered.
// BMODE 0: B stored [N,K] k-contiguous (NT).  BMODE 1: B stored [K,N] n-contiguous (NN).
// EPI: 0 store(+bias), 1 gelu(+bias), 2 C+=v(+bias), 3 C+=rowscale*v(+bias)
#define PITCH 36
#define TCSM_WORDS (4 * 128 * PITCH)   // 73728 B

template<int BMODE, int EPI>
__global__ void __launch_bounds__(256, 1)
tc_gemm_k(const float* __restrict__ Ag, const float* __restrict__ Bg, float* __restrict__ Cg,
          int M, int N, int K, int lda, int ldb, int ldc,
          long long sA, long long sB, long long sC,
          const float* __restrict__ bias, const float* __restrict__ rowscale,
          int rs_stride, float alpha)
{
    extern __shared__ uint32_t sm[];
    uint32_t* AsB[2] = { sm,                sm + 128 * PITCH };
    uint32_t* BsB[2] = { sm + 2 * 128 * PITCH, sm + 3 * 128 * PITCH };

    const float* A = Ag + (long long)blockIdx.z * sA;
    const float* Bm = Bg + (long long)blockIdx.z * sB;
    float* C = Cg + (long long)blockIdx.z * sC;
    const int m0 = blockIdx.y * 128, n0 = blockIdx.x * 128;
    const int tid = threadIdx.x, lane = tid & 31, wid = tid >> 5;
    const int wm = (wid >> 2) * 64, wn = (wid & 3) * 32;

    float acc[4][4][4];
#pragma unroll
    for (int i = 0; i < 4; i++)
#pragma unroll
        for (int j = 0; j < 4; j++)
#pragma unroll
            for (int k = 0; k < 4; k++) acc[i][j][k] = 0.f;

    const int nch = K >> 5;

    // --- global-load / smem-store helpers ---
    const int arow = tid >> 3, ac4 = (tid & 7) << 2;   // A & BMODE0 pattern

    auto loadA = [&](int c, float4* v) {
        const float* Ak = A + (long long)m0 * lda + (c << 5);
#pragma unroll
        for (int i = 0; i < 4; i++)
            v[i] = *(const float4*)(Ak + (long long)(i * 32 + arow) * lda + ac4);
    };
    auto storeA = [&](int b, const float4* v) {
        uint32_t* dst = AsB[b];
#pragma unroll
        for (int i = 0; i < 4; i++) {
            uint32_t* p = dst + (i * 32 + arow) * PITCH + ac4;
            p[0] = f2tf32(v[i].x); p[1] = f2tf32(v[i].y);
            p[2] = f2tf32(v[i].z); p[3] = f2tf32(v[i].w);
        }
    };
    auto loadB = [&](int c, float4* v) {
        if (BMODE == 0) {
            const float* Bk = Bm + (long long)n0 * ldb + (c << 5);
#pragma unroll
            for (int i = 0; i < 4; i++)
                v[i] = *(const float4*)(Bk + (long long)(i * 32 + arow) * ldb + ac4);
        } else {
            const float* Bk = Bm + (long long)((c << 5) + lane) * ldb + n0;
#pragma unroll
            for (int i = 0; i < 4; i++)
                v[i] = *(const float4*)(Bk + ((i * 8 + wid) << 2));
        }
    };
    auto storeB = [&](int b, const float4* v) {
        uint32_t* dst = BsB[b];
        if (BMODE == 0) {
#pragma unroll
            for (int i = 0; i < 4; i++) {
                uint32_t* p = dst + (i * 32 + arow) * PITCH + ac4;
                p[0] = f2tf32(v[i].x); p[1] = f2tf32(v[i].y);
                p[2] = f2tf32(v[i].z); p[3] = f2tf32(v[i].w);
            }
        } else {
#pragma unroll
            for (int i = 0; i < 4; i++) {
                int n4 = (i * 8 + wid) << 2;      // base n of this float4
                dst[(n4 + 0) * PITCH + lane] = f2tf32(v[i].x);
                dst[(n4 + 1) * PITCH + lane] = f2tf32(v[i].y);
                dst[(n4 + 2) * PITCH + lane] = f2tf32(v[i].z);
                dst[(n4 + 3) * PITCH + lane] = f2tf32(v[i].w);
            }
        }
    };

    // prologue: chunk 0
    {
        float4 av[4], bv[4];
        loadA(0, av); loadB(0, bv);
        storeA(0, av); storeB(0, bv);
    }
    __syncthreads();

    const int fr = lane >> 2, fq = lane & 3;

    for (int c = 0; c < nch; c++) {
        const int b = c & 1;
        float4 av[4], bv[4];
        if (c + 1 < nch) { loadA(c + 1, av); loadB(c + 1, bv); }

        const uint32_t* Ab = AsB[b];
        const uint32_t* Bb = BsB[b];
#pragma unroll
        for (int ks = 0; ks < 4; ks++) {
            const int kb = ks * 8 + fq;
            uint32_t af[4][4], bf[4][2];
#pragma unroll
            for (int mt = 0; mt < 4; mt++) {
                const uint32_t* p = Ab + (wm + mt * 16 + fr) * PITCH + kb;
                af[mt][0] = p[0];
                af[mt][1] = p[8 * PITCH];
                af[mt][2] = p[4];
                af[mt][3] = p[8 * PITCH + 4];
            }
#pragma unroll
            for (int nt = 0; nt < 4; nt++) {
                const uint32_t* p = Bb + (wn + nt * 8 + fr) * PITCH + kb;
                bf[nt][0] = p[0];
                bf[nt][1] = p[4];
            }
#pragma unroll
            for (int mt = 0; mt < 4; mt++)
#pragma unroll
                for (int nt = 0; nt < 4; nt++)
                    mma1688(acc[mt][nt], af[mt], bf[nt]);
        }

        if (c + 1 < nch) {
            __syncthreads();               // consumers of buf b^1 done (read at iter c-1)
            storeA(b ^ 1, av); storeB(b ^ 1, bv);
            __syncthreads();
        }
    }

    // ---- epilogue: direct register stores ----
    const int cq = (lane & 3) * 2;
#pragma unroll
    for (int mt = 0; mt < 4; mt++) {
        int gr0 = m0 + wm + mt * 16 + fr;
        int gr1 = gr0 + 8;
        float rs0 = 1.f, rs1 = 1.f;
        if (EPI == 3) {
            rs0 = rowscale[(long long)gr0 * rs_stride];
            rs1 = rowscale[(long long)gr1 * rs_stride];
        }
#pragma unroll
        for (int nt = 0; nt < 4; nt++) {
            int gc = n0 + wn + nt * 8 + cq;
            float b0 = bias ? bias[gc] : 0.f;
            float b1 = bias ? bias[gc + 1] : 0.f;
            float v00 = acc[mt][nt][0] * alpha + b0;
            float v01 = acc[mt][nt][1] * alpha + b1;
            float v10 = acc[mt][nt][2] * alpha + b0;
            float v11 = acc[mt][nt][3] * alpha + b1;
            float* p0 = C + (long long)gr0 * ldc + gc;
            float* p1 = C + (long long)gr1 * ldc + gc;
            if (EPI == 0) {
                *(float2*)p0 = make_float2(v00, v01);
                *(float2*)p1 = make_float2(v10, v11);
            } else if (EPI == 1) {
                *(float2*)p0 = make_float2(gelu_f(v00), gelu_f(v01));
                *(float2*)p1 = make_float2(gelu_f(v10), gelu_f(v11));
            } else if (EPI == 2) {
                p0[0] += v00; p0[1] += v01;
                p1[0] += v10; p1[1] += v11;
            } else {
                p0[0] += rs0 * v00; p0[1] += rs0 * v01;
                p1[0] += rs1 * v10; p1[1] += rs1 * v11;
            }
        }
    }
}

static void tcg(int bmode, int epi,
                const float* A, const float* Bm, float* C,
                int M, int N, int K, int lda, int ldb, int ldc,
                long long sA, long long sB, long long sC, int batch,
                const float* bias, const float* rowscale, int rs_stride, float alpha)
{
    dim3 g(N / 128, M / 128, batch), blk(256);
    size_t sh = TCSM_WORDS * 4;
#define LNCH(BM, EP) do { \
    cudaFuncSetAttribute(tc_gemm_k<BM, EP>, cudaFuncAttributeMaxDynamicSharedMemorySize, (int)sh); \
    tc_gemm_k<BM, EP><<<g, blk, sh>>>(A, Bm, C, M, N, K, lda, ldb, ldc, sA, sB, sC, bias, rowscale, rs_stride, alpha); \
} while (0)
    if (bmode == 0) { LNCH(0, 0); }
    else {
        if (epi == 0)      { LNCH(1, 0); }
        else if (epi == 1) { LNCH(1, 1); }
        else if (epi == 2) { LNCH(1, 2); }
        else               { LNCH(1, 3); }
    }
#undef LNCH
}

// ================= fallback SIMT GEMM (small shapes only) =================
template<bool TRANSB, int EPI>
__global__ __launch_bounds__(256, 2)
void gemm_k(const float* __restrict__ Ag, const float* __restrict__ Bg,
            float* __restrict__ Cg,
            int M, int N, int K, int lda, int ldb, int ldc,
            long long sA, long long sB, long long sC,
            const float* __restrict__ bias,
            const float* __restrict__ rowscale, int rs_stride, float alpha)
{
    __shared__ float As[8][128];
    __shared__ float Bs[8][128];
    const float* A = Ag + (long long)blockIdx.z * sA;
    const float* Bm = Bg + (long long)blockIdx.z * sB;
    float* C = Cg + (long long)blockIdx.z * sC;
    const int m0 = blockIdx.y * 128, n0 = blockIdx.x * 128;
    const int tid = threadIdx.x;
    const int tx = tid & 15, ty = tid >> 4;

    float acc[8][8];
#pragma unroll
    for (int i = 0; i < 8; i++)
#pragma unroll
        for (int j = 0; j < 8; j++) acc[i][j] = 0.f;

    const int am = tid >> 1, ak = (tid & 1) << 2;

    for (int k0 = 0; k0 < K; k0 += 8) {
        float4 av = *(const float4*)(A + (long long)(m0 + am) * lda + k0 + ak);
        As[ak + 0][am] = av.x; As[ak + 1][am] = av.y;
        As[ak + 2][am] = av.z; As[ak + 3][am] = av.w;
        if (!TRANSB) {
            int bk = tid >> 5, bn = (tid & 31) << 2;
            float4 bv = make_float4(0.f, 0.f, 0.f, 0.f);
            if (n0 + bn < N)
                bv = *(const float4*)(Bm + (long long)(k0 + bk) * ldb + n0 + bn);
            *(float4*)&Bs[bk][bn] = bv;
        } else {
            int bn = tid >> 1, bk = (tid & 1) << 2;
            float4 bv = make_float4(0.f, 0.f, 0.f, 0.f);
            if (n0 + bn < N)
                bv = *(const float4*)(Bm + (long long)(n0 + bn) * ldb + k0 + bk);
            Bs[bk + 0][bn] = bv.x; Bs[bk + 1][bn] = bv.y;
            Bs[bk + 2][bn] = bv.z; Bs[bk + 3][bn] = bv.w;
        }
        __syncthreads();
#pragma unroll
        for (int k = 0; k < 8; k++) {
            float4 a0 = *(float4*)&As[k][ty * 4];
            float4 a1 = *(float4*)&As[k][ty * 4 + 64];
            float4 b0 = *(float4*)&Bs[k][tx * 4];
            float4 b1 = *(float4*)&Bs[k][tx * 4 + 64];
            float a[8] = {a0.x, a0.y, a0.z, a0.w, a1.x, a1.y, a1.z, a1.w};
            float b[8] = {b0.x, b0.y, b0.z, b0.w, b1.x, b1.y, b1.z, b1.w};
#pragma unroll
            for (int i = 0; i < 8; i++)
#pragma unroll
                for (int j = 0; j < 8; j++) acc[i][j] += a[i] * b[j];
        }
        __syncthreads();
    }

#pragma unroll
    for (int i = 0; i < 8; i++) {
        int gr = m0 + ty * 4 + (i & 3) + ((i >> 2) << 6);
        float rs = 1.f;
        if (EPI == 3) rs = rowscale[(long long)gr * rs_stride];
        float* Crow = C + (long long)gr * ldc;
#pragma unroll
        for (int j = 0; j < 8; j++) {
            int gc = n0 + tx * 4 + (j & 3) + ((j >> 2) << 6);
            if (gc < N) {
                float v = acc[i][j] * alpha;
                if (bias) v += bias[gc];
                if (EPI == 0)      Crow[gc] = v;
                else if (EPI == 1) Crow[gc] = gelu_f(v);
                else if (EPI == 2) Crow[gc] += v;
                else               Crow[gc] += rs * v;
            }
        }
    }
}

static void gemm(bool transb, int epi,
                 const float* A, const float* Bm, float* C,
                 int M, int N, int K, int lda, int ldb, int ldc,
                 long long sA, long long sB, long long sC, int batch,
                 const float* bias, const float* rowscale, int rs_stride,
                 float alpha)
{
    dim3 g((N + 127) / 128, M / 128, batch), blk(256);
    if (!transb) {
        gemm_k<false, 0><<<g, blk>>>(A, Bm, C, M, N, K, lda, ldb, ldc, sA, sB, sC, bias, rowscale, rs_stride, alpha);
    } else {
        gemm_k<true, 0><<<g, blk>>>(A, Bm, C, M, N, K, lda, ldb, ldc, sA, sB, sC, bias, rowscale, rs_stride, alpha);
    }
}

// ---------------- softmax over full rows of 2048 ----------------
__global__ void softmax2048_k(float* __restrict__ Sc) {
    __shared__ float red[256];
    const int tid = threadIdx.x;
    float* p = Sc + (long long)blockIdx.x * 2048;
    float v[8];
    float mx = -3.4e38f;
#pragma unroll
    for (int i = 0; i < 8; i++) { v[i] = p[tid + i * 256]; mx = fmaxf(mx, v[i]); }
    red[tid] = mx; __syncthreads();
    for (int s = 128; s; s >>= 1) { if (tid < s) red[tid] = fmaxf(red[tid], red[tid + s]); __syncthreads(); }
    mx = red[0]; __syncthreads();
    float sum = 0.f;
#pragma unroll
    for (int i = 0; i < 8; i++) { v[i] = expf(v[i] - mx); sum += v[i]; }
    red[tid] = sum; __syncthreads();
    for (int s = 128; s; s >>= 1) { if (tid < s) red[tid] += red[tid + s]; __syncthreads(); }
    float inv = 1.f / red[0];
#pragma unroll
    for (int i = 0; i < 8; i++) p[tid + i * 256] = v[i] * inv;
}

// ---------------- sparse top-k threshold + masked softmax ----------------
__global__ void sparse_softmax_k(float* __restrict__ Sc) {
    __shared__ float sv[2048];
    __shared__ float srt[2048];
    __shared__ float red[256];
    const int tid = threadIdx.x;
    float* p = Sc + (long long)blockIdx.x * 2048;
#pragma unroll
    for (int i = 0; i < 8; i++) {
        float v = p[tid + i * 256];
        sv[tid + i * 256] = v; srt[tid + i * 256] = v;
    }
    __syncthreads();
    for (int k = 2; k <= 2048; k <<= 1) {
        for (int j = k >> 1; j > 0; j >>= 1) {
            for (int t = tid; t < 2048; t += 256) {
                int ixj = t ^ j;
                if (ixj > t) {
                    float a = srt[t], b = srt[ixj];
                    bool up = ((t & k) == 0);
                    if ((a > b) == up) { srt[t] = b; srt[ixj] = a; }
                }
            }
            __syncthreads();
        }
    }
    const float thr = srt[2048 - KSP_];
    const float mx  = srt[2047];
    float e[8]; float sum = 0.f;
#pragma unroll
    for (int i = 0; i < 8; i++) {
        float v = sv[tid + i * 256];
        float ev = (v >= thr) ? expf(v - mx) : 0.f;
        e[i] = ev; sum += ev;
    }
    red[tid] = sum; __syncthreads();
    for (int s = 128; s; s >>= 1) { if (tid < s) red[tid] += red[tid + s]; __syncthreads(); }
    float inv = 1.f / red[0];
#pragma unroll
    for (int i = 0; i < 8; i++) p[tid + i * 256] = e[i] * inv;
}

// ---------------- softmax rows of 64 ----------------
__global__ void softmax64_k(float* __restrict__ mw, int rows) {
    int row = (blockIdx.x * blockDim.x + threadIdx.x) >> 5;
    int lane = threadIdx.x & 31;
    if (row >= rows) return;
    float* p = mw + (long long)row * 64;
    float a = p[lane], b = p[lane + 32];
    float mx = fmaxf(a, b);
    for (int o = 16; o; o >>= 1) mx = fmaxf(mx, __shfl_xor_sync(0xffffffffu, mx, o));
    float ea = expf(a - mx), eb = expf(b - mx);
    float s = ea + eb;
    for (int o = 16; o; o >>= 1) s += __shfl_xor_sync(0xffffffffu, s, o);
    float inv = 1.f / s;
    p[lane] = ea * inv; p[lane + 32] = eb * inv;
}

// ---------------- router ----------------
__global__ void router_k(const float* __restrict__ x2, const float* __restrict__ Wr,
                         const float* __restrict__ br, float* __restrict__ rw, int rows) {
    int tok = (blockIdx.x * blockDim.x + threadIdx.x) >> 5;
    int lane = threadIdx.x & 31;
    if (tok >= rows) return;
    const float* xr = x2 + (long long)tok * D_;
    float s0 = 0.f, s1 = 0.f, s2 = 0.f, s3 = 0.f;
    for (int d = lane; d < D_; d += 32) {
        float xv = xr[d];
        const float* w = Wr + d * 4;
        s0 += xv * w[0]; s1 += xv * w[1]; s2 += xv * w[2]; s3 += xv * w[3];
    }
    for (int o = 16; o; o >>= 1) {
        s0 += __shfl_xor_sync(0xffffffffu, s0, o);
        s1 += __shfl_xor_sync(0xffffffffu, s1, o);
        s2 += __shfl_xor_sync(0xffffffffu, s2, o);
        s3 += __shfl_xor_sync(0xffffffffu, s3, o);
    }
    if (lane == 0) {
        s0 += br[0]; s1 += br[1]; s2 += br[2]; s3 += br[3];
        float mx = fmaxf(fmaxf(s0, s1), fmaxf(s2, s3));
        float e0 = expf(s0 - mx), e1 = expf(s1 - mx), e2 = expf(s2 - mx), e3 = expf(s3 - mx);
        float inv = 1.f / (e0 + e1 + e2 + e3);
        float* o4 = rw + (long long)tok * 4;
        o4[0] = e0 * inv; o4[1] = e1 * inv; o4[2] = e2 * inv; o4[3] = e3 * inv;
    }
}

__global__ void copy_k(const float* __restrict__ a, float* __restrict__ b, int n) {
    int i = blockIdx.x * 256 + threadIdx.x;
    if (i < n) b[i] = a[i];
}

// ---------------- launch ----------------
extern "C" void kernel_launch(void* const* d_in, const int* in_sizes, int n_in,
                              void* d_out, int out_size) {
    const float* x     = (const float*)d_in[0];
    const float* WqkvL = (const float*)d_in[1];
    const float* WqkvS = (const float*)d_in[2];
    const float* memb  = (const float*)d_in[3];
    const float* Wm    = (const float*)d_in[4];
    const float* Wo    = (const float*)d_in[5];
    const float* bo    = (const float*)d_in[6];
    const float* Wi    = (const float*)d_in[7];
    const float* bi    = (const float*)d_in[8];
    const float* Wp1   = (const float*)d_in[9];
    const float* bp1   = (const float*)d_in[10];
    const float* Wp2   = (const float*)d_in[11];
    const float* bp2   = (const float*)d_in[12];
    const float* Wwb   = (const float*)d_in[13];
    const float* bwb   = (const float*)d_in[14];
    const float* Wr    = (const float*)d_in[15];
    const float* br    = (const float*)d_in[16];
    const float* We1   = (const float*)d_in[17];
    const float* be1   = (const float*)d_in[18];
    const float* We2   = (const float*)d_in[19];
    const float* be2   = (const float*)d_in[20];
    float* out = (float*)d_out;

    float *qkvL, *qkvS, *sc, *mc, *mw, *hy, *x2, *pp, *tt, *rw, *hh;
    cudaGetSymbolAddress((void**)&qkvL, g_qkv_loc);
    cudaGetSymbolAddress((void**)&qkvS, g_qkv_sp);
    cudaGetSymbolAddress((void**)&sc,   g_scores);
    cudaGetSymbolAddress((void**)&mc,   g_memcat);
    cudaGetSymbolAddress((void**)&mw,   g_mw);
    cudaGetSymbolAddress((void**)&hy,   g_hydra);
    cudaGetSymbolAddress((void**)&x2,   g_x2);
    cudaGetSymbolAddress((void**)&pp,   g_pp);
    cudaGetSymbolAddress((void**)&tt,   g_t);
    cudaGetSymbolAddress((void**)&rw,   g_rw);
    cudaGetSymbolAddress((void**)&hh,   g_h);

    const float scale = 0.0625f; // H^-0.5

    // ---- local attention branch ----
    tcg(1, 0, x, WqkvL, qkvL, BS_, 3 * H_, D_, D_, 3 * H_, 3 * H_, 0, 0, 0, 1, nullptr, nullptr, 0, 1.f);
    tcg(0, 0, qkvL, qkvL + H_, sc, S_, S_, H_,
        3 * H_, 3 * H_, S_, (long long)S_ * 3 * H_, (long long)S_ * 3 * H_, (long long)S_ * S_, B_,
        nullptr, nullptr, 0, scale);
    softmax2048_k<<<BS_, 256>>>(sc);
    tcg(1, 0, sc, qkvL + 2 * H_, hy, S_, H_, S_,
        S_, 3 * H_, 4 * H_, (long long)S_ * S_, (long long)S_ * 3 * H_, (long long)S_ * 4 * H_, B_,
        nullptr, nullptr, 0, 1.f);

    // ---- sparse attention branch ----
    tcg(1, 0, x, WqkvS, qkvS, BS_, 3 * H_, D_, D_, 3 * H_, 3 * H_, 0, 0, 0, 1, nullptr, nullptr, 0, 1.f);
    tcg(0, 0, qkvS, qkvS + H_, sc, S_, S_, H_,
        3 * H_, 3 * H_, S_, (long long)S_ * 3 * H_, (long long)S_ * 3 * H_, (long long)S_ * S_, B_,
        nullptr, nullptr, 0, scale);
    sparse_softmax_k<<<BS_, 256>>>(sc);
    tcg(1, 0, sc, qkvS + 2 * H_, hy + H_, S_, H_, S_,
        S_, 3 * H_, 4 * H_, (long long)S_ * S_, (long long)S_ * 3 * H_, (long long)S_ * 4 * H_, B_,
        nullptr, nullptr, 0, 1.f);

    // ---- memory branch ----
    tcg(1, 0, x, Wm, mc, BS_, H_, D_, D_, H_, 2 * H_, 0, 0, 0, 1, nullptr, nullptr, 0, 1.f);
    gemm(true, 0, mc, memb, mw, BS_, M_, H_, 2 * H_, H_, M_, 0, 0, 0, 1, nullptr, nullptr, 0, 1.f);
    softmax64_k<<<(BS_ * 32 + 255) / 256, 256>>>(mw, BS_);
    gemm(false, 0, mw, memb, mc + H_, BS_, H_, M_, M_, H_, 2 * H_, 0, 0, 0, 1, nullptr, nullptr, 0, 1.f);
    tcg(1, 0, mc, Wo, hy + 2 * H_, BS_, H_, 2 * H_, 2 * H_, H_, 4 * H_, 0, 0, 0, 1, bo, nullptr, 0, 1.f);

    // ---- predictor branch ----
    tcg(1, 0, x, Wi, pp, BS_, H_, D_, D_, H_, H_, 0, 0, 0, 1, bi, nullptr, 0, 1.f);
    tcg(1, 1, pp, Wp1, tt, BS_, 2 * H_, H_, H_, 2 * H_, 2 * H_, 0, 0, 0, 1, bp1, nullptr, 0, 1.f);
    tcg(1, 0, tt, Wp2, hy + 3 * H_, BS_, H_, 2 * H_, 2 * H_, H_, 4 * H_, 0, 0, 0, 1, bp2, nullptr, 0, 1.f);

    // ---- hydra combine: x2 = x + concat @ Wwb + bwb ----
    copy_k<<<(BS_ * D_ + 255) / 256, 256>>>(x, x2, BS_ * D_);
    tcg(1, 2, hy, Wwb, x2, BS_, D_, 4 * H_, 4 * H_, D_, D_, 0, 0, 0, 1, bwb, nullptr, 0, 1.f);

    // ---- router ----
    router_k<<<(BS_ * 32 + 255) / 256, 256>>>(x2, Wr, br, rw, BS_);

    // ---- MoE ----
    copy_k<<<(BS_ * D_ + 255) / 256, 256>>>(x2, out, BS_ * D_);
    for (int e = 0; e < E_; e++) {
        tcg(1, 1, x2, We1 + (long long)e * D_ * F_, hh,
            BS_, F_, D_, D_, F_, F_, 0, 0, 0, 1, be1 + (long long)e * F_, nullptr, 0, 1.f);
        tcg(1, 3, hh, We2 + (long long)e * F_ * D_, out,
            BS_, D_, F_, F_, D_, D_, 0, 0, 0, 1, be2 + (long long)e * D_, rw + e, E_, 1.f);
    }
}

// round 4
// speedup vs baseline: 2.7378x; 1.9760x over previous
#include <cuda_runtime.h>
#include <cuda_bf16.h>
#include <math.h>
#include <stdint.h>

// ---------------- problem constants ----------------
#define B_   4
#define S_   2048
#define D_   1024
#define H_   256
#define E_   4
#define F_   4096
#define M_   64
#define BS_  (B_ * S_)          // 8192
#define KSP_ 204                // int(2048*0.1)

// ---------------- scratch (device globals; no allocation allowed) ----------------
__device__ float g_qkv_loc[(size_t)BS_ * 3 * H_];
__device__ float g_qkv_sp [(size_t)BS_ * 3 * H_];
__device__ float g_scores [(size_t)B_ * S_ * S_];
__device__ float g_memcat [(size_t)BS_ * 2 * H_];
__device__ float g_mcr    [(size_t)BS_ * 2 * H_];
__device__ float g_mw     [(size_t)BS_ * M_];
__device__ float g_hydra  [(size_t)BS_ * 4 * H_];
__device__ float g_x2     [(size_t)BS_ * D_];
__device__ float g_x2r    [(size_t)BS_ * D_];
__device__ float g_xr     [(size_t)BS_ * D_];
__device__ float g_pp     [(size_t)BS_ * H_];
__device__ float g_t      [(size_t)BS_ * 2 * H_];
__device__ float g_rw     [(size_t)BS_ * E_];
__device__ float g_h      [(size_t)BS_ * F_];
__device__ float g_vtl    [(size_t)B_ * H_ * S_];
__device__ float g_vts    [(size_t)B_ * H_ * S_];
// transposed+rounded weights [N][K]
__device__ float g_wqkvl_t[(size_t)768 * 1024];
__device__ float g_wqkvs_t[(size_t)768 * 1024];
__device__ float g_wm_t   [(size_t)256 * 1024];
__device__ float g_wo_t   [(size_t)256 * 512];
__device__ float g_wi_t   [(size_t)256 * 1024];
__device__ float g_wp1_t  [(size_t)512 * 256];
__device__ float g_wp2_t  [(size_t)256 * 512];
__device__ float g_wwb_t  [(size_t)1024 * 1024];
__device__ float g_we1_t  [(size_t)E_ * F_ * D_];
__device__ float g_we2_t  [(size_t)E_ * D_ * F_];

__device__ __forceinline__ float gelu_f(float x) {
    return 0.5f * x * (1.0f + erff(x * 0.7071067811865476f));
}
__device__ __forceinline__ uint32_t f2tf32(float f) {
    uint32_t r; asm("cvt.rna.tf32.f32 %0, %1;" : "=r"(r) : "f"(f)); return r;
}
__device__ __forceinline__ float rndf(float f) { return __uint_as_float(f2tf32(f)); }
__device__ __forceinline__ void mma1688(float* c, const uint32_t* a, const uint32_t* b) {
    asm volatile("mma.sync.aligned.m16n8k8.row.col.f32.tf32.tf32.f32 "
                 "{%0,%1,%2,%3}, {%4,%5,%6,%7}, {%8,%9}, {%0,%1,%2,%3};"
                 : "+f"(c[0]), "+f"(c[1]), "+f"(c[2]), "+f"(c[3])
                 : "r"(a[0]), "r"(a[1]), "r"(a[2]), "r"(a[3]), "r"(b[0]), "r"(b[1]));
}
__device__ __forceinline__ void cp16(uint32_t dst, const void* src) {
    asm volatile("cp.async.ca.shared.global [%0], [%1], 16;" :: "r"(dst), "l"(src));
}
#define CP_COMMIT asm volatile("cp.async.commit_group;" ::: "memory")
#define CP_WAIT1  asm volatile("cp.async.wait_group 1;" ::: "memory")
__device__ __forceinline__ uint32_t smem_u32(const void* p) {
    uint32_t a;
    asm("{ .reg .u64 t; cvta.to.shared.u64 t, %1; cvt.u32.u64 %0, t; }" : "=r"(a) : "l"(p));
    return a;
}

// ================= tf32 warp-MMA GEMM (NT, both operands pre-rounded, K-major) =================
// CTA tile 128x128, 8 warps (2m x 4n), warp 64x32, K-chunks of 32, 3-stage cp.async.
// EPI: 0 store(+bias), 1 gelu(+bias), 2 C+=v(+bias), 3 C+=rowscale*v(+bias)
// RND: round stored value to tf32 (outputs that only feed later tf32 GEMMs)
#define PITCH 36
#define ST 3
#define KC 32
#define STAGE_W (2 * 128 * PITCH)             // words per stage (A then B)
#define TC_SMEM (ST * STAGE_W * 4)            // 110592 bytes

template<int EPI, bool RND>
__global__ void __launch_bounds__(256, 2)
tc_gemm_k(const float* __restrict__ Ag, const float* __restrict__ Bg, float* __restrict__ Cg,
          int K, int lda, int ldb, int ldc,
          long long sA, long long sB, long long sC,
          const float* __restrict__ bias, const float* __restrict__ rowscale,
          int rs_stride, float alpha)
{
    extern __shared__ uint32_t sm[];
    const uint32_t smb = smem_u32(sm);
    const int tid = threadIdx.x, lane = tid & 31, wid = tid >> 5;
    const int m0 = blockIdx.y * 128, n0 = blockIdx.x * 128;
    const int wm = (wid >> 2) * 64, wn = (wid & 3) * 32;
    const int arow = tid >> 3, ac4 = (tid & 7) << 2;

    const float* A  = Ag + blockIdx.z * sA + (long long)(m0 + arow) * lda + ac4;
    const float* Bp = Bg + blockIdx.z * sB + (long long)(n0 + arow) * ldb + ac4;
    float* C = Cg + blockIdx.z * sC;

    const uint32_t myA = smb + (uint32_t)(arow * PITCH + ac4) * 4;
    const uint32_t myB = myA + 128 * PITCH * 4;

    float acc[4][4][4];
#pragma unroll
    for (int i = 0; i < 4; i++)
#pragma unroll
        for (int j = 0; j < 4; j++)
#pragma unroll
            for (int k = 0; k < 4; k++) acc[i][j][k] = 0.f;

    const int nch = K >> 5;

    auto issue = [&](int c) {
        const int s = c % ST;
        const uint32_t sa = myA + s * (STAGE_W * 4);
        const uint32_t sb = myB + s * (STAGE_W * 4);
        const float* ga = A + c * KC;
        const float* gb = Bp + c * KC;
#pragma unroll
        for (int i = 0; i < 4; i++) {
            cp16(sa + i * (32 * PITCH * 4), ga + (long long)i * 32 * lda);
            cp16(sb + i * (32 * PITCH * 4), gb + (long long)i * 32 * ldb);
        }
    };

    issue(0); CP_COMMIT;
    issue(1); CP_COMMIT;

    const int fr = lane >> 2, fq = lane & 3;

    for (int c = 0; c < nch; c++) {
        CP_WAIT1;
        __syncthreads();
        if (c + ST - 1 < nch) issue(c + ST - 1);
        CP_COMMIT;

        const uint32_t* Ab = sm + (c % ST) * STAGE_W;
        const uint32_t* Bb = Ab + 128 * PITCH;
#pragma unroll
        for (int ks = 0; ks < 4; ks++) {
            const int kb = ks * 8 + fq;
            uint32_t af[4][4], bf[4][2];
#pragma unroll
            for (int mt = 0; mt < 4; mt++) {
                const uint32_t* p = Ab + (wm + mt * 16 + fr) * PITCH + kb;
                af[mt][0] = p[0];
                af[mt][1] = p[8 * PITCH];
                af[mt][2] = p[4];
                af[mt][3] = p[8 * PITCH + 4];
            }
#pragma unroll
            for (int nt = 0; nt < 4; nt++) {
                const uint32_t* p = Bb + (wn + nt * 8 + fr) * PITCH + kb;
                bf[nt][0] = p[0];
                bf[nt][1] = p[4];
            }
#pragma unroll
            for (int mt = 0; mt < 4; mt++)
#pragma unroll
                for (int nt = 0; nt < 4; nt++)
                    mma1688(acc[mt][nt], af[mt], bf[nt]);
        }
    }

    // ---- epilogue ----
    const int cq = (lane & 3) * 2;
#pragma unroll
    for (int mt = 0; mt < 4; mt++) {
        int gr0 = m0 + wm + mt * 16 + fr;
        int gr1 = gr0 + 8;
        float rs0 = 1.f, rs1 = 1.f;
        if (EPI == 3) {
            rs0 = rowscale[(long long)gr0 * rs_stride];
            rs1 = rowscale[(long long)gr1 * rs_stride];
        }
#pragma unroll
        for (int nt = 0; nt < 4; nt++) {
            int gc = n0 + wn + nt * 8 + cq;
            float b0 = bias ? bias[gc] : 0.f;
            float b1 = bias ? bias[gc + 1] : 0.f;
            float v00 = acc[mt][nt][0] * alpha + b0;
            float v01 = acc[mt][nt][1] * alpha + b1;
            float v10 = acc[mt][nt][2] * alpha + b0;
            float v11 = acc[mt][nt][3] * alpha + b1;
            float* p0 = C + (long long)gr0 * ldc + gc;
            float* p1 = C + (long long)gr1 * ldc + gc;
            if (EPI == 1) {
                v00 = gelu_f(v00); v01 = gelu_f(v01);
                v10 = gelu_f(v10); v11 = gelu_f(v11);
            }
            if (RND) {
                v00 = rndf(v00); v01 = rndf(v01);
                v10 = rndf(v10); v11 = rndf(v11);
            }
            if (EPI == 0 || EPI == 1) {
                *(float2*)p0 = make_float2(v00, v01);
                *(float2*)p1 = make_float2(v10, v11);
            } else if (EPI == 2) {
                p0[0] += v00; p0[1] += v01;
                p1[0] += v10; p1[1] += v11;
            } else {
                p0[0] += rs0 * v00; p0[1] += rs0 * v01;
                p1[0] += rs1 * v10; p1[1] += rs1 * v11;
            }
        }
    }
}

static void tcg(int epi, bool rnd,
                const float* A, const float* Bm, float* C,
                int M, int N, int K, int lda, int ldb, int ldc,
                long long sA, long long sB, long long sC, int batch,
                const float* bias, const float* rowscale, int rs_stride, float alpha)
{
    dim3 g(N / 128, M / 128, batch), blk(256);
#define LNCH(EP, RN) do { \
    cudaFuncSetAttribute(tc_gemm_k<EP, RN>, cudaFuncAttributeMaxDynamicSharedMemorySize, TC_SMEM); \
    tc_gemm_k<EP, RN><<<g, blk, TC_SMEM>>>(A, Bm, C, K, lda, ldb, ldc, sA, sB, sC, bias, rowscale, rs_stride, alpha); \
} while (0)
    if (epi == 0) { if (rnd) LNCH(0, true); else LNCH(0, false); }
    else if (epi == 1) LNCH(1, true);
    else if (epi == 2) LNCH(2, false);
    else LNCH(3, false);
#undef LNCH
}

// ================= weight round + transpose: in[K][N] -> out[N][K] (tf32-rounded) =================
__global__ void roundT_k(const float* __restrict__ in, float* __restrict__ out,
                         int K, int N, long long inS, long long outS)
{
    __shared__ float t[32][33];
    const float* ip = in + blockIdx.z * inS;
    float* op = out + blockIdx.z * outS;
    int n0 = blockIdx.x * 32, k0 = blockIdx.y * 32;
    int tx = threadIdx.x & 31, ty = threadIdx.x >> 5;
#pragma unroll
    for (int i = 0; i < 32; i += 8)
        t[ty + i][tx] = ip[(long long)(k0 + ty + i) * N + n0 + tx];
    __syncthreads();
#pragma unroll
    for (int i = 0; i < 32; i += 8)
        op[(long long)(n0 + ty + i) * K + k0 + tx] = rndf(t[tx][ty + i]);
}

__global__ void round_copy_k(const float* __restrict__ a, float* __restrict__ b, int n) {
    int i = blockIdx.x * 256 + threadIdx.x;
    if (i < n) b[i] = rndf(a[i]);
}

// v transpose: qkv [BS][768] cols 512.. -> vT [B][H][S] (values already rounded)
__global__ void vtrans_k(const float* __restrict__ qkv, float* __restrict__ vT) {
    __shared__ float t[32][33];
    int s0 = blockIdx.x * 32, h0 = blockIdx.y * 32, b = blockIdx.z;
    int tx = threadIdx.x & 31, ty = threadIdx.x >> 5;
#pragma unroll
    for (int i = 0; i < 32; i += 8)
        t[ty + i][tx] = qkv[(long long)(b * S_ + s0 + ty + i) * 768 + 512 + h0 + tx];
    __syncthreads();
#pragma unroll
    for (int i = 0; i < 32; i += 8)
        vT[(long long)b * H_ * S_ + (long long)(h0 + ty + i) * S_ + s0 + tx] = t[tx][ty + i];
}

// ================= fallback SIMT GEMM (small fp32 shapes) =================
template<bool TRANSB>
__global__ __launch_bounds__(256, 2)
void gemm_k(const float* __restrict__ Ag, const float* __restrict__ Bg,
            float* __restrict__ Cg,
            int M, int N, int K, int lda, int ldb, int ldc)
{
    __shared__ float As[8][128];
    __shared__ float Bs[8][128];
    const float* A = Ag;
    const float* Bm = Bg;
    float* C = Cg;
    const int m0 = blockIdx.y * 128, n0 = blockIdx.x * 128;
    const int tid = threadIdx.x;
    const int tx = tid & 15, ty = tid >> 4;

    float acc[8][8];
#pragma unroll
    for (int i = 0; i < 8; i++)
#pragma unroll
        for (int j = 0; j < 8; j++) acc[i][j] = 0.f;

    const int am = tid >> 1, ak = (tid & 1) << 2;

    for (int k0 = 0; k0 < K; k0 += 8) {
        float4 av = *(const float4*)(A + (long long)(m0 + am) * lda + k0 + ak);
        As[ak + 0][am] = av.x; As[ak + 1][am] = av.y;
        As[ak + 2][am] = av.z; As[ak + 3][am] = av.w;
        if (!TRANSB) {
            int bk = tid >> 5, bn = (tid & 31) << 2;
            float4 bv = make_float4(0.f, 0.f, 0.f, 0.f);
            if (n0 + bn < N)
                bv = *(const float4*)(Bm + (long long)(k0 + bk) * ldb + n0 + bn);
            *(float4*)&Bs[bk][bn] = bv;
        } else {
            int bn = tid >> 1, bk = (tid & 1) << 2;
            float4 bv = make_float4(0.f, 0.f, 0.f, 0.f);
            if (n0 + bn < N)
                bv = *(const float4*)(Bm + (long long)(n0 + bn) * ldb + k0 + bk);
            Bs[bk + 0][bn] = bv.x; Bs[bk + 1][bn] = bv.y;
            Bs[bk + 2][bn] = bv.z; Bs[bk + 3][bn] = bv.w;
        }
        __syncthreads();
#pragma unroll
        for (int k = 0; k < 8; k++) {
            float4 a0 = *(float4*)&As[k][ty * 4];
            float4 a1 = *(float4*)&As[k][ty * 4 + 64];
            float4 b0 = *(float4*)&Bs[k][tx * 4];
            float4 b1 = *(float4*)&Bs[k][tx * 4 + 64];
            float a[8] = {a0.x, a0.y, a0.z, a0.w, a1.x, a1.y, a1.z, a1.w};
            float b[8] = {b0.x, b0.y, b0.z, b0.w, b1.x, b1.y, b1.z, b1.w};
#pragma unroll
            for (int i = 0; i < 8; i++)
#pragma unroll
                for (int j = 0; j < 8; j++) acc[i][j] += a[i] * b[j];
        }
        __syncthreads();
    }

#pragma unroll
    for (int i = 0; i < 8; i++) {
        int gr = m0 + ty * 4 + (i & 3) + ((i >> 2) << 6);
        float* Crow = C + (long long)gr * ldc;
#pragma unroll
        for (int j = 0; j < 8; j++) {
            int gc = n0 + tx * 4 + (j & 3) + ((j >> 2) << 6);
            if (gc < N) Crow[gc] = acc[i][j];
        }
    }
}

// ---------------- softmax over full rows of 2048 (rounded output) ----------------
__global__ void softmax2048_k(float* __restrict__ Sc) {
    __shared__ float red[256];
    const int tid = threadIdx.x;
    float* p = Sc + (long long)blockIdx.x * 2048;
    float v[8];
    float mx = -3.4e38f;
#pragma unroll
    for (int i = 0; i < 8; i++) { v[i] = p[tid + i * 256]; mx = fmaxf(mx, v[i]); }
    red[tid] = mx; __syncthreads();
    for (int s = 128; s; s >>= 1) { if (tid < s) red[tid] = fmaxf(red[tid], red[tid + s]); __syncthreads(); }
    mx = red[0]; __syncthreads();
    float sum = 0.f;
#pragma unroll
    for (int i = 0; i < 8; i++) { v[i] = expf(v[i] - mx); sum += v[i]; }
    red[tid] = sum; __syncthreads();
    for (int s = 128; s; s >>= 1) { if (tid < s) red[tid] += red[tid + s]; __syncthreads(); }
    float inv = 1.f / red[0];
#pragma unroll
    for (int i = 0; i < 8; i++) p[tid + i * 256] = rndf(v[i] * inv);
}

// ---------------- sparse top-k threshold + masked softmax (rounded output) ----------------
__global__ void sparse_softmax_k(float* __restrict__ Sc) {
    __shared__ float sv[2048];
    __shared__ float srt[2048];
    __shared__ float red[256];
    const int tid = threadIdx.x;
    float* p = Sc + (long long)blockIdx.x * 2048;
#pragma unroll
    for (int i = 0; i < 8; i++) {
        float v = p[tid + i * 256];
        sv[tid + i * 256] = v; srt[tid + i * 256] = v;
    }
    __syncthreads();
    for (int k = 2; k <= 2048; k <<= 1) {
        for (int j = k >> 1; j > 0; j >>= 1) {
            for (int t = tid; t < 2048; t += 256) {
                int ixj = t ^ j;
                if (ixj > t) {
                    float a = srt[t], b = srt[ixj];
                    bool up = ((t & k) == 0);
                    if ((a > b) == up) { srt[t] = b; srt[ixj] = a; }
                }
            }
            __syncthreads();
        }
    }
    const float thr = srt[2048 - KSP_];
    const float mx  = srt[2047];
    float e[8]; float sum = 0.f;
#pragma unroll
    for (int i = 0; i < 8; i++) {
        float v = sv[tid + i * 256];
        float ev = (v >= thr) ? expf(v - mx) : 0.f;
        e[i] = ev; sum += ev;
    }
    red[tid] = sum; __syncthreads();
    for (int s = 128; s; s >>= 1) { if (tid < s) red[tid] += red[tid + s]; __syncthreads(); }
    float inv = 1.f / red[0];
#pragma unroll
    for (int i = 0; i < 8; i++) p[tid + i * 256] = rndf(e[i] * inv);
}

// ---------------- softmax rows of 64 ----------------
__global__ void softmax64_k(float* __restrict__ mw, int rows) {
    int row = (blockIdx.x * blockDim.x + threadIdx.x) >> 5;
    int lane = threadIdx.x & 31;
    if (row >= rows) return;
    float* p = mw + (long long)row * 64;
    float a = p[lane], b = p[lane + 32];
    float mx = fmaxf(a, b);
    for (int o = 16; o; o >>= 1) mx = fmaxf(mx, __shfl_xor_sync(0xffffffffu, mx, o));
    float ea = expf(a - mx), eb = expf(b - mx);
    float s = ea + eb;
    for (int o = 16; o; o >>= 1) s += __shfl_xor_sync(0xffffffffu, s, o);
    float inv = 1.f / s;
    p[lane] = ea * inv; p[lane + 32] = eb * inv;
}

// ---------------- router ----------------
__global__ void router_k(const float* __restrict__ x2, const float* __restrict__ Wr,
                         const float* __restrict__ br, float* __restrict__ rw, int rows) {
    int tok = (blockIdx.x * blockDim.x + threadIdx.x) >> 5;
    int lane = threadIdx.x & 31;
    if (tok >= rows) return;
    const float* xr = x2 + (long long)tok * D_;
    float s0 = 0.f, s1 = 0.f, s2 = 0.f, s3 = 0.f;
    for (int d = lane; d < D_; d += 32) {
        float xv = xr[d];
        const float* w = Wr + d * 4;
        s0 += xv * w[0]; s1 += xv * w[1]; s2 += xv * w[2]; s3 += xv * w[3];
    }
    for (int o = 16; o; o >>= 1) {
        s0 += __shfl_xor_sync(0xffffffffu, s0, o);
        s1 += __shfl_xor_sync(0xffffffffu, s1, o);
        s2 += __shfl_xor_sync(0xffffffffu, s2, o);
        s3 += __shfl_xor_sync(0xffffffffu, s3, o);
    }
    if (lane == 0) {
        s0 += br[0]; s1 += br[1]; s2 += br[2]; s3 += br[3];
        float mx = fmaxf(fmaxf(s0, s1), fmaxf(s2, s3));
        float e0 = expf(s0 - mx), e1 = expf(s1 - mx), e2 = expf(s2 - mx), e3 = expf(s3 - mx);
        float inv = 1.f / (e0 + e1 + e2 + e3);
        float* o4 = rw + (long long)tok * 4;
        o4[0] = e0 * inv; o4[1] = e1 * inv; o4[2] = e2 * inv; o4[3] = e3 * inv;
    }
}

__global__ void copy_k(const float* __restrict__ a, float* __restrict__ b, int n) {
    int i = blockIdx.x * 256 + threadIdx.x;
    if (i < n) b[i] = a[i];
}

// ---------------- launch ----------------
extern "C" void kernel_launch(void* const* d_in, const int* in_sizes, int n_in,
                              void* d_out, int out_size) {
    const float* x     = (const float*)d_in[0];
    const float* WqkvL = (const float*)d_in[1];
    const float* WqkvS = (const float*)d_in[2];
    const float* memb  = (const float*)d_in[3];
    const float* Wm    = (const float*)d_in[4];
    const float* Wo    = (const float*)d_in[5];
    const float* bo    = (const float*)d_in[6];
    const float* Wi    = (const float*)d_in[7];
    const float* bi    = (const float*)d_in[8];
    const float* Wp1   = (const float*)d_in[9];
    const float* bp1   = (const float*)d_in[10];
    const float* Wp2   = (const float*)d_in[11];
    const float* bp2   = (const float*)d_in[12];
    const float* Wwb   = (const float*)d_in[13];
    const float* bwb   = (const float*)d_in[14];
    const float* Wr    = (const float*)d_in[15];
    const float* br    = (const float*)d_in[16];
    const float* We1   = (const float*)d_in[17];
    const float* be1   = (const float*)d_in[18];
    const float* We2   = (const float*)d_in[19];
    const float* be2   = (const float*)d_in[20];
    float* out = (float*)d_out;

    float *qkvL, *qkvS, *sc, *mc, *mcr, *mw, *hy, *x2, *x2r, *xr, *pp, *tt, *rw, *hh, *vtl, *vts;
    float *wqkvl_t, *wqkvs_t, *wm_t, *wo_t, *wi_t, *wp1_t, *wp2_t, *wwb_t, *we1_t, *we2_t;
    cudaGetSymbolAddress((void**)&qkvL, g_qkv_loc);
    cudaGetSymbolAddress((void**)&qkvS, g_qkv_sp);
    cudaGetSymbolAddress((void**)&sc,   g_scores);
    cudaGetSymbolAddress((void**)&mc,   g_memcat);
    cudaGetSymbolAddress((void**)&mcr,  g_mcr);
    cudaGetSymbolAddress((void**)&mw,   g_mw);
    cudaGetSymbolAddress((void**)&hy,   g_hydra);
    cudaGetSymbolAddress((void**)&x2,   g_x2);
    cudaGetSymbolAddress((void**)&x2r,  g_x2r);
    cudaGetSymbolAddress((void**)&xr,   g_xr);
    cudaGetSymbolAddress((void**)&pp,   g_pp);
    cudaGetSymbolAddress((void**)&tt,   g_t);
    cudaGetSymbolAddress((void**)&rw,   g_rw);
    cudaGetSymbolAddress((void**)&hh,   g_h);
    cudaGetSymbolAddress((void**)&vtl,  g_vtl);
    cudaGetSymbolAddress((void**)&vts,  g_vts);
    cudaGetSymbolAddress((void**)&wqkvl_t, g_wqkvl_t);
    cudaGetSymbolAddress((void**)&wqkvs_t, g_wqkvs_t);
    cudaGetSymbolAddress((void**)&wm_t,  g_wm_t);
    cudaGetSymbolAddress((void**)&wo_t,  g_wo_t);
    cudaGetSymbolAddress((void**)&wi_t,  g_wi_t);
    cudaGetSymbolAddress((void**)&wp1_t, g_wp1_t);
    cudaGetSymbolAddress((void**)&wp2_t, g_wp2_t);
    cudaGetSymbolAddress((void**)&wwb_t, g_wwb_t);
    cudaGetSymbolAddress((void**)&we1_t, g_we1_t);
    cudaGetSymbolAddress((void**)&we2_t, g_we2_t);

    const float scale = 0.0625f; // H^-0.5
    dim3 t256(256);

    // ---- pre-pass: round(+transpose) all tf32 GEMM operands ----
    roundT_k<<<dim3(768 / 32, 1024 / 32, 1), t256>>>(WqkvL, wqkvl_t, 1024, 768, 0, 0);
    roundT_k<<<dim3(768 / 32, 1024 / 32, 1), t256>>>(WqkvS, wqkvs_t, 1024, 768, 0, 0);
    roundT_k<<<dim3(256 / 32, 1024 / 32, 1), t256>>>(Wm, wm_t, 1024, 256, 0, 0);
    roundT_k<<<dim3(256 / 32, 512 / 32, 1), t256>>>(Wo, wo_t, 512, 256, 0, 0);
    roundT_k<<<dim3(256 / 32, 1024 / 32, 1), t256>>>(Wi, wi_t, 1024, 256, 0, 0);
    roundT_k<<<dim3(512 / 32, 256 / 32, 1), t256>>>(Wp1, wp1_t, 256, 512, 0, 0);
    roundT_k<<<dim3(256 / 32, 512 / 32, 1), t256>>>(Wp2, wp2_t, 512, 256, 0, 0);
    roundT_k<<<dim3(1024 / 32, 1024 / 32, 1), t256>>>(Wwb, wwb_t, 1024, 1024, 0, 0);
    roundT_k<<<dim3(F_ / 32, D_ / 32, E_), t256>>>(We1, we1_t, D_, F_, (long long)D_ * F_, (long long)F_ * D_);
    roundT_k<<<dim3(D_ / 32, F_ / 32, E_), t256>>>(We2, we2_t, F_, D_, (long long)F_ * D_, (long long)D_ * F_);
    round_copy_k<<<(BS_ * D_ + 255) / 256, 256>>>(x, xr, BS_ * D_);

    // ---- local attention ----
    tcg(0, true, xr, wqkvl_t, qkvL, BS_, 768, D_, D_, D_, 768, 0, 0, 0, 1, nullptr, nullptr, 0, 1.f);
    vtrans_k<<<dim3(S_ / 32, H_ / 32, B_), t256>>>(qkvL, vtl);
    tcg(0, false, qkvL, qkvL + H_, sc, S_, S_, H_, 768, 768, S_,
        (long long)S_ * 768, (long long)S_ * 768, (long long)S_ * S_, B_, nullptr, nullptr, 0, scale);
    softmax2048_k<<<BS_, 256>>>(sc);
    tcg(0, true, sc, vtl, hy, S_, H_, S_, S_, S_, 4 * H_,
        (long long)S_ * S_, (long long)H_ * S_, (long long)S_ * 4 * H_, B_, nullptr, nullptr, 0, 1.f);

    // ---- sparse attention ----
    tcg(0, true, xr, wqkvs_t, qkvS, BS_, 768, D_, D_, D_, 768, 0, 0, 0, 1, nullptr, nullptr, 0, 1.f);
    vtrans_k<<<dim3(S_ / 32, H_ / 32, B_), t256>>>(qkvS, vts);
    tcg(0, false, qkvS, qkvS + H_, sc, S_, S_, H_, 768, 768, S_,
        (long long)S_ * 768, (long long)S_ * 768, (long long)S_ * S_, B_, nullptr, nullptr, 0, scale);
    sparse_softmax_k<<<BS_, 256>>>(sc);
    tcg(0, true, sc, vts, hy + H_, S_, H_, S_, S_, S_, 4 * H_,
        (long long)S_ * S_, (long long)H_ * S_, (long long)S_ * 4 * H_, B_, nullptr, nullptr, 0, 1.f);

    // ---- memory branch ----
    tcg(0, false, xr, wm_t, mc, BS_, H_, D_, D_, D_, 2 * H_, 0, 0, 0, 1, nullptr, nullptr, 0, 1.f);
    gemm_k<true><<<dim3(1, BS_ / 128, 1), t256>>>(mc, memb, mw, BS_, M_, H_, 2 * H_, H_, M_);
    softmax64_k<<<(BS_ * 32 + 255) / 256, 256>>>(mw, BS_);
    gemm_k<false><<<dim3(2, BS_ / 128, 1), t256>>>(mw, memb, mc + H_, BS_, H_, M_, M_, H_, 2 * H_);
    round_copy_k<<<(BS_ * 2 * H_ + 255) / 256, 256>>>(mc, mcr, BS_ * 2 * H_);
    tcg(0, true, mcr, wo_t, hy + 2 * H_, BS_, H_, 2 * H_, 2 * H_, 2 * H_, 4 * H_, 0, 0, 0, 1, bo, nullptr, 0, 1.f);

    // ---- predictor branch ----
    tcg(0, true, xr, wi_t, pp, BS_, H_, D_, D_, D_, H_, 0, 0, 0, 1, bi, nullptr, 0, 1.f);
    tcg(1, true, pp, wp1_t, tt, BS_, 2 * H_, H_, H_, H_, 2 * H_, 0, 0, 0, 1, bp1, nullptr, 0, 1.f);
    tcg(0, true, tt, wp2_t, hy + 3 * H_, BS_, H_, 2 * H_, 2 * H_, 2 * H_, 4 * H_, 0, 0, 0, 1, bp2, nullptr, 0, 1.f);

    // ---- hydra combine ----
    copy_k<<<(BS_ * D_ + 255) / 256, 256>>>(x, x2, BS_ * D_);
    tcg(2, false, hy, wwb_t, x2, BS_, D_, 4 * H_, 4 * H_, 4 * H_, D_, 0, 0, 0, 1, bwb, nullptr, 0, 1.f);

    // ---- router + MoE ----
    router_k<<<(BS_ * 32 + 255) / 256, 256>>>(x2, Wr, br, rw, BS_);
    round_copy_k<<<(BS_ * D_ + 255) / 256, 256>>>(x2, x2r, BS_ * D_);
    copy_k<<<(BS_ * D_ + 255) / 256, 256>>>(x2, out, BS_ * D_);
    for (int e = 0; e < E_; e++) {
        tcg(1, true, x2r, we1_t + (long long)e * F_ * D_, hh,
            BS_, F_, D_, D_, D_, F_, 0, 0, 0, 1, be1 + (long long)e * F_, nullptr, 0, 1.f);
        tcg(3, false, hh, we2_t + (long long)e * D_ * F_, out,
            BS_, D_, F_, F_, F_, D_, 0, 0, 0, 1, be2 + (long long)e * D_, rw + e, E_, 1.f);
    }
}

// round 5
// speedup vs baseline: 3.0820x; 1.1257x over previous
#include <cuda_runtime.h>
#include <cuda_bf16.h>
#include <math.h>
#include <stdint.h>

// ---------------- problem constants ----------------
#define B_   4
#define S_   2048
#define D_   1024
#define H_   256
#define E_   4
#define F_   4096
#define M_   64
#define BS_  (B_ * S_)          // 8192
#define KSP_ 204                // int(2048*0.1)

// ---------------- scratch (device globals; no allocation allowed) ----------------
__device__ float g_qkv_loc[(size_t)BS_ * 3 * H_];
__device__ float g_qkv_sp [(size_t)BS_ * 3 * H_];
__device__ float g_scores [(size_t)B_ * S_ * S_];
__device__ float g_memcat [(size_t)BS_ * 2 * H_];
__device__ float g_mcr    [(size_t)BS_ * 2 * H_];
__device__ float g_mw     [(size_t)BS_ * M_];
__device__ float g_hydra  [(size_t)BS_ * 4 * H_];
__device__ float g_x2     [(size_t)BS_ * D_];
__device__ float g_x2r    [(size_t)BS_ * D_];
__device__ float g_xr     [(size_t)BS_ * D_];
__device__ float g_pp     [(size_t)BS_ * H_];
__device__ float g_t      [(size_t)BS_ * 2 * H_];
__device__ float g_rw     [(size_t)BS_ * E_];
__device__ float g_h      [(size_t)BS_ * F_];
__device__ float g_vtl    [(size_t)B_ * H_ * S_];
__device__ float g_vts    [(size_t)B_ * H_ * S_];
// transposed+rounded weights [N][K]
__device__ float g_wqkvl_t[(size_t)768 * 1024];
__device__ float g_wqkvs_t[(size_t)768 * 1024];
__device__ float g_wm_t   [(size_t)256 * 1024];
__device__ float g_wo_t   [(size_t)256 * 512];
__device__ float g_wi_t   [(size_t)256 * 1024];
__device__ float g_wp1_t  [(size_t)512 * 256];
__device__ float g_wp2_t  [(size_t)256 * 512];
__device__ float g_wwb_t  [(size_t)1024 * 1024];
__device__ float g_we1_t  [(size_t)E_ * F_ * D_];
__device__ float g_we2_t  [(size_t)E_ * D_ * F_];

__device__ __forceinline__ float gelu_f(float x) {
    return 0.5f * x * (1.0f + erff(x * 0.7071067811865476f));
}
__device__ __forceinline__ uint32_t f2tf32(float f) {
    uint32_t r; asm("cvt.rna.tf32.f32 %0, %1;" : "=r"(r) : "f"(f)); return r;
}
__device__ __forceinline__ float rndf(float f) { return __uint_as_float(f2tf32(f)); }
__device__ __forceinline__ void mma1688(float* c, const uint32_t* a, const uint32_t* b) {
    asm volatile("mma.sync.aligned.m16n8k8.row.col.f32.tf32.tf32.f32 "
                 "{%0,%1,%2,%3}, {%4,%5,%6,%7}, {%8,%9}, {%0,%1,%2,%3};"
                 : "+f"(c[0]), "+f"(c[1]), "+f"(c[2]), "+f"(c[3])
                 : "r"(a[0]), "r"(a[1]), "r"(a[2]), "r"(a[3]), "r"(b[0]), "r"(b[1]));
}
__device__ __forceinline__ void cp16(uint32_t dst, const void* src) {
    asm volatile("cp.async.ca.shared.global [%0], [%1], 16;" :: "r"(dst), "l"(src));
}
#define CP_COMMIT asm volatile("cp.async.commit_group;" ::: "memory")
#define CP_WAIT1  asm volatile("cp.async.wait_group 1;" ::: "memory")
__device__ __forceinline__ uint32_t smem_u32(const void* p) {
    uint32_t a;
    asm("{ .reg .u64 t; cvta.to.shared.u64 t, %1; cvt.u32.u64 %0, t; }" : "=r"(a) : "l"(p));
    return a;
}

// ================= tf32 warp-MMA GEMM (NT, both operands pre-rounded, K-major) =================
// CTA tile 128x128, 4 warps (2m x 2n), warp tile 64x64, K-chunks of 32, 3-stage cp.async.
// EPI: 0 store(+bias), 1 gelu(+bias), 3 C+=rowscale*v(+bias), 4 triple-write (x2 path)
// RND: round stored value to tf32
#define PITCH 36
#define ST 3
#define KC 32
#define STAGE_W (2 * 128 * PITCH)             // words per stage (A then B)
#define TC_SMEM (ST * STAGE_W * 4)            // 110592 bytes

template<int EPI, bool RND>
__global__ void __launch_bounds__(128, 2)
tc_gemm_k(const float* __restrict__ Ag, const float* __restrict__ Bg, float* __restrict__ Cg,
          int K, int lda, int ldb, int ldc,
          long long sA, long long sB, long long sC,
          const float* __restrict__ bias, const float* __restrict__ rowscale,
          int rs_stride, float alpha,
          const float* __restrict__ resid, float* __restrict__ aux1, float* __restrict__ aux2)
{
    extern __shared__ uint32_t sm[];
    const uint32_t smb = smem_u32(sm);
    const int tid = threadIdx.x, lane = tid & 31, wid = tid >> 5;
    const int m0 = blockIdx.y * 128, n0 = blockIdx.x * 128;
    const int wm = (wid >> 1) * 64, wn = (wid & 1) * 64;
    const int arow = tid >> 3, ac4 = (tid & 7) << 2;   // 16 rows x 8 col4 per pass

    const float* A  = Ag + blockIdx.z * sA + (long long)(m0 + arow) * lda + ac4;
    const float* Bp = Bg + blockIdx.z * sB + (long long)(n0 + arow) * ldb + ac4;
    float* C = Cg + blockIdx.z * sC;

    const uint32_t myA = smb + (uint32_t)(arow * PITCH + ac4) * 4;
    const uint32_t myB = myA + 128 * PITCH * 4;

    float acc[4][8][4];
#pragma unroll
    for (int i = 0; i < 4; i++)
#pragma unroll
        for (int j = 0; j < 8; j++)
#pragma unroll
            for (int k = 0; k < 4; k++) acc[i][j][k] = 0.f;

    const int nch = K >> 5;

    auto issue = [&](int c) {
        const int s = c % ST;
        const uint32_t sa = myA + s * (STAGE_W * 4);
        const uint32_t sb = myB + s * (STAGE_W * 4);
        const float* ga = A + c * KC;
        const float* gb = Bp + c * KC;
#pragma unroll
        for (int i = 0; i < 8; i++) {
            cp16(sa + i * (16 * PITCH * 4), ga + (long long)i * 16 * lda);
            cp16(sb + i * (16 * PITCH * 4), gb + (long long)i * 16 * ldb);
        }
    };

    issue(0); CP_COMMIT;
    issue(1); CP_COMMIT;

    const int fr = lane >> 2, fq = lane & 3;

    for (int c = 0; c < nch; c++) {
        CP_WAIT1;
        __syncthreads();
        if (c + ST - 1 < nch) issue(c + ST - 1);
        CP_COMMIT;

        const uint32_t* Ab = sm + (c % ST) * STAGE_W;
        const uint32_t* Bb = Ab + 128 * PITCH;
#pragma unroll
        for (int ks = 0; ks < 4; ks++) {
            const int kb = ks * 8 + fq;
            uint32_t af[4][4], bf[8][2];
#pragma unroll
            for (int mt = 0; mt < 4; mt++) {
                const uint32_t* p = Ab + (wm + mt * 16 + fr) * PITCH + kb;
                af[mt][0] = p[0];
                af[mt][1] = p[8 * PITCH];
                af[mt][2] = p[4];
                af[mt][3] = p[8 * PITCH + 4];
            }
#pragma unroll
            for (int nt = 0; nt < 8; nt++) {
                const uint32_t* p = Bb + (wn + nt * 8 + fr) * PITCH + kb;
                bf[nt][0] = p[0];
                bf[nt][1] = p[4];
            }
#pragma unroll
            for (int mt = 0; mt < 4; mt++)
#pragma unroll
                for (int nt = 0; nt < 8; nt++)
                    mma1688(acc[mt][nt], af[mt], bf[nt]);
        }
    }

    // ---- epilogue ----
    const int cq = (lane & 3) * 2;
#pragma unroll
    for (int mt = 0; mt < 4; mt++) {
        int gr0 = m0 + wm + mt * 16 + fr;
        int gr1 = gr0 + 8;
        float rs0 = 1.f, rs1 = 1.f;
        if (EPI == 3) {
            rs0 = rowscale[(long long)gr0 * rs_stride];
            rs1 = rowscale[(long long)gr1 * rs_stride];
        }
#pragma unroll
        for (int nt = 0; nt < 8; nt++) {
            int gc = n0 + wn + nt * 8 + cq;
            float b0 = bias ? bias[gc] : 0.f;
            float b1 = bias ? bias[gc + 1] : 0.f;
            float v00 = acc[mt][nt][0] * alpha + b0;
            float v01 = acc[mt][nt][1] * alpha + b1;
            float v10 = acc[mt][nt][2] * alpha + b0;
            float v11 = acc[mt][nt][3] * alpha + b1;
            long long o0 = (long long)gr0 * ldc + gc;
            long long o1 = (long long)gr1 * ldc + gc;
            if (EPI == 1) {
                v00 = gelu_f(v00); v01 = gelu_f(v01);
                v10 = gelu_f(v10); v11 = gelu_f(v11);
            }
            if (RND) {
                v00 = rndf(v00); v01 = rndf(v01);
                v10 = rndf(v10); v11 = rndf(v11);
            }
            if (EPI == 0 || EPI == 1) {
                *(float2*)(C + o0) = make_float2(v00, v01);
                *(float2*)(C + o1) = make_float2(v10, v11);
            } else if (EPI == 3) {
                C[o0] += rs0 * v00; C[o0 + 1] += rs0 * v01;
                C[o1] += rs1 * v10; C[o1 + 1] += rs1 * v11;
            } else { // EPI 4: x2 = resid + v; aux1 = rnd(x2); aux2 = x2
                float w00 = resid[o0] + v00, w01 = resid[o0 + 1] + v01;
                float w10 = resid[o1] + v10, w11 = resid[o1 + 1] + v11;
                *(float2*)(C + o0) = make_float2(w00, w01);
                *(float2*)(C + o1) = make_float2(w10, w11);
                *(float2*)(aux1 + o0) = make_float2(rndf(w00), rndf(w01));
                *(float2*)(aux1 + o1) = make_float2(rndf(w10), rndf(w11));
                *(float2*)(aux2 + o0) = make_float2(w00, w01);
                *(float2*)(aux2 + o1) = make_float2(w10, w11);
            }
        }
    }
}

static void tcg(int epi, bool rnd,
                const float* A, const float* Bm, float* C,
                int M, int N, int K, int lda, int ldb, int ldc,
                long long sA, long long sB, long long sC, int batch,
                const float* bias, const float* rowscale, int rs_stride, float alpha,
                const float* resid = nullptr, float* aux1 = nullptr, float* aux2 = nullptr)
{
    dim3 g(N / 128, M / 128, batch), blk(128);
#define LNCH(EP, RN) do { \
    cudaFuncSetAttribute(tc_gemm_k<EP, RN>, cudaFuncAttributeMaxDynamicSharedMemorySize, TC_SMEM); \
    tc_gemm_k<EP, RN><<<g, blk, TC_SMEM>>>(A, Bm, C, K, lda, ldb, ldc, sA, sB, sC, bias, rowscale, rs_stride, alpha, resid, aux1, aux2); \
} while (0)
    if (epi == 0) { if (rnd) LNCH(0, true); else LNCH(0, false); }
    else if (epi == 1) LNCH(1, true);
    else if (epi == 3) LNCH(3, false);
    else LNCH(4, false);
#undef LNCH
}

// ================= weight round + transpose: in[K][N] -> out[N][K] (tf32-rounded) =================
__global__ void roundT_k(const float* __restrict__ in, float* __restrict__ out,
                         int K, int N, long long inS, long long outS)
{
    __shared__ float t[32][33];
    const float* ip = in + blockIdx.z * inS;
    float* op = out + blockIdx.z * outS;
    int n0 = blockIdx.x * 32, k0 = blockIdx.y * 32;
    int tx = threadIdx.x & 31, ty = threadIdx.x >> 5;
#pragma unroll
    for (int i = 0; i < 32; i += 8)
        t[ty + i][tx] = ip[(long long)(k0 + ty + i) * N + n0 + tx];
    __syncthreads();
#pragma unroll
    for (int i = 0; i < 32; i += 8)
        op[(long long)(n0 + ty + i) * K + k0 + tx] = rndf(t[tx][ty + i]);
}

__global__ void round_copy_k(const float* __restrict__ a, float* __restrict__ b, int n) {
    int i = blockIdx.x * 256 + threadIdx.x;
    if (i < n) b[i] = rndf(a[i]);
}

// v transpose: qkv [BS][768] cols 512.. -> vT [B][H][S]
__global__ void vtrans_k(const float* __restrict__ qkv, float* __restrict__ vT) {
    __shared__ float t[32][33];
    int s0 = blockIdx.x * 32, h0 = blockIdx.y * 32, b = blockIdx.z;
    int tx = threadIdx.x & 31, ty = threadIdx.x >> 5;
#pragma unroll
    for (int i = 0; i < 32; i += 8)
        t[ty + i][tx] = qkv[(long long)(b * S_ + s0 + ty + i) * 768 + 512 + h0 + tx];
    __syncthreads();
#pragma unroll
    for (int i = 0; i < 32; i += 8)
        vT[(long long)b * H_ * S_ + (long long)(h0 + ty + i) * S_ + s0 + tx] = t[tx][ty + i];
}

// ================= fallback SIMT GEMM (small fp32 shapes) =================
template<bool TRANSB>
__global__ __launch_bounds__(256, 2)
void gemm_k(const float* __restrict__ Ag, const float* __restrict__ Bg,
            float* __restrict__ Cg,
            int M, int N, int K, int lda, int ldb, int ldc)
{
    __shared__ float As[8][128];
    __shared__ float Bs[8][128];
    const float* A = Ag;
    const float* Bm = Bg;
    float* C = Cg;
    const int m0 = blockIdx.y * 128, n0 = blockIdx.x * 128;
    const int tid = threadIdx.x;
    const int tx = tid & 15, ty = tid >> 4;

    float acc[8][8];
#pragma unroll
    for (int i = 0; i < 8; i++)
#pragma unroll
        for (int j = 0; j < 8; j++) acc[i][j] = 0.f;

    const int am = tid >> 1, ak = (tid & 1) << 2;

    for (int k0 = 0; k0 < K; k0 += 8) {
        float4 av = *(const float4*)(A + (long long)(m0 + am) * lda + k0 + ak);
        As[ak + 0][am] = av.x; As[ak + 1][am] = av.y;
        As[ak + 2][am] = av.z; As[ak + 3][am] = av.w;
        if (!TRANSB) {
            int bk = tid >> 5, bn = (tid & 31) << 2;
            float4 bv = make_float4(0.f, 0.f, 0.f, 0.f);
            if (n0 + bn < N)
                bv = *(const float4*)(Bm + (long long)(k0 + bk) * ldb + n0 + bn);
            *(float4*)&Bs[bk][bn] = bv;
        } else {
            int bn = tid >> 1, bk = (tid & 1) << 2;
            float4 bv = make_float4(0.f, 0.f, 0.f, 0.f);
            if (n0 + bn < N)
                bv = *(const float4*)(Bm + (long long)(n0 + bn) * ldb + k0 + bk);
            Bs[bk + 0][bn] = bv.x; Bs[bk + 1][bn] = bv.y;
            Bs[bk + 2][bn] = bv.z; Bs[bk + 3][bn] = bv.w;
        }
        __syncthreads();
#pragma unroll
        for (int k = 0; k < 8; k++) {
            float4 a0 = *(float4*)&As[k][ty * 4];
            float4 a1 = *(float4*)&As[k][ty * 4 + 64];
            float4 b0 = *(float4*)&Bs[k][tx * 4];
            float4 b1 = *(float4*)&Bs[k][tx * 4 + 64];
            float a[8] = {a0.x, a0.y, a0.z, a0.w, a1.x, a1.y, a1.z, a1.w};
            float b[8] = {b0.x, b0.y, b0.z, b0.w, b1.x, b1.y, b1.z, b1.w};
#pragma unroll
            for (int i = 0; i < 8; i++)
#pragma unroll
                for (int j = 0; j < 8; j++) acc[i][j] += a[i] * b[j];
        }
        __syncthreads();
    }

#pragma unroll
    for (int i = 0; i < 8; i++) {
        int gr = m0 + ty * 4 + (i & 3) + ((i >> 2) << 6);
        float* Crow = C + (long long)gr * ldc;
#pragma unroll
        for (int j = 0; j < 8; j++) {
            int gc = n0 + tx * 4 + (j & 3) + ((j >> 2) << 6);
            if (gc < N) Crow[gc] = acc[i][j];
        }
    }
}

// ---------------- softmax over full rows of 2048 (rounded output) ----------------
__global__ void softmax2048_k(float* __restrict__ Sc) {
    __shared__ float red[256];
    const int tid = threadIdx.x;
    float* p = Sc + (long long)blockIdx.x * 2048;
    float v[8];
    float mx = -3.4e38f;
#pragma unroll
    for (int i = 0; i < 8; i++) { v[i] = p[tid + i * 256]; mx = fmaxf(mx, v[i]); }
    red[tid] = mx; __syncthreads();
    for (int s = 128; s; s >>= 1) { if (tid < s) red[tid] = fmaxf(red[tid], red[tid + s]); __syncthreads(); }
    mx = red[0]; __syncthreads();
    float sum = 0.f;
#pragma unroll
    for (int i = 0; i < 8; i++) { v[i] = expf(v[i] - mx); sum += v[i]; }
    red[tid] = sum; __syncthreads();
    for (int s = 128; s; s >>= 1) { if (tid < s) red[tid] += red[tid + s]; __syncthreads(); }
    float inv = 1.f / red[0];
#pragma unroll
    for (int i = 0; i < 8; i++) p[tid + i * 256] = rndf(v[i] * inv);
}

// ---------------- sparse top-k via exact radix select + masked softmax ----------------
__global__ void sparse_softmax_k(float* __restrict__ Sc) {
    __shared__ uint32_t hist[256];
    __shared__ uint32_t sfx[257];
    __shared__ uint32_t s_prefix, s_k;
    __shared__ float red[256];
    const int tid = threadIdx.x;
    float* p = Sc + (long long)blockIdx.x * 2048;

    float v[8]; uint32_t key[8];
    float mx = -3.4e38f;
#pragma unroll
    for (int i = 0; i < 8; i++) {
        v[i] = p[tid + i * 256];
        mx = fmaxf(mx, v[i]);
        uint32_t u = __float_as_uint(v[i]);
        key[i] = (u & 0x80000000u) ? ~u : (u | 0x80000000u);
    }
    // row max
    red[tid] = mx; __syncthreads();
    for (int s = 128; s; s >>= 1) { if (tid < s) red[tid] = fmaxf(red[tid], red[tid + s]); __syncthreads(); }
    mx = red[0];

    // exact kth-largest via 4-pass radix select on keys
    uint32_t prefix = 0, kk = KSP_;
#pragma unroll 1
    for (int b = 3; b >= 0; b--) {
        const int sh = b * 8;
        const uint32_t pmask = (b == 3) ? 0u : ~((1u << (sh + 8)) - 1u);
        hist[tid] = 0;
        if (tid == 0) sfx[256] = 0;
        __syncthreads();
#pragma unroll
        for (int i = 0; i < 8; i++)
            if ((key[i] & pmask) == prefix)
                atomicAdd(&hist[(key[i] >> sh) & 255u], 1u);
        __syncthreads();
        sfx[tid] = hist[tid];
        __syncthreads();
        for (int off = 1; off < 256; off <<= 1) {
            uint32_t add = (tid + off < 256) ? sfx[tid + off] : 0u;
            __syncthreads();
            sfx[tid] += add;
            __syncthreads();
        }
        if (sfx[tid] >= kk && (tid == 255 || sfx[tid + 1] < kk)) {
            s_prefix = prefix | ((uint32_t)tid << sh);
            s_k = kk - sfx[tid + 1];
        }
        __syncthreads();
        prefix = s_prefix; kk = s_k;
        __syncthreads();
    }
    const uint32_t tk = prefix;
    const float thr = (tk & 0x80000000u) ? __uint_as_float(tk ^ 0x80000000u)
                                         : __uint_as_float(~tk);

    float e[8]; float sum = 0.f;
#pragma unroll
    for (int i = 0; i < 8; i++) {
        float ev = (v[i] >= thr) ? expf(v[i] - mx) : 0.f;
        e[i] = ev; sum += ev;
    }
    red[tid] = sum; __syncthreads();
    for (int s = 128; s; s >>= 1) { if (tid < s) red[tid] += red[tid + s]; __syncthreads(); }
    float inv = 1.f / red[0];
#pragma unroll
    for (int i = 0; i < 8; i++) p[tid + i * 256] = rndf(e[i] * inv);
}

// ---------------- softmax rows of 64 ----------------
__global__ void softmax64_k(float* __restrict__ mw, int rows) {
    int row = (blockIdx.x * blockDim.x + threadIdx.x) >> 5;
    int lane = threadIdx.x & 31;
    if (row >= rows) return;
    float* p = mw + (long long)row * 64;
    float a = p[lane], b = p[lane + 32];
    float mx = fmaxf(a, b);
    for (int o = 16; o; o >>= 1) mx = fmaxf(mx, __shfl_xor_sync(0xffffffffu, mx, o));
    float ea = expf(a - mx), eb = expf(b - mx);
    float s = ea + eb;
    for (int o = 16; o; o >>= 1) s += __shfl_xor_sync(0xffffffffu, s, o);
    float inv = 1.f / s;
    p[lane] = ea * inv; p[lane + 32] = eb * inv;
}

// ---------------- router ----------------
__global__ void router_k(const float* __restrict__ x2, const float* __restrict__ Wr,
                         const float* __restrict__ br, float* __restrict__ rw, int rows) {
    int tok = (blockIdx.x * blockDim.x + threadIdx.x) >> 5;
    int lane = threadIdx.x & 31;
    if (tok >= rows) return;
    const float* xr = x2 + (long long)tok * D_;
    float s0 = 0.f, s1 = 0.f, s2 = 0.f, s3 = 0.f;
    for (int d = lane; d < D_; d += 32) {
        float xv = xr[d];
        const float* w = Wr + d * 4;
        s0 += xv * w[0]; s1 += xv * w[1]; s2 += xv * w[2]; s3 += xv * w[3];
    }
    for (int o = 16; o; o >>= 1) {
        s0 += __shfl_xor_sync(0xffffffffu, s0, o);
        s1 += __shfl_xor_sync(0xffffffffu, s1, o);
        s2 += __shfl_xor_sync(0xffffffffu, s2, o);
        s3 += __shfl_xor_sync(0xffffffffu, s3, o);
    }
    if (lane == 0) {
        s0 += br[0]; s1 += br[1]; s2 += br[2]; s3 += br[3];
        float mx = fmaxf(fmaxf(s0, s1), fmaxf(s2, s3));
        float e0 = expf(s0 - mx), e1 = expf(s1 - mx), e2 = expf(s2 - mx), e3 = expf(s3 - mx);
        float inv = 1.f / (e0 + e1 + e2 + e3);
        float* o4 = rw + (long long)tok * 4;
        o4[0] = e0 * inv; o4[1] = e1 * inv; o4[2] = e2 * inv; o4[3] = e3 * inv;
    }
}

// ---------------- launch ----------------
extern "C" void kernel_launch(void* const* d_in, const int* in_sizes, int n_in,
                              void* d_out, int out_size) {
    const float* x     = (const float*)d_in[0];
    const float* WqkvL = (const float*)d_in[1];
    const float* WqkvS = (const float*)d_in[2];
    const float* memb  = (const float*)d_in[3];
    const float* Wm    = (const float*)d_in[4];
    const float* Wo    = (const float*)d_in[5];
    const float* bo    = (const float*)d_in[6];
    const float* Wi    = (const float*)d_in[7];
    const float* bi    = (const float*)d_in[8];
    const float* Wp1   = (const float*)d_in[9];
    const float* bp1   = (const float*)d_in[10];
    const float* Wp2   = (const float*)d_in[11];
    const float* bp2   = (const float*)d_in[12];
    const float* Wwb   = (const float*)d_in[13];
    const float* bwb   = (const float*)d_in[14];
    const float* Wr    = (const float*)d_in[15];
    const float* br    = (const float*)d_in[16];
    const float* We1   = (const float*)d_in[17];
    const float* be1   = (const float*)d_in[18];
    const float* We2   = (const float*)d_in[19];
    const float* be2   = (const float*)d_in[20];
    float* out = (float*)d_out;

    float *qkvL, *qkvS, *sc, *mc, *mcr, *mw, *hy, *x2, *x2r, *xr, *pp, *tt, *rw, *hh, *vtl, *vts;
    float *wqkvl_t, *wqkvs_t, *wm_t, *wo_t, *wi_t, *wp1_t, *wp2_t, *wwb_t, *we1_t, *we2_t;
    cudaGetSymbolAddress((void**)&qkvL, g_qkv_loc);
    cudaGetSymbolAddress((void**)&qkvS, g_qkv_sp);
    cudaGetSymbolAddress((void**)&sc,   g_scores);
    cudaGetSymbolAddress((void**)&mc,   g_memcat);
    cudaGetSymbolAddress((void**)&mcr,  g_mcr);
    cudaGetSymbolAddress((void**)&mw,   g_mw);
    cudaGetSymbolAddress((void**)&hy,   g_hydra);
    cudaGetSymbolAddress((void**)&x2,   g_x2);
    cudaGetSymbolAddress((void**)&x2r,  g_x2r);
    cudaGetSymbolAddress((void**)&xr,   g_xr);
    cudaGetSymbolAddress((void**)&pp,   g_pp);
    cudaGetSymbolAddress((void**)&tt,   g_t);
    cudaGetSymbolAddress((void**)&rw,   g_rw);
    cudaGetSymbolAddress((void**)&hh,   g_h);
    cudaGetSymbolAddress((void**)&vtl,  g_vtl);
    cudaGetSymbolAddress((void**)&vts,  g_vts);
    cudaGetSymbolAddress((void**)&wqkvl_t, g_wqkvl_t);
    cudaGetSymbolAddress((void**)&wqkvs_t, g_wqkvs_t);
    cudaGetSymbolAddress((void**)&wm_t,  g_wm_t);
    cudaGetSymbolAddress((void**)&wo_t,  g_wo_t);
    cudaGetSymbolAddress((void**)&wi_t,  g_wi_t);
    cudaGetSymbolAddress((void**)&wp1_t, g_wp1_t);
    cudaGetSymbolAddress((void**)&wp2_t, g_wp2_t);
    cudaGetSymbolAddress((void**)&wwb_t, g_wwb_t);
    cudaGetSymbolAddress((void**)&we1_t, g_we1_t);
    cudaGetSymbolAddress((void**)&we2_t, g_we2_t);

    const float scale = 0.0625f; // H^-0.5
    dim3 t256(256);

    // ---- pre-pass: round(+transpose) all tf32 GEMM operands ----
    roundT_k<<<dim3(768 / 32, 1024 / 32, 1), t256>>>(WqkvL, wqkvl_t, 1024, 768, 0, 0);
    roundT_k<<<dim3(768 / 32, 1024 / 32, 1), t256>>>(WqkvS, wqkvs_t, 1024, 768, 0, 0);
    roundT_k<<<dim3(256 / 32, 1024 / 32, 1), t256>>>(Wm, wm_t, 1024, 256, 0, 0);
    roundT_k<<<dim3(256 / 32, 512 / 32, 1), t256>>>(Wo, wo_t, 512, 256, 0, 0);
    roundT_k<<<dim3(256 / 32, 1024 / 32, 1), t256>>>(Wi, wi_t, 1024, 256, 0, 0);
    roundT_k<<<dim3(512 / 32, 256 / 32, 1), t256>>>(Wp1, wp1_t, 256, 512, 0, 0);
    roundT_k<<<dim3(256 / 32, 512 / 32, 1), t256>>>(Wp2, wp2_t, 512, 256, 0, 0);
    roundT_k<<<dim3(1024 / 32, 1024 / 32, 1), t256>>>(Wwb, wwb_t, 1024, 1024, 0, 0);
    roundT_k<<<dim3(F_ / 32, D_ / 32, E_), t256>>>(We1, we1_t, D_, F_, (long long)D_ * F_, (long long)F_ * D_);
    roundT_k<<<dim3(D_ / 32, F_ / 32, E_), t256>>>(We2, we2_t, F_, D_, (long long)F_ * D_, (long long)D_ * F_);
    round_copy_k<<<(BS_ * D_ + 255) / 256, 256>>>(x, xr, BS_ * D_);

    // ---- local attention ----
    tcg(0, true, xr, wqkvl_t, qkvL, BS_, 768, D_, D_, D_, 768, 0, 0, 0, 1, nullptr, nullptr, 0, 1.f);
    vtrans_k<<<dim3(S_ / 32, H_ / 32, B_), t256>>>(qkvL, vtl);
    tcg(0, false, qkvL, qkvL + H_, sc, S_, S_, H_, 768, 768, S_,
        (long long)S_ * 768, (long long)S_ * 768, (long long)S_ * S_, B_, nullptr, nullptr, 0, scale);
    softmax2048_k<<<BS_, 256>>>(sc);
    tcg(0, true, sc, vtl, hy, S_, H_, S_, S_, S_, 4 * H_,
        (long long)S_ * S_, (long long)H_ * S_, (long long)S_ * 4 * H_, B_, nullptr, nullptr, 0, 1.f);

    // ---- sparse attention ----
    tcg(0, true, xr, wqkvs_t, qkvS, BS_, 768, D_, D_, D_, 768, 0, 0, 0, 1, nullptr, nullptr, 0, 1.f);
    vtrans_k<<<dim3(S_ / 32, H_ / 32, B_), t256>>>(qkvS, vts);
    tcg(0, false, qkvS, qkvS + H_, sc, S_, S_, H_, 768, 768, S_,
        (long long)S_ * 768, (long long)S_ * 768, (long long)S_ * S_, B_, nullptr, nullptr, 0, scale);
    sparse_softmax_k<<<BS_, 256>>>(sc);
    tcg(0, true, sc, vts, hy + H_, S_, H_, S_, S_, S_, 4 * H_,
        (long long)S_ * S_, (long long)H_ * S_, (long long)S_ * 4 * H_, B_, nullptr, nullptr, 0, 1.f);

    // ---- memory branch ----
    tcg(0, false, xr, wm_t, mc, BS_, H_, D_, D_, D_, 2 * H_, 0, 0, 0, 1, nullptr, nullptr, 0, 1.f);
    gemm_k<true><<<dim3(1, BS_ / 128, 1), t256>>>(mc, memb, mw, BS_, M_, H_, 2 * H_, H_, M_);
    softmax64_k<<<(BS_ * 32 + 255) / 256, 256>>>(mw, BS_);
    gemm_k<false><<<dim3(2, BS_ / 128, 1), t256>>>(mw, memb, mc + H_, BS_, H_, M_, M_, H_, 2 * H_);
    round_copy_k<<<(BS_ * 2 * H_ + 255) / 256, 256>>>(mc, mcr, BS_ * 2 * H_);
    tcg(0, true, mcr, wo_t, hy + 2 * H_, BS_, H_, 2 * H_, 2 * H_, 2 * H_, 4 * H_, 0, 0, 0, 1, bo, nullptr, 0, 1.f);

    // ---- predictor branch ----
    tcg(0, true, xr, wi_t, pp, BS_, H_, D_, D_, D_, H_, 0, 0, 0, 1, bi, nullptr, 0, 1.f);
    tcg(1, true, pp, wp1_t, tt, BS_, 2 * H_, H_, H_, H_, 2 * H_, 0, 0, 0, 1, bp1, nullptr, 0, 1.f);
    tcg(0, true, tt, wp2_t, hy + 3 * H_, BS_, H_, 2 * H_, 2 * H_, 2 * H_, 4 * H_, 0, 0, 0, 1, bp2, nullptr, 0, 1.f);

    // ---- hydra combine (fused: x2 = x + concat@Wwb + bwb; x2r = rnd(x2); out = x2) ----
    tcg(4, false, hy, wwb_t, x2, BS_, D_, 4 * H_, 4 * H_, 4 * H_, D_, 0, 0, 0, 1, bwb, nullptr, 0, 1.f,
        x, x2r, out);

    // ---- router + MoE ----
    router_k<<<(BS_ * 32 + 255) / 256, 256>>>(x2, Wr, br, rw, BS_);
    for (int e = 0; e < E_; e++) {
        tcg(1, true, x2r, we1_t + (long long)e * F_ * D_, hh,
            BS_, F_, D_, D_, D_, F_, 0, 0, 0, 1, be1 + (long long)e * F_, nullptr, 0, 1.f);
        tcg(3, false, hh, we2_t + (long long)e * D_ * F_, out,
            BS_, D_, F_, F_, F_, D_, 0, 0, 0, 1, be2 + (long long)e * D_, rw + e, E_, 1.f);
    }
}

// round 6
// speedup vs baseline: 3.2910x; 1.0678x over previous
#include <cuda_runtime.h>
#include <cuda_bf16.h>
#include <math.h>
#include <stdint.h>

// ---------------- problem constants ----------------
#define B_   4
#define S_   2048
#define D_   1024
#define H_   256
#define E_   4
#define F_   4096
#define M_   64
#define BS_  (B_ * S_)          // 8192
#define KSP_ 204                // int(2048*0.1)

// ---------------- scratch (device globals; no allocation allowed) ----------------
__device__ float g_qkv_loc[(size_t)BS_ * 3 * H_];
__device__ float g_qkv_sp [(size_t)BS_ * 3 * H_];
__device__ float g_scores [(size_t)B_ * S_ * S_];
__device__ float g_memcat [(size_t)BS_ * 2 * H_];
__device__ float g_mcr    [(size_t)BS_ * 2 * H_];
__device__ float g_mw     [(size_t)BS_ * M_];
__device__ float g_hydra  [(size_t)BS_ * 4 * H_];
__device__ float g_x2     [(size_t)BS_ * D_];
__device__ float g_x2r    [(size_t)BS_ * D_];
__device__ float g_xr     [(size_t)BS_ * D_];
__device__ float g_pp     [(size_t)BS_ * H_];
__device__ float g_t      [(size_t)BS_ * 2 * H_];
__device__ float g_rw     [(size_t)BS_ * E_];
__device__ float g_h      [(size_t)BS_ * F_];
__device__ float g_vtl    [(size_t)B_ * H_ * S_];
__device__ float g_vts    [(size_t)B_ * H_ * S_];
// transposed+rounded weights [N][K]
__device__ float g_wqkvl_t[(size_t)768 * 1024];
__device__ float g_wqkvs_t[(size_t)768 * 1024];
__device__ float g_wm_t   [(size_t)256 * 1024];
__device__ float g_wo_t   [(size_t)256 * 512];
__device__ float g_wi_t   [(size_t)256 * 1024];
__device__ float g_wp1_t  [(size_t)512 * 256];
__device__ float g_wp2_t  [(size_t)256 * 512];
__device__ float g_wwb_t  [(size_t)1024 * 1024];
__device__ float g_we1_t  [(size_t)E_ * F_ * D_];
__device__ float g_we2_t  [(size_t)E_ * D_ * F_];

__device__ __forceinline__ float gelu_f(float x) {
    return 0.5f * x * (1.0f + erff(x * 0.7071067811865476f));
}
__device__ __forceinline__ uint32_t f2tf32(float f) {
    uint32_t r; asm("cvt.rna.tf32.f32 %0, %1;" : "=r"(r) : "f"(f)); return r;
}
__device__ __forceinline__ float rndf(float f) { return __uint_as_float(f2tf32(f)); }
__device__ __forceinline__ void mma1688(float* c, const uint32_t* a, const uint32_t* b) {
    asm volatile("mma.sync.aligned.m16n8k8.row.col.f32.tf32.tf32.f32 "
                 "{%0,%1,%2,%3}, {%4,%5,%6,%7}, {%8,%9}, {%0,%1,%2,%3};"
                 : "+f"(c[0]), "+f"(c[1]), "+f"(c[2]), "+f"(c[3])
                 : "r"(a[0]), "r"(a[1]), "r"(a[2]), "r"(a[3]), "r"(b[0]), "r"(b[1]));
}
__device__ __forceinline__ void cp16(uint32_t dst, const void* src) {
    asm volatile("cp.async.cg.shared.global [%0], [%1], 16;" :: "r"(dst), "l"(src));
}
#define CP_COMMIT asm volatile("cp.async.commit_group;" ::: "memory")
#define CP_WAIT1  asm volatile("cp.async.wait_group 1;" ::: "memory")
__device__ __forceinline__ uint32_t smem_u32(const void* p) {
    uint32_t a;
    asm("{ .reg .u64 t; cvta.to.shared.u64 t, %1; cvt.u32.u64 %0, t; }" : "=r"(a) : "l"(p));
    return a;
}

// ================= tf32 warp-MMA GEMM (NT, both operands pre-rounded, K-major) =================
// CTA tile 128x128, 4 warps (2m x 2n), warp tile 64x64, K-chunks of 32, 3-stage cp.async,
// register-double-buffered fragment pipeline.
// EPI: 0 store(+bias), 1 gelu(+bias), 3 C+=rowscale*v(+bias), 4 triple-write (x2 path)
#define PITCH 36
#define ST 3
#define KC 32
#define STAGE_W (2 * 128 * PITCH)
#define TC_SMEM (ST * STAGE_W * 4)            // 110592 bytes

template<int EPI, bool RND>
__global__ void __launch_bounds__(128, 2)
tc_gemm_k(const float* __restrict__ Ag, const float* __restrict__ Bg, float* __restrict__ Cg,
          int K, int lda, int ldb, int ldc,
          long long sA, long long sB, long long sC,
          const float* __restrict__ bias, const float* __restrict__ rowscale,
          int rs_stride, float alpha,
          const float* __restrict__ resid, float* __restrict__ aux1, float* __restrict__ aux2)
{
    extern __shared__ uint32_t sm[];
    const uint32_t smb = smem_u32(sm);
    const int tid = threadIdx.x, lane = tid & 31, wid = tid >> 5;
    const int m0 = blockIdx.y * 128, n0 = blockIdx.x * 128;
    const int wm = (wid >> 1) * 64, wn = (wid & 1) * 64;
    const int arow = tid >> 3, ac4 = (tid & 7) << 2;

    const float* A  = Ag + blockIdx.z * sA + (long long)(m0 + arow) * lda + ac4;
    const float* Bp = Bg + blockIdx.z * sB + (long long)(n0 + arow) * ldb + ac4;
    float* C = Cg + blockIdx.z * sC;

    const uint32_t myA = smb + (uint32_t)(arow * PITCH + ac4) * 4;
    const uint32_t myB = myA + 128 * PITCH * 4;

    float acc[4][8][4];
#pragma unroll
    for (int i = 0; i < 4; i++)
#pragma unroll
        for (int j = 0; j < 8; j++)
#pragma unroll
            for (int k = 0; k < 4; k++) acc[i][j][k] = 0.f;

    const int nch = K >> 5;

    auto issue = [&](int c) {
        const int s = c % ST;
        const uint32_t sa = myA + s * (STAGE_W * 4);
        const uint32_t sb = myB + s * (STAGE_W * 4);
        const float* ga = A + c * KC;
        const float* gb = Bp + c * KC;
#pragma unroll
        for (int i = 0; i < 8; i++) {
            cp16(sa + i * (16 * PITCH * 4), ga + (long long)i * 16 * lda);
            cp16(sb + i * (16 * PITCH * 4), gb + (long long)i * 16 * ldb);
        }
    };

    issue(0); CP_COMMIT;
    issue(1); CP_COMMIT;

    const int fr = lane >> 2, fq = lane & 3;
    uint32_t afA[4][4], bfA[8][2], afB[4][4], bfB[8][2];

#define LDFRAG(ks, af, bf) do { \
    const int kb_ = (ks) * 8 + fq; \
    _Pragma("unroll") \
    for (int mt = 0; mt < 4; mt++) { \
        const uint32_t* p_ = Ab + (wm + mt * 16 + fr) * PITCH + kb_; \
        af[mt][0] = p_[0]; af[mt][1] = p_[8 * PITCH]; \
        af[mt][2] = p_[4]; af[mt][3] = p_[8 * PITCH + 4]; \
    } \
    _Pragma("unroll") \
    for (int nt = 0; nt < 8; nt++) { \
        const uint32_t* p_ = Bb + (wn + nt * 8 + fr) * PITCH + kb_; \
        bf[nt][0] = p_[0]; bf[nt][1] = p_[4]; \
    } \
} while (0)

#define MMASET(af, bf) do { \
    _Pragma("unroll") \
    for (int mt = 0; mt < 4; mt++) \
        _Pragma("unroll") \
        for (int nt = 0; nt < 8; nt++) \
            mma1688(acc[mt][nt], af[mt], bf[nt]); \
} while (0)

    for (int c = 0; c < nch; c++) {
        CP_WAIT1;
        __syncthreads();
        if (c + ST - 1 < nch) issue(c + ST - 1);
        CP_COMMIT;

        const uint32_t* Ab = sm + (c % ST) * STAGE_W;
        const uint32_t* Bb = Ab + 128 * PITCH;

        LDFRAG(0, afA, bfA);
        LDFRAG(1, afB, bfB);
        MMASET(afA, bfA);
        LDFRAG(2, afA, bfA);
        MMASET(afB, bfB);
        LDFRAG(3, afB, bfB);
        MMASET(afA, bfA);
        MMASET(afB, bfB);
    }
#undef LDFRAG
#undef MMASET

    // ---- epilogue ----
    const int cq = (lane & 3) * 2;
#pragma unroll
    for (int mt = 0; mt < 4; mt++) {
        int gr0 = m0 + wm + mt * 16 + fr;
        int gr1 = gr0 + 8;
        float rs0 = 1.f, rs1 = 1.f;
        if (EPI == 3) {
            rs0 = rowscale[(long long)gr0 * rs_stride];
            rs1 = rowscale[(long long)gr1 * rs_stride];
        }
#pragma unroll
        for (int nt = 0; nt < 8; nt++) {
            int gc = n0 + wn + nt * 8 + cq;
            float b0 = bias ? bias[gc] : 0.f;
            float b1 = bias ? bias[gc + 1] : 0.f;
            float v00 = acc[mt][nt][0] * alpha + b0;
            float v01 = acc[mt][nt][1] * alpha + b1;
            float v10 = acc[mt][nt][2] * alpha + b0;
            float v11 = acc[mt][nt][3] * alpha + b1;
            long long o0 = (long long)gr0 * ldc + gc;
            long long o1 = (long long)gr1 * ldc + gc;
            if (EPI == 1) {
                v00 = gelu_f(v00); v01 = gelu_f(v01);
                v10 = gelu_f(v10); v11 = gelu_f(v11);
            }
            if (RND) {
                v00 = rndf(v00); v01 = rndf(v01);
                v10 = rndf(v10); v11 = rndf(v11);
            }
            if (EPI == 0 || EPI == 1) {
                *(float2*)(C + o0) = make_float2(v00, v01);
                *(float2*)(C + o1) = make_float2(v10, v11);
            } else if (EPI == 3) {
                C[o0] += rs0 * v00; C[o0 + 1] += rs0 * v01;
                C[o1] += rs1 * v10; C[o1 + 1] += rs1 * v11;
            } else { // EPI 4: x2 = resid + v; aux1 = rnd(x2); aux2 = x2
                float w00 = resid[o0] + v00, w01 = resid[o0 + 1] + v01;
                float w10 = resid[o1] + v10, w11 = resid[o1 + 1] + v11;
                *(float2*)(C + o0) = make_float2(w00, w01);
                *(float2*)(C + o1) = make_float2(w10, w11);
                *(float2*)(aux1 + o0) = make_float2(rndf(w00), rndf(w01));
                *(float2*)(aux1 + o1) = make_float2(rndf(w10), rndf(w11));
                *(float2*)(aux2 + o0) = make_float2(w00, w01);
                *(float2*)(aux2 + o1) = make_float2(w10, w11);
            }
        }
    }
}

static void tcg(int epi, bool rnd,
                const float* A, const float* Bm, float* C,
                int M, int N, int K, int lda, int ldb, int ldc,
                long long sA, long long sB, long long sC, int batch,
                const float* bias, const float* rowscale, int rs_stride, float alpha,
                const float* resid = nullptr, float* aux1 = nullptr, float* aux2 = nullptr)
{
    dim3 g(N / 128, M / 128, batch), blk(128);
#define LNCH(EP, RN) do { \
    cudaFuncSetAttribute(tc_gemm_k<EP, RN>, cudaFuncAttributeMaxDynamicSharedMemorySize, TC_SMEM); \
    tc_gemm_k<EP, RN><<<g, blk, TC_SMEM>>>(A, Bm, C, K, lda, ldb, ldc, sA, sB, sC, bias, rowscale, rs_stride, alpha, resid, aux1, aux2); \
} while (0)
    if (epi == 0) { if (rnd) LNCH(0, true); else LNCH(0, false); }
    else if (epi == 1) LNCH(1, true);
    else if (epi == 3) LNCH(3, false);
    else LNCH(4, false);
#undef LNCH
}

// ================= weight round + transpose: in[K][N] -> out[N][K] (tf32-rounded) =================
__global__ void roundT_k(const float* __restrict__ in, float* __restrict__ out,
                         int K, int N, long long inS, long long outS)
{
    __shared__ float t[32][33];
    const float* ip = in + blockIdx.z * inS;
    float* op = out + blockIdx.z * outS;
    int n0 = blockIdx.x * 32, k0 = blockIdx.y * 32;
    int tx = threadIdx.x & 31, ty = threadIdx.x >> 5;
#pragma unroll
    for (int i = 0; i < 32; i += 8)
        t[ty + i][tx] = ip[(long long)(k0 + ty + i) * N + n0 + tx];
    __syncthreads();
#pragma unroll
    for (int i = 0; i < 32; i += 8)
        op[(long long)(n0 + ty + i) * K + k0 + tx] = rndf(t[tx][ty + i]);
}

__global__ void round_copy_k(const float* __restrict__ a, float* __restrict__ b, int n) {
    int i = blockIdx.x * 256 + threadIdx.x;
    if (i < n) b[i] = rndf(a[i]);
}

// v transpose: qkv [BS][768] cols 512.. -> vT [B][H][S]
__global__ void vtrans_k(const float* __restrict__ qkv, float* __restrict__ vT) {
    __shared__ float t[32][33];
    int s0 = blockIdx.x * 32, h0 = blockIdx.y * 32, b = blockIdx.z;
    int tx = threadIdx.x & 31, ty = threadIdx.x >> 5;
#pragma unroll
    for (int i = 0; i < 32; i += 8)
        t[ty + i][tx] = qkv[(long long)(b * S_ + s0 + ty + i) * 768 + 512 + h0 + tx];
    __syncthreads();
#pragma unroll
    for (int i = 0; i < 32; i += 8)
        vT[(long long)b * H_ * S_ + (long long)(h0 + ty + i) * S_ + s0 + tx] = t[tx][ty + i];
}

// ================= fallback SIMT GEMM (small fp32 shapes) =================
template<bool TRANSB>
__global__ __launch_bounds__(256, 2)
void gemm_k(const float* __restrict__ Ag, const float* __restrict__ Bg,
            float* __restrict__ Cg,
            int M, int N, int K, int lda, int ldb, int ldc)
{
    __shared__ float As[8][128];
    __shared__ float Bs[8][128];
    const float* A = Ag;
    const float* Bm = Bg;
    float* C = Cg;
    const int m0 = blockIdx.y * 128, n0 = blockIdx.x * 128;
    const int tid = threadIdx.x;
    const int tx = tid & 15, ty = tid >> 4;

    float acc[8][8];
#pragma unroll
    for (int i = 0; i < 8; i++)
#pragma unroll
        for (int j = 0; j < 8; j++) acc[i][j] = 0.f;

    const int am = tid >> 1, ak = (tid & 1) << 2;

    for (int k0 = 0; k0 < K; k0 += 8) {
        float4 av = *(const float4*)(A + (long long)(m0 + am) * lda + k0 + ak);
        As[ak + 0][am] = av.x; As[ak + 1][am] = av.y;
        As[ak + 2][am] = av.z; As[ak + 3][am] = av.w;
        if (!TRANSB) {
            int bk = tid >> 5, bn = (tid & 31) << 2;
            float4 bv = make_float4(0.f, 0.f, 0.f, 0.f);
            if (n0 + bn < N)
                bv = *(const float4*)(Bm + (long long)(k0 + bk) * ldb + n0 + bn);
            *(float4*)&Bs[bk][bn] = bv;
        } else {
            int bn = tid >> 1, bk = (tid & 1) << 2;
            float4 bv = make_float4(0.f, 0.f, 0.f, 0.f);
            if (n0 + bn < N)
                bv = *(const float4*)(Bm + (long long)(n0 + bn) * ldb + k0 + bk);
            Bs[bk + 0][bn] = bv.x; Bs[bk + 1][bn] = bv.y;
            Bs[bk + 2][bn] = bv.z; Bs[bk + 3][bn] = bv.w;
        }
        __syncthreads();
#pragma unroll
        for (int k = 0; k < 8; k++) {
            float4 a0 = *(float4*)&As[k][ty * 4];
            float4 a1 = *(float4*)&As[k][ty * 4 + 64];
            float4 b0 = *(float4*)&Bs[k][tx * 4];
            float4 b1 = *(float4*)&Bs[k][tx * 4 + 64];
            float a[8] = {a0.x, a0.y, a0.z, a0.w, a1.x, a1.y, a1.z, a1.w};
            float b[8] = {b0.x, b0.y, b0.z, b0.w, b1.x, b1.y, b1.z, b1.w};
#pragma unroll
            for (int i = 0; i < 8; i++)
#pragma unroll
                for (int j = 0; j < 8; j++) acc[i][j] += a[i] * b[j];
        }
        __syncthreads();
    }

#pragma unroll
    for (int i = 0; i < 8; i++) {
        int gr = m0 + ty * 4 + (i & 3) + ((i >> 2) << 6);
        float* Crow = C + (long long)gr * ldc;
#pragma unroll
        for (int j = 0; j < 8; j++) {
            int gc = n0 + tx * 4 + (j & 3) + ((j >> 2) << 6);
            if (gc < N) Crow[gc] = acc[i][j];
        }
    }
}

// ---------------- softmax over full rows of 2048 (rounded output) ----------------
__global__ void softmax2048_k(float* __restrict__ Sc) {
    __shared__ float red[256];
    const int tid = threadIdx.x;
    float* p = Sc + (long long)blockIdx.x * 2048;
    float v[8];
    float mx = -3.4e38f;
#pragma unroll
    for (int i = 0; i < 8; i++) { v[i] = p[tid + i * 256]; mx = fmaxf(mx, v[i]); }
    red[tid] = mx; __syncthreads();
    for (int s = 128; s; s >>= 1) { if (tid < s) red[tid] = fmaxf(red[tid], red[tid + s]); __syncthreads(); }
    mx = red[0]; __syncthreads();
    float sum = 0.f;
#pragma unroll
    for (int i = 0; i < 8; i++) { v[i] = expf(v[i] - mx); sum += v[i]; }
    red[tid] = sum; __syncthreads();
    for (int s = 128; s; s >>= 1) { if (tid < s) red[tid] += red[tid + s]; __syncthreads(); }
    float inv = 1.f / red[0];
#pragma unroll
    for (int i = 0; i < 8; i++) p[tid + i * 256] = rndf(v[i] * inv);
}

// ---------------- sparse top-k via exact radix select + masked softmax ----------------
__global__ void sparse_softmax_k(float* __restrict__ Sc) {
    __shared__ uint32_t hist[256];
    __shared__ uint32_t sfx[257];
    __shared__ uint32_t s_prefix, s_k;
    __shared__ float red[256];
    const int tid = threadIdx.x;
    float* p = Sc + (long long)blockIdx.x * 2048;

    float v[8]; uint32_t key[8];
    float mx = -3.4e38f;
#pragma unroll
    for (int i = 0; i < 8; i++) {
        v[i] = p[tid + i * 256];
        mx = fmaxf(mx, v[i]);
        uint32_t u = __float_as_uint(v[i]);
        key[i] = (u & 0x80000000u) ? ~u : (u | 0x80000000u);
    }
    red[tid] = mx; __syncthreads();
    for (int s = 128; s; s >>= 1) { if (tid < s) red[tid] = fmaxf(red[tid], red[tid + s]); __syncthreads(); }
    mx = red[0];

    uint32_t prefix = 0, kk = KSP_;
#pragma unroll 1
    for (int b = 3; b >= 0; b--) {
        const int sh = b * 8;
        const uint32_t pmask = (b == 3) ? 0u : ~((1u << (sh + 8)) - 1u);
        hist[tid] = 0;
        if (tid == 0) sfx[256] = 0;
        __syncthreads();
#pragma unroll
        for (int i = 0; i < 8; i++)
            if ((key[i] & pmask) == prefix)
                atomicAdd(&hist[(key[i] >> sh) & 255u], 1u);
        __syncthreads();
        sfx[tid] = hist[tid];
        __syncthreads();
        for (int off = 1; off < 256; off <<= 1) {
            uint32_t add = (tid + off < 256) ? sfx[tid + off] : 0u;
            __syncthreads();
            sfx[tid] += add;
            __syncthreads();
        }
        if (sfx[tid] >= kk && (tid == 255 || sfx[tid + 1] < kk)) {
            s_prefix = prefix | ((uint32_t)tid << sh);
            s_k = kk - sfx[tid + 1];
        }
        __syncthreads();
        prefix = s_prefix; kk = s_k;
        __syncthreads();
    }
    const uint32_t tk = prefix;
    const float thr = (tk & 0x80000000u) ? __uint_as_float(tk ^ 0x80000000u)
                                         : __uint_as_float(~tk);

    float e[8]; float sum = 0.f;
#pragma unroll
    for (int i = 0; i < 8; i++) {
        float ev = (v[i] >= thr) ? expf(v[i] - mx) : 0.f;
        e[i] = ev; sum += ev;
    }
    red[tid] = sum; __syncthreads();
    for (int s = 128; s; s >>= 1) { if (tid < s) red[tid] += red[tid + s]; __syncthreads(); }
    float inv = 1.f / red[0];
#pragma unroll
    for (int i = 0; i < 8; i++) p[tid + i * 256] = rndf(e[i] * inv);
}

// ---------------- softmax rows of 64 ----------------
__global__ void softmax64_k(float* __restrict__ mw, int rows) {
    int row = (blockIdx.x * blockDim.x + threadIdx.x) >> 5;
    int lane = threadIdx.x & 31;
    if (row >= rows) return;
    float* p = mw + (long long)row * 64;
    float a = p[lane], b = p[lane + 32];
    float mx = fmaxf(a, b);
    for (int o = 16; o; o >>= 1) mx = fmaxf(mx, __shfl_xor_sync(0xffffffffu, mx, o));
    float ea = expf(a - mx), eb = expf(b - mx);
    float s = ea + eb;
    for (int o = 16; o; o >>= 1) s += __shfl_xor_sync(0xffffffffu, s, o);
    float inv = 1.f / s;
    p[lane] = ea * inv; p[lane + 32] = eb * inv;
}

// ---------------- router ----------------
__global__ void router_k(const float* __restrict__ x2, const float* __restrict__ Wr,
                         const float* __restrict__ br, float* __restrict__ rw, int rows) {
    int tok = (blockIdx.x * blockDim.x + threadIdx.x) >> 5;
    int lane = threadIdx.x & 31;
    if (tok >= rows) return;
    const float* xr = x2 + (long long)tok * D_;
    float s0 = 0.f, s1 = 0.f, s2 = 0.f, s3 = 0.f;
    for (int d = lane; d < D_; d += 32) {
        float xv = xr[d];
        const float* w = Wr + d * 4;
        s0 += xv * w[0]; s1 += xv * w[1]; s2 += xv * w[2]; s3 += xv * w[3];
    }
    for (int o = 16; o; o >>= 1) {
        s0 += __shfl_xor_sync(0xffffffffu, s0, o);
        s1 += __shfl_xor_sync(0xffffffffu, s1, o);
        s2 += __shfl_xor_sync(0xffffffffu, s2, o);
        s3 += __shfl_xor_sync(0xffffffffu, s3, o);
    }
    if (lane == 0) {
        s0 += br[0]; s1 += br[1]; s2 += br[2]; s3 += br[3];
        float mx = fmaxf(fmaxf(s0, s1), fmaxf(s2, s3));
        float e0 = expf(s0 - mx), e1 = expf(s1 - mx), e2 = expf(s2 - mx), e3 = expf(s3 - mx);
        float inv = 1.f / (e0 + e1 + e2 + e3);
        float* o4 = rw + (long long)tok * 4;
        o4[0] = e0 * inv; o4[1] = e1 * inv; o4[2] = e2 * inv; o4[3] = e3 * inv;
    }
}

// ---------------- launch ----------------
extern "C" void kernel_launch(void* const* d_in, const int* in_sizes, int n_in,
                              void* d_out, int out_size) {
    const float* x     = (const float*)d_in[0];
    const float* WqkvL = (const float*)d_in[1];
    const float* WqkvS = (const float*)d_in[2];
    const float* memb  = (const float*)d_in[3];
    const float* Wm    = (const float*)d_in[4];
    const float* Wo    = (const float*)d_in[5];
    const float* bo    = (const float*)d_in[6];
    const float* Wi    = (const float*)d_in[7];
    const float* bi    = (const float*)d_in[8];
    const float* Wp1   = (const float*)d_in[9];
    const float* bp1   = (const float*)d_in[10];
    const float* Wp2   = (const float*)d_in[11];
    const float* bp2   = (const float*)d_in[12];
    const float* Wwb   = (const float*)d_in[13];
    const float* bwb   = (const float*)d_in[14];
    const float* Wr    = (const float*)d_in[15];
    const float* br    = (const float*)d_in[16];
    const float* We1   = (const float*)d_in[17];
    const float* be1   = (const float*)d_in[18];
    const float* We2   = (const float*)d_in[19];
    const float* be2   = (const float*)d_in[20];
    float* out = (float*)d_out;

    float *qkvL, *qkvS, *sc, *mc, *mcr, *mw, *hy, *x2, *x2r, *xr, *pp, *tt, *rw, *hh, *vtl, *vts;
    float *wqkvl_t, *wqkvs_t, *wm_t, *wo_t, *wi_t, *wp1_t, *wp2_t, *wwb_t, *we1_t, *we2_t;
    cudaGetSymbolAddress((void**)&qkvL, g_qkv_loc);
    cudaGetSymbolAddress((void**)&qkvS, g_qkv_sp);
    cudaGetSymbolAddress((void**)&sc,   g_scores);
    cudaGetSymbolAddress((void**)&mc,   g_memcat);
    cudaGetSymbolAddress((void**)&mcr,  g_mcr);
    cudaGetSymbolAddress((void**)&mw,   g_mw);
    cudaGetSymbolAddress((void**)&hy,   g_hydra);
    cudaGetSymbolAddress((void**)&x2,   g_x2);
    cudaGetSymbolAddress((void**)&x2r,  g_x2r);
    cudaGetSymbolAddress((void**)&xr,   g_xr);
    cudaGetSymbolAddress((void**)&pp,   g_pp);
    cudaGetSymbolAddress((void**)&tt,   g_t);
    cudaGetSymbolAddress((void**)&rw,   g_rw);
    cudaGetSymbolAddress((void**)&hh,   g_h);
    cudaGetSymbolAddress((void**)&vtl,  g_vtl);
    cudaGetSymbolAddress((void**)&vts,  g_vts);
    cudaGetSymbolAddress((void**)&wqkvl_t, g_wqkvl_t);
    cudaGetSymbolAddress((void**)&wqkvs_t, g_wqkvs_t);
    cudaGetSymbolAddress((void**)&wm_t,  g_wm_t);
    cudaGetSymbolAddress((void**)&wo_t,  g_wo_t);
    cudaGetSymbolAddress((void**)&wi_t,  g_wi_t);
    cudaGetSymbolAddress((void**)&wp1_t, g_wp1_t);
    cudaGetSymbolAddress((void**)&wp2_t, g_wp2_t);
    cudaGetSymbolAddress((void**)&wwb_t, g_wwb_t);
    cudaGetSymbolAddress((void**)&we1_t, g_we1_t);
    cudaGetSymbolAddress((void**)&we2_t, g_we2_t);

    const float scale = 0.0625f; // H^-0.5
    dim3 t256(256);

    // ---- minimal pre-pass for first GEMM (launch #6 = QKV GEMM for ncu) ----
    roundT_k<<<dim3(768 / 32, 1024 / 32, 1), t256>>>(WqkvL, wqkvl_t, 1024, 768, 0, 0);   // 1
    roundT_k<<<dim3(768 / 32, 1024 / 32, 1), t256>>>(WqkvS, wqkvs_t, 1024, 768, 0, 0);   // 2
    roundT_k<<<dim3(256 / 32, 1024 / 32, 1), t256>>>(Wm, wm_t, 1024, 256, 0, 0);         // 3
    roundT_k<<<dim3(256 / 32, 512 / 32, 1), t256>>>(Wo, wo_t, 512, 256, 0, 0);           // 4
    round_copy_k<<<(BS_ * D_ + 255) / 256, 256>>>(x, xr, BS_ * D_);                      // 5

    // ---- local attention ----
    tcg(0, true, xr, wqkvl_t, qkvL, BS_, 768, D_, D_, D_, 768, 0, 0, 0, 1, nullptr, nullptr, 0, 1.f); // 6 <- profiled
    vtrans_k<<<dim3(S_ / 32, H_ / 32, B_), t256>>>(qkvL, vtl);
    tcg(0, false, qkvL, qkvL + H_, sc, S_, S_, H_, 768, 768, S_,
        (long long)S_ * 768, (long long)S_ * 768, (long long)S_ * S_, B_, nullptr, nullptr, 0, scale);
    softmax2048_k<<<BS_, 256>>>(sc);
    tcg(0, true, sc, vtl, hy, S_, H_, S_, S_, S_, 4 * H_,
        (long long)S_ * S_, (long long)H_ * S_, (long long)S_ * 4 * H_, B_, nullptr, nullptr, 0, 1.f);

    // ---- sparse attention ----
    tcg(0, true, xr, wqkvs_t, qkvS, BS_, 768, D_, D_, D_, 768, 0, 0, 0, 1, nullptr, nullptr, 0, 1.f);
    vtrans_k<<<dim3(S_ / 32, H_ / 32, B_), t256>>>(qkvS, vts);
    tcg(0, false, qkvS, qkvS + H_, sc, S_, S_, H_, 768, 768, S_,
        (long long)S_ * 768, (long long)S_ * 768, (long long)S_ * S_, B_, nullptr, nullptr, 0, scale);
    sparse_softmax_k<<<BS_, 256>>>(sc);
    tcg(0, true, sc, vts, hy + H_, S_, H_, S_, S_, S_, 4 * H_,
        (long long)S_ * S_, (long long)H_ * S_, (long long)S_ * 4 * H_, B_, nullptr, nullptr, 0, 1.f);

    // ---- memory branch ----
    tcg(0, false, xr, wm_t, mc, BS_, H_, D_, D_, D_, 2 * H_, 0, 0, 0, 1, nullptr, nullptr, 0, 1.f);
    gemm_k<true><<<dim3(1, BS_ / 128, 1), t256>>>(mc, memb, mw, BS_, M_, H_, 2 * H_, H_, M_);
    softmax64_k<<<(BS_ * 32 + 255) / 256, 256>>>(mw, BS_);
    gemm_k<false><<<dim3(2, BS_ / 128, 1), t256>>>(mw, memb, mc + H_, BS_, H_, M_, M_, H_, 2 * H_);
    round_copy_k<<<(BS_ * 2 * H_ + 255) / 256, 256>>>(mc, mcr, BS_ * 2 * H_);
    tcg(0, true, mcr, wo_t, hy + 2 * H_, BS_, H_, 2 * H_, 2 * H_, 2 * H_, 4 * H_, 0, 0, 0, 1, bo, nullptr, 0, 1.f);

    // ---- predictor branch (round weights just-in-time) ----
    roundT_k<<<dim3(256 / 32, 1024 / 32, 1), t256>>>(Wi, wi_t, 1024, 256, 0, 0);
    roundT_k<<<dim3(512 / 32, 256 / 32, 1), t256>>>(Wp1, wp1_t, 256, 512, 0, 0);
    roundT_k<<<dim3(256 / 32, 512 / 32, 1), t256>>>(Wp2, wp2_t, 512, 256, 0, 0);
    roundT_k<<<dim3(1024 / 32, 1024 / 32, 1), t256>>>(Wwb, wwb_t, 1024, 1024, 0, 0);
    tcg(0, true, xr, wi_t, pp, BS_, H_, D_, D_, D_, H_, 0, 0, 0, 1, bi, nullptr, 0, 1.f);
    tcg(1, true, pp, wp1_t, tt, BS_, 2 * H_, H_, H_, H_, 2 * H_, 0, 0, 0, 1, bp1, nullptr, 0, 1.f);
    tcg(0, true, tt, wp2_t, hy + 3 * H_, BS_, H_, 2 * H_, 2 * H_, 2 * H_, 4 * H_, 0, 0, 0, 1, bp2, nullptr, 0, 1.f);

    // ---- hydra combine (fused: x2 = x + concat@Wwb + bwb; x2r = rnd(x2); out = x2) ----
    tcg(4, false, hy, wwb_t, x2, BS_, D_, 4 * H_, 4 * H_, 4 * H_, D_, 0, 0, 0, 1, bwb, nullptr, 0, 1.f,
        x, x2r, out);

    // ---- router + MoE ----
    router_k<<<(BS_ * 32 + 255) / 256, 256>>>(x2, Wr, br, rw, BS_);
    roundT_k<<<dim3(F_ / 32, D_ / 32, E_), t256>>>(We1, we1_t, D_, F_, (long long)D_ * F_, (long long)F_ * D_);
    roundT_k<<<dim3(D_ / 32, F_ / 32, E_), t256>>>(We2, we2_t, F_, D_, (long long)F_ * D_, (long long)D_ * F_);
    for (int e = 0; e < E_; e++) {
        tcg(1, true, x2r, we1_t + (long long)e * F_ * D_, hh,
            BS_, F_, D_, D_, D_, F_, 0, 0, 0, 1, be1 + (long long)e * F_, nullptr, 0, 1.f);
        tcg(3, false, hh, we2_t + (long long)e * D_ * F_, out,
            BS_, D_, F_, F_, F_, D_, 0, 0, 0, 1, be2 + (long long)e * D_, rw + e, E_, 1.f);
    }
}

// round 7
// speedup vs baseline: 3.4908x; 1.0607x over previous
#include <cuda_runtime.h>
#include <cuda_bf16.h>
#include <math.h>
#include <stdint.h>

// ---------------- problem constants ----------------
#define B_   4
#define S_   2048
#define D_   1024
#define H_   256
#define E_   4
#define F_   4096
#define M_   64
#define BS_  (B_ * S_)          // 8192
#define KSP_ 204                // int(2048*0.1)

// ---------------- scratch (device globals; no allocation allowed) ----------------
__device__ float g_qkv_loc[(size_t)BS_ * 3 * H_];
__device__ float g_qkv_sp [(size_t)BS_ * 3 * H_];
__device__ float g_scores [(size_t)B_ * S_ * S_];
__device__ float g_memcat [(size_t)BS_ * 2 * H_];
__device__ float g_mcr    [(size_t)BS_ * 2 * H_];
__device__ float g_mw     [(size_t)BS_ * M_];
__device__ float g_hydra  [(size_t)BS_ * 4 * H_];
__device__ float g_x2     [(size_t)BS_ * D_];
__device__ float g_x2r    [(size_t)BS_ * D_];
__device__ float g_xr     [(size_t)BS_ * D_];
__device__ float g_pp     [(size_t)BS_ * H_];
__device__ float g_t      [(size_t)BS_ * 2 * H_];
__device__ float g_rw     [(size_t)BS_ * E_];
__device__ float g_h      [(size_t)BS_ * F_];
__device__ float g_vtl    [(size_t)B_ * H_ * S_];
__device__ float g_vts    [(size_t)B_ * H_ * S_];
// transposed+rounded weights [N][K]
__device__ float g_wqkvl_t[(size_t)768 * 1024];
__device__ float g_wqkvs_t[(size_t)768 * 1024];
__device__ float g_wm_t   [(size_t)256 * 1024];
__device__ float g_wo_t   [(size_t)256 * 512];
__device__ float g_wi_t   [(size_t)256 * 1024];
__device__ float g_wp1_t  [(size_t)512 * 256];
__device__ float g_wp2_t  [(size_t)256 * 512];
__device__ float g_wwb_t  [(size_t)1024 * 1024];
__device__ float g_we1_t  [(size_t)E_ * F_ * D_];
__device__ float g_we2_t  [(size_t)E_ * D_ * F_];

__device__ __forceinline__ float gelu_f(float x) {
    return 0.5f * x * (1.0f + erff(x * 0.7071067811865476f));
}
__device__ __forceinline__ uint32_t f2tf32(float f) {
    uint32_t r; asm("cvt.rna.tf32.f32 %0, %1;" : "=r"(r) : "f"(f)); return r;
}
__device__ __forceinline__ float rndf(float f) { return __uint_as_float(f2tf32(f)); }
__device__ __forceinline__ void mma1688(float* c, const uint32_t* a, const uint32_t* b) {
    asm volatile("mma.sync.aligned.m16n8k8.row.col.f32.tf32.tf32.f32 "
                 "{%0,%1,%2,%3}, {%4,%5,%6,%7}, {%8,%9}, {%0,%1,%2,%3};"
                 : "+f"(c[0]), "+f"(c[1]), "+f"(c[2]), "+f"(c[3])
                 : "r"(a[0]), "r"(a[1]), "r"(a[2]), "r"(a[3]), "r"(b[0]), "r"(b[1]));
}
__device__ __forceinline__ void cp16(uint32_t dst, const void* src) {
    asm volatile("cp.async.cg.shared.global [%0], [%1], 16;" :: "r"(dst), "l"(src));
}
#define CP_COMMIT asm volatile("cp.async.commit_group;" ::: "memory")
#define CP_WAIT1  asm volatile("cp.async.wait_group 1;" ::: "memory")
#define CP_WAIT0  asm volatile("cp.async.wait_group 0;" ::: "memory")
__device__ __forceinline__ uint32_t smem_u32(const void* p) {
    uint32_t a;
    asm("{ .reg .u64 t; cvta.to.shared.u64 t, %1; cvt.u32.u64 %0, t; }" : "=r"(a) : "l"(p));
    return a;
}

// ================= tf32 warp-MMA GEMM (NT, pre-rounded, K-major) =================
// CTA tile 128x128, 4 warps (2m x 2n), warp tile 64x64, K-chunks of 32, 2-stage cp.async.
// k axis inside each 8-group permuted (logical fq <-> stored 2fq, fq+4 <-> 2fq+1) so
// fragment loads are LDS.64, conflict-free with PITCH=40 (PITCH % 32 == 8).
// EPI: 0 store(+bias), 1 gelu(+bias), 3 C+=rowscale*v(+bias), 4 triple-write (x2 path)
#define PITCH 40
#define KC 32
#define STAGE_W (2 * 128 * PITCH)
#define TC_SMEM (2 * STAGE_W * 4)             // 81920 bytes

template<int EPI, bool RND>
__global__ void __launch_bounds__(128, 2)
tc_gemm_k(const float* __restrict__ Ag, const float* __restrict__ Bg, float* __restrict__ Cg,
          int K, int lda, int ldb, int ldc,
          long long sA, long long sB, long long sC,
          const float* __restrict__ bias, const float* __restrict__ rowscale,
          int rs_stride, float alpha,
          const float* __restrict__ resid, float* __restrict__ aux1, float* __restrict__ aux2)
{
    extern __shared__ uint32_t sm[];
    const uint32_t smb = smem_u32(sm);
    const int tid = threadIdx.x, lane = tid & 31, wid = tid >> 5;
    const int m0 = blockIdx.y * 128, n0 = blockIdx.x * 128;
    const int wm = (wid >> 1) * 64, wn = (wid & 1) * 64;
    const int arow = tid >> 3, ac4 = (tid & 7) << 2;

    const float* A  = Ag + blockIdx.z * sA + (long long)(m0 + arow) * lda + ac4;
    const float* Bp = Bg + blockIdx.z * sB + (long long)(n0 + arow) * ldb + ac4;
    float* C = Cg + blockIdx.z * sC;

    const uint32_t myA = smb + (uint32_t)(arow * PITCH + ac4) * 4;
    const uint32_t myB = myA + 128 * PITCH * 4;

    float acc[4][8][4];
#pragma unroll
    for (int i = 0; i < 4; i++)
#pragma unroll
        for (int j = 0; j < 8; j++)
#pragma unroll
            for (int k = 0; k < 4; k++) acc[i][j][k] = 0.f;

    const int nch = K >> 5;

    auto issue = [&](int c) {
        const int s = c & 1;
        const uint32_t sa = myA + s * (STAGE_W * 4);
        const uint32_t sb = myB + s * (STAGE_W * 4);
        const float* ga = A + c * KC;
        const float* gb = Bp + c * KC;
#pragma unroll
        for (int i = 0; i < 8; i++) {
            cp16(sa + i * (16 * PITCH * 4), ga + (long long)i * 16 * lda);
            cp16(sb + i * (16 * PITCH * 4), gb + (long long)i * 16 * ldb);
        }
    };

    issue(0); CP_COMMIT;

    const int fr = lane >> 2, fq2 = (lane & 3) << 1;   // permuted k base: 2*fq
    uint32_t afA[4][4], bfA[8][2], afB[4][4], bfB[8][2];

// k-permuted fragment load: logical k {fq, fq+4} <-> stored {2fq, 2fq+1} (LDS.64)
#define LDFRAG(ks, af, bf) do { \
    const int kb_ = (ks) * 8 + fq2; \
    _Pragma("unroll") \
    for (int mt = 0; mt < 4; mt++) { \
        const uint32_t* p_ = Ab + (wm + mt * 16 + fr) * PITCH + kb_; \
        uint2 lo_ = *(const uint2*)p_; \
        uint2 hi_ = *(const uint2*)(p_ + 8 * PITCH); \
        af[mt][0] = lo_.x; af[mt][1] = hi_.x; af[mt][2] = lo_.y; af[mt][3] = hi_.y; \
    } \
    _Pragma("unroll") \
    for (int nt = 0; nt < 8; nt++) { \
        uint2 v_ = *(const uint2*)(Bb + (wn + nt * 8 + fr) * PITCH + kb_); \
        bf[nt][0] = v_.x; bf[nt][1] = v_.y; \
    } \
} while (0)

#define MMASET(af, bf) do { \
    _Pragma("unroll") \
    for (int mt = 0; mt < 4; mt++) \
        _Pragma("unroll") \
        for (int nt = 0; nt < 8; nt++) \
            mma1688(acc[mt][nt], af[mt], bf[nt]); \
} while (0)

    for (int c = 0; c < nch; c++) {
        if (c + 1 < nch) { issue(c + 1); CP_COMMIT; CP_WAIT1; }
        else             { CP_WAIT0; }
        __syncthreads();

        const uint32_t* Ab = sm + (c & 1) * STAGE_W;
        const uint32_t* Bb = Ab + 128 * PITCH;

        LDFRAG(0, afA, bfA);
        LDFRAG(1, afB, bfB);
        MMASET(afA, bfA);
        LDFRAG(2, afA, bfA);
        MMASET(afB, bfB);
        LDFRAG(3, afB, bfB);
        MMASET(afA, bfA);
        MMASET(afB, bfB);

        __syncthreads();   // protect this buffer before it is overwritten at c+2
    }
#undef LDFRAG
#undef MMASET

    // ---- epilogue ----
    const int cq = (lane & 3) * 2;
#pragma unroll
    for (int mt = 0; mt < 4; mt++) {
        int gr0 = m0 + wm + mt * 16 + fr;
        int gr1 = gr0 + 8;
        float rs0 = 1.f, rs1 = 1.f;
        if (EPI == 3) {
            rs0 = rowscale[(long long)gr0 * rs_stride];
            rs1 = rowscale[(long long)gr1 * rs_stride];
        }
#pragma unroll
        for (int nt = 0; nt < 8; nt++) {
            int gc = n0 + wn + nt * 8 + cq;
            float b0 = bias ? bias[gc] : 0.f;
            float b1 = bias ? bias[gc + 1] : 0.f;
            float v00 = acc[mt][nt][0] * alpha + b0;
            float v01 = acc[mt][nt][1] * alpha + b1;
            float v10 = acc[mt][nt][2] * alpha + b0;
            float v11 = acc[mt][nt][3] * alpha + b1;
            long long o0 = (long long)gr0 * ldc + gc;
            long long o1 = (long long)gr1 * ldc + gc;
            if (EPI == 1) {
                v00 = gelu_f(v00); v01 = gelu_f(v01);
                v10 = gelu_f(v10); v11 = gelu_f(v11);
            }
            if (RND) {
                v00 = rndf(v00); v01 = rndf(v01);
                v10 = rndf(v10); v11 = rndf(v11);
            }
            if (EPI == 0 || EPI == 1) {
                *(float2*)(C + o0) = make_float2(v00, v01);
                *(float2*)(C + o1) = make_float2(v10, v11);
            } else if (EPI == 3) {
                C[o0] += rs0 * v00; C[o0 + 1] += rs0 * v01;
                C[o1] += rs1 * v10; C[o1 + 1] += rs1 * v11;
            } else { // EPI 4: x2 = resid + v; aux1 = rnd(x2); aux2 = x2
                float w00 = resid[o0] + v00, w01 = resid[o0 + 1] + v01;
                float w10 = resid[o1] + v10, w11 = resid[o1 + 1] + v11;
                *(float2*)(C + o0) = make_float2(w00, w01);
                *(float2*)(C + o1) = make_float2(w10, w11);
                *(float2*)(aux1 + o0) = make_float2(rndf(w00), rndf(w01));
                *(float2*)(aux1 + o1) = make_float2(rndf(w10), rndf(w11));
                *(float2*)(aux2 + o0) = make_float2(w00, w01);
                *(float2*)(aux2 + o1) = make_float2(w10, w11);
            }
        }
    }
}

static void tcg(int epi, bool rnd,
                const float* A, const float* Bm, float* C,
                int M, int N, int K, int lda, int ldb, int ldc,
                long long sA, long long sB, long long sC, int batch,
                const float* bias, const float* rowscale, int rs_stride, float alpha,
                const float* resid = nullptr, float* aux1 = nullptr, float* aux2 = nullptr)
{
    dim3 g(N / 128, M / 128, batch), blk(128);
#define LNCH(EP, RN) do { \
    cudaFuncSetAttribute(tc_gemm_k<EP, RN>, cudaFuncAttributeMaxDynamicSharedMemorySize, TC_SMEM); \
    tc_gemm_k<EP, RN><<<g, blk, TC_SMEM>>>(A, Bm, C, K, lda, ldb, ldc, sA, sB, sC, bias, rowscale, rs_stride, alpha, resid, aux1, aux2); \
} while (0)
    if (epi == 0) { if (rnd) LNCH(0, true); else LNCH(0, false); }
    else if (epi == 1) LNCH(1, true);
    else if (epi == 3) LNCH(3, false);
    else LNCH(4, false);
#undef LNCH
}

// ================= weight round + transpose: in[K][N] -> out[N][K] (tf32-rounded) =================
__global__ void roundT_k(const float* __restrict__ in, float* __restrict__ out,
                         int K, int N, long long inS, long long outS)
{
    __shared__ float t[32][33];
    const float* ip = in + blockIdx.z * inS;
    float* op = out + blockIdx.z * outS;
    int n0 = blockIdx.x * 32, k0 = blockIdx.y * 32;
    int tx = threadIdx.x & 31, ty = threadIdx.x >> 5;
#pragma unroll
    for (int i = 0; i < 32; i += 8)
        t[ty + i][tx] = ip[(long long)(k0 + ty + i) * N + n0 + tx];
    __syncthreads();
#pragma unroll
    for (int i = 0; i < 32; i += 8)
        op[(long long)(n0 + ty + i) * K + k0 + tx] = rndf(t[tx][ty + i]);
}

__global__ void round_copy_k(const float* __restrict__ a, float* __restrict__ b, int n) {
    int i = blockIdx.x * 256 + threadIdx.x;
    if (i < n) b[i] = rndf(a[i]);
}

// v transpose: qkv [BS][768] cols 512.. -> vT [B][H][S]
__global__ void vtrans_k(const float* __restrict__ qkv, float* __restrict__ vT) {
    __shared__ float t[32][33];
    int s0 = blockIdx.x * 32, h0 = blockIdx.y * 32, b = blockIdx.z;
    int tx = threadIdx.x & 31, ty = threadIdx.x >> 5;
#pragma unroll
    for (int i = 0; i < 32; i += 8)
        t[ty + i][tx] = qkv[(long long)(b * S_ + s0 + ty + i) * 768 + 512 + h0 + tx];
    __syncthreads();
#pragma unroll
    for (int i = 0; i < 32; i += 8)
        vT[(long long)b * H_ * S_ + (long long)(h0 + ty + i) * S_ + s0 + tx] = t[tx][ty + i];
}

// ================= fallback SIMT GEMM (small fp32 shapes) =================
template<bool TRANSB>
__global__ __launch_bounds__(256, 2)
void gemm_k(const float* __restrict__ Ag, const float* __restrict__ Bg,
            float* __restrict__ Cg,
            int M, int N, int K, int lda, int ldb, int ldc)
{
    __shared__ float As[8][128];
    __shared__ float Bs[8][128];
    const float* A = Ag;
    const float* Bm = Bg;
    float* C = Cg;
    const int m0 = blockIdx.y * 128, n0 = blockIdx.x * 128;
    const int tid = threadIdx.x;
    const int tx = tid & 15, ty = tid >> 4;

    float acc[8][8];
#pragma unroll
    for (int i = 0; i < 8; i++)
#pragma unroll
        for (int j = 0; j < 8; j++) acc[i][j] = 0.f;

    const int am = tid >> 1, ak = (tid & 1) << 2;

    for (int k0 = 0; k0 < K; k0 += 8) {
        float4 av = *(const float4*)(A + (long long)(m0 + am) * lda + k0 + ak);
        As[ak + 0][am] = av.x; As[ak + 1][am] = av.y;
        As[ak + 2][am] = av.z; As[ak + 3][am] = av.w;
        if (!TRANSB) {
            int bk = tid >> 5, bn = (tid & 31) << 2;
            float4 bv = make_float4(0.f, 0.f, 0.f, 0.f);
            if (n0 + bn < N)
                bv = *(const float4*)(Bm + (long long)(k0 + bk) * ldb + n0 + bn);
            *(float4*)&Bs[bk][bn] = bv;
        } else {
            int bn = tid >> 1, bk = (tid & 1) << 2;
            float4 bv = make_float4(0.f, 0.f, 0.f, 0.f);
            if (n0 + bn < N)
                bv = *(const float4*)(Bm + (long long)(n0 + bn) * ldb + k0 + bk);
            Bs[bk + 0][bn] = bv.x; Bs[bk + 1][bn] = bv.y;
            Bs[bk + 2][bn] = bv.z; Bs[bk + 3][bn] = bv.w;
        }
        __syncthreads();
#pragma unroll
        for (int k = 0; k < 8; k++) {
            float4 a0 = *(float4*)&As[k][ty * 4];
            float4 a1 = *(float4*)&As[k][ty * 4 + 64];
            float4 b0 = *(float4*)&Bs[k][tx * 4];
            float4 b1 = *(float4*)&Bs[k][tx * 4 + 64];
            float a[8] = {a0.x, a0.y, a0.z, a0.w, a1.x, a1.y, a1.z, a1.w};
            float b[8] = {b0.x, b0.y, b0.z, b0.w, b1.x, b1.y, b1.z, b1.w};
#pragma unroll
            for (int i = 0; i < 8; i++)
#pragma unroll
                for (int j = 0; j < 8; j++) acc[i][j] += a[i] * b[j];
        }
        __syncthreads();
    }

#pragma unroll
    for (int i = 0; i < 8; i++) {
        int gr = m0 + ty * 4 + (i & 3) + ((i >> 2) << 6);
        float* Crow = C + (long long)gr * ldc;
#pragma unroll
        for (int j = 0; j < 8; j++) {
            int gc = n0 + tx * 4 + (j & 3) + ((j >> 2) << 6);
            if (gc < N) Crow[gc] = acc[i][j];
        }
    }
}

// ---------------- softmax over full rows of 2048 (rounded output) ----------------
__global__ void softmax2048_k(float* __restrict__ Sc) {
    __shared__ float red[256];
    const int tid = threadIdx.x;
    float* p = Sc + (long long)blockIdx.x * 2048;
    float v[8];
    float mx = -3.4e38f;
#pragma unroll
    for (int i = 0; i < 8; i++) { v[i] = p[tid + i * 256]; mx = fmaxf(mx, v[i]); }
    red[tid] = mx; __syncthreads();
    for (int s = 128; s; s >>= 1) { if (tid < s) red[tid] = fmaxf(red[tid], red[tid + s]); __syncthreads(); }
    mx = red[0]; __syncthreads();
    float sum = 0.f;
#pragma unroll
    for (int i = 0; i < 8; i++) { v[i] = expf(v[i] - mx); sum += v[i]; }
    red[tid] = sum; __syncthreads();
    for (int s = 128; s; s >>= 1) { if (tid < s) red[tid] += red[tid + s]; __syncthreads(); }
    float inv = 1.f / red[0];
#pragma unroll
    for (int i = 0; i < 8; i++) p[tid + i * 256] = rndf(v[i] * inv);
}

// ---------------- sparse top-k via exact radix select + masked softmax ----------------
__global__ void sparse_softmax_k(float* __restrict__ Sc) {
    __shared__ uint32_t hist[256];
    __shared__ uint32_t sfx[257];
    __shared__ uint32_t s_prefix, s_k;
    __shared__ float red[256];
    const int tid = threadIdx.x;
    float* p = Sc + (long long)blockIdx.x * 2048;

    float v[8]; uint32_t key[8];
    float mx = -3.4e38f;
#pragma unroll
    for (int i = 0; i < 8; i++) {
        v[i] = p[tid + i * 256];
        mx = fmaxf(mx, v[i]);
        uint32_t u = __float_as_uint(v[i]);
        key[i] = (u & 0x80000000u) ? ~u : (u | 0x80000000u);
    }
    red[tid] = mx; __syncthreads();
    for (int s = 128; s; s >>= 1) { if (tid < s) red[tid] = fmaxf(red[tid], red[tid + s]); __syncthreads(); }
    mx = red[0];

    uint32_t prefix = 0, kk = KSP_;
#pragma unroll 1
    for (int b = 3; b >= 0; b--) {
        const int sh = b * 8;
        const uint32_t pmask = (b == 3) ? 0u : ~((1u << (sh + 8)) - 1u);
        hist[tid] = 0;
        if (tid == 0) sfx[256] = 0;
        __syncthreads();
#pragma unroll
        for (int i = 0; i < 8; i++)
            if ((key[i] & pmask) == prefix)
                atomicAdd(&hist[(key[i] >> sh) & 255u], 1u);
        __syncthreads();
        sfx[tid] = hist[tid];
        __syncthreads();
        for (int off = 1; off < 256; off <<= 1) {
            uint32_t add = (tid + off < 256) ? sfx[tid + off] : 0u;
            __syncthreads();
            sfx[tid] += add;
            __syncthreads();
        }
        if (sfx[tid] >= kk && (tid == 255 || sfx[tid + 1] < kk)) {
            s_prefix = prefix | ((uint32_t)tid << sh);
            s_k = kk - sfx[tid + 1];
        }
        __syncthreads();
        prefix = s_prefix; kk = s_k;
        __syncthreads();
    }
    const uint32_t tk = prefix;
    const float thr = (tk & 0x80000000u) ? __uint_as_float(tk ^ 0x80000000u)
                                         : __uint_as_float(~tk);

    float e[8]; float sum = 0.f;
#pragma unroll
    for (int i = 0; i < 8; i++) {
        float ev = (v[i] >= thr) ? expf(v[i] - mx) : 0.f;
        e[i] = ev; sum += ev;
    }
    red[tid] = sum; __syncthreads();
    for (int s = 128; s; s >>= 1) { if (tid < s) red[tid] += red[tid + s]; __syncthreads(); }
    float inv = 1.f / red[0];
#pragma unroll
    for (int i = 0; i < 8; i++) p[tid + i * 256] = rndf(e[i] * inv);
}

// ---------------- softmax rows of 64 ----------------
__global__ void softmax64_k(float* __restrict__ mw, int rows) {
    int row = (blockIdx.x * blockDim.x + threadIdx.x) >> 5;
    int lane = threadIdx.x & 31;
    if (row >= rows) return;
    float* p = mw + (long long)row * 64;
    float a = p[lane], b = p[lane + 32];
    float mx = fmaxf(a, b);
    for (int o = 16; o; o >>= 1) mx = fmaxf(mx, __shfl_xor_sync(0xffffffffu, mx, o));
    float ea = expf(a - mx), eb = expf(b - mx);
    float s = ea + eb;
    for (int o = 16; o; o >>= 1) s += __shfl_xor_sync(0xffffffffu, s, o);
    float inv = 1.f / s;
    p[lane] = ea * inv; p[lane + 32] = eb * inv;
}

// ---------------- router ----------------
__global__ void router_k(const float* __restrict__ x2, const float* __restrict__ Wr,
                         const float* __restrict__ br, float* __restrict__ rw, int rows) {
    int tok = (blockIdx.x * blockDim.x + threadIdx.x) >> 5;
    int lane = threadIdx.x & 31;
    if (tok >= rows) return;
    const float* xr = x2 + (long long)tok * D_;
    float s0 = 0.f, s1 = 0.f, s2 = 0.f, s3 = 0.f;
    for (int d = lane; d < D_; d += 32) {
        float xv = xr[d];
        const float* w = Wr + d * 4;
        s0 += xv * w[0]; s1 += xv * w[1]; s2 += xv * w[2]; s3 += xv * w[3];
    }
    for (int o = 16; o; o >>= 1) {
        s0 += __shfl_xor_sync(0xffffffffu, s0, o);
        s1 += __shfl_xor_sync(0xffffffffu, s1, o);
        s2 += __shfl_xor_sync(0xffffffffu, s2, o);
        s3 += __shfl_xor_sync(0xffffffffu, s3, o);
    }
    if (lane == 0) {
        s0 += br[0]; s1 += br[1]; s2 += br[2]; s3 += br[3];
        float mx = fmaxf(fmaxf(s0, s1), fmaxf(s2, s3));
        float e0 = expf(s0 - mx), e1 = expf(s1 - mx), e2 = expf(s2 - mx), e3 = expf(s3 - mx);
        float inv = 1.f / (e0 + e1 + e2 + e3);
        float* o4 = rw + (long long)tok * 4;
        o4[0] = e0 * inv; o4[1] = e1 * inv; o4[2] = e2 * inv; o4[3] = e3 * inv;
    }
}

// ---------------- launch ----------------
extern "C" void kernel_launch(void* const* d_in, const int* in_sizes, int n_in,
                              void* d_out, int out_size) {
    const float* x     = (const float*)d_in[0];
    const float* WqkvL = (const float*)d_in[1];
    const float* WqkvS = (const float*)d_in[2];
    const float* memb  = (const float*)d_in[3];
    const float* Wm    = (const float*)d_in[4];
    const float* Wo    = (const float*)d_in[5];
    const float* bo    = (const float*)d_in[6];
    const float* Wi    = (const float*)d_in[7];
    const float* bi    = (const float*)d_in[8];
    const float* Wp1   = (const float*)d_in[9];
    const float* bp1   = (const float*)d_in[10];
    const float* Wp2   = (const float*)d_in[11];
    const float* bp2   = (const float*)d_in[12];
    const float* Wwb   = (const float*)d_in[13];
    const float* bwb   = (const float*)d_in[14];
    const float* Wr    = (const float*)d_in[15];
    const float* br    = (const float*)d_in[16];
    const float* We1   = (const float*)d_in[17];
    const float* be1   = (const float*)d_in[18];
    const float* We2   = (const float*)d_in[19];
    const float* be2   = (const float*)d_in[20];
    float* out = (float*)d_out;

    float *qkvL, *qkvS, *sc, *mc, *mcr, *mw, *hy, *x2, *x2r, *xr, *pp, *tt, *rw, *hh, *vtl, *vts;
    float *wqkvl_t, *wqkvs_t, *wm_t, *wo_t, *wi_t, *wp1_t, *wp2_t, *wwb_t, *we1_t, *we2_t;
    cudaGetSymbolAddress((void**)&qkvL, g_qkv_loc);
    cudaGetSymbolAddress((void**)&qkvS, g_qkv_sp);
    cudaGetSymbolAddress((void**)&sc,   g_scores);
    cudaGetSymbolAddress((void**)&mc,   g_memcat);
    cudaGetSymbolAddress((void**)&mcr,  g_mcr);
    cudaGetSymbolAddress((void**)&mw,   g_mw);
    cudaGetSymbolAddress((void**)&hy,   g_hydra);
    cudaGetSymbolAddress((void**)&x2,   g_x2);
    cudaGetSymbolAddress((void**)&x2r,  g_x2r);
    cudaGetSymbolAddress((void**)&xr,   g_xr);
    cudaGetSymbolAddress((void**)&pp,   g_pp);
    cudaGetSymbolAddress((void**)&tt,   g_t);
    cudaGetSymbolAddress((void**)&rw,   g_rw);
    cudaGetSymbolAddress((void**)&hh,   g_h);
    cudaGetSymbolAddress((void**)&vtl,  g_vtl);
    cudaGetSymbolAddress((void**)&vts,  g_vts);
    cudaGetSymbolAddress((void**)&wqkvl_t, g_wqkvl_t);
    cudaGetSymbolAddress((void**)&wqkvs_t, g_wqkvs_t);
    cudaGetSymbolAddress((void**)&wm_t,  g_wm_t);
    cudaGetSymbolAddress((void**)&wo_t,  g_wo_t);
    cudaGetSymbolAddress((void**)&wi_t,  g_wi_t);
    cudaGetSymbolAddress((void**)&wp1_t, g_wp1_t);
    cudaGetSymbolAddress((void**)&wp2_t, g_wp2_t);
    cudaGetSymbolAddress((void**)&wwb_t, g_wwb_t);
    cudaGetSymbolAddress((void**)&we1_t, g_we1_t);
    cudaGetSymbolAddress((void**)&we2_t, g_we2_t);

    const float scale = 0.0625f; // H^-0.5
    dim3 t256(256);

    // launches 1-5 (then #6 = batched score GEMM, the ncu capture target)
    roundT_k<<<dim3(768 / 32, 1024 / 32, 1), t256>>>(WqkvL, wqkvl_t, 1024, 768, 0, 0);   // 1
    roundT_k<<<dim3(768 / 32, 1024 / 32, 1), t256>>>(WqkvS, wqkvs_t, 1024, 768, 0, 0);   // 2
    round_copy_k<<<(BS_ * D_ + 255) / 256, 256>>>(x, xr, BS_ * D_);                      // 3
    tcg(0, true, xr, wqkvl_t, qkvL, BS_, 768, D_, D_, D_, 768, 0, 0, 0, 1, nullptr, nullptr, 0, 1.f); // 4
    tcg(0, true, xr, wqkvs_t, qkvS, BS_, 768, D_, D_, D_, 768, 0, 0, 0, 1, nullptr, nullptr, 0, 1.f); // 5
    tcg(0, false, qkvL, qkvL + H_, sc, S_, S_, H_, 768, 768, S_,
        (long long)S_ * 768, (long long)S_ * 768, (long long)S_ * S_, B_, nullptr, nullptr, 0, scale); // 6 <- profiled
    vtrans_k<<<dim3(S_ / 32, H_ / 32, B_), t256>>>(qkvL, vtl);
    softmax2048_k<<<BS_, 256>>>(sc);
    tcg(0, true, sc, vtl, hy, S_, H_, S_, S_, S_, 4 * H_,
        (long long)S_ * S_, (long long)H_ * S_, (long long)S_ * 4 * H_, B_, nullptr, nullptr, 0, 1.f);

    // ---- sparse attention ----
    vtrans_k<<<dim3(S_ / 32, H_ / 32, B_), t256>>>(qkvS, vts);
    tcg(0, false, qkvS, qkvS + H_, sc, S_, S_, H_, 768, 768, S_,
        (long long)S_ * 768, (long long)S_ * 768, (long long)S_ * S_, B_, nullptr, nullptr, 0, scale);
    sparse_softmax_k<<<BS_, 256>>>(sc);
    tcg(0, true, sc, vts, hy + H_, S_, H_, S_, S_, S_, 4 * H_,
        (long long)S_ * S_, (long long)H_ * S_, (long long)S_ * 4 * H_, B_, nullptr, nullptr, 0, 1.f);

    // ---- memory branch ----
    roundT_k<<<dim3(256 / 32, 1024 / 32, 1), t256>>>(Wm, wm_t, 1024, 256, 0, 0);
    roundT_k<<<dim3(256 / 32, 512 / 32, 1), t256>>>(Wo, wo_t, 512, 256, 0, 0);
    tcg(0, false, xr, wm_t, mc, BS_, H_, D_, D_, D_, 2 * H_, 0, 0, 0, 1, nullptr, nullptr, 0, 1.f);
    gemm_k<true><<<dim3(1, BS_ / 128, 1), t256>>>(mc, memb, mw, BS_, M_, H_, 2 * H_, H_, M_);
    softmax64_k<<<(BS_ * 32 + 255) / 256, 256>>>(mw, BS_);
    gemm_k<false><<<dim3(2, BS_ / 128, 1), t256>>>(mw, memb, mc + H_, BS_, H_, M_, M_, H_, 2 * H_);
    round_copy_k<<<(BS_ * 2 * H_ + 255) / 256, 256>>>(mc, mcr, BS_ * 2 * H_);
    tcg(0, true, mcr, wo_t, hy + 2 * H_, BS_, H_, 2 * H_, 2 * H_, 2 * H_, 4 * H_, 0, 0, 0, 1, bo, nullptr, 0, 1.f);

    // ---- predictor branch ----
    roundT_k<<<dim3(256 / 32, 1024 / 32, 1), t256>>>(Wi, wi_t, 1024, 256, 0, 0);
    roundT_k<<<dim3(512 / 32, 256 / 32, 1), t256>>>(Wp1, wp1_t, 256, 512, 0, 0);
    roundT_k<<<dim3(256 / 32, 512 / 32, 1), t256>>>(Wp2, wp2_t, 512, 256, 0, 0);
    roundT_k<<<dim3(1024 / 32, 1024 / 32, 1), t256>>>(Wwb, wwb_t, 1024, 1024, 0, 0);
    tcg(0, true, xr, wi_t, pp, BS_, H_, D_, D_, D_, H_, 0, 0, 0, 1, bi, nullptr, 0, 1.f);
    tcg(1, true, pp, wp1_t, tt, BS_, 2 * H_, H_, H_, H_, 2 * H_, 0, 0, 0, 1, bp1, nullptr, 0, 1.f);
    tcg(0, true, tt, wp2_t, hy + 3 * H_, BS_, H_, 2 * H_, 2 * H_, 2 * H_, 4 * H_, 0, 0, 0, 1, bp2, nullptr, 0, 1.f);

    // ---- hydra combine (fused: x2 = x + concat@Wwb + bwb; x2r = rnd(x2); out = x2) ----
    tcg(4, false, hy, wwb_t, x2, BS_, D_, 4 * H_, 4 * H_, 4 * H_, D_, 0, 0, 0, 1, bwb, nullptr, 0, 1.f,
        x, x2r, out);

    // ---- router + MoE ----
    router_k<<<(BS_ * 32 + 255) / 256, 256>>>(x2, Wr, br, rw, BS_);
    roundT_k<<<dim3(F_ / 32, D_ / 32, E_), t256>>>(We1, we1_t, D_, F_, (long long)D_ * F_, (long long)F_ * D_);
    roundT_k<<<dim3(D_ / 32, F_ / 32, E_), t256>>>(We2, we2_t, F_, D_, (long long)F_ * D_, (long long)D_ * F_);
    for (int e = 0; e < E_; e++) {
        tcg(1, true, x2r, we1_t + (long long)e * F_ * D_, hh,
            BS_, F_, D_, D_, D_, F_, 0, 0, 0, 1, be1 + (long long)e * F_, nullptr, 0, 1.f);
        tcg(3, false, hh, we2_t + (long long)e * D_ * F_, out,
            BS_, D_, F_, F_, F_, D_, 0, 0, 0, 1, be2 + (long long)e * D_, rw + e, E_, 1.f);
    }
}

// round 8
// speedup vs baseline: 3.6095x; 1.0340x over previous
#include <cuda_runtime.h>
#include <cuda_bf16.h>
#include <math.h>
#include <stdint.h>

// ---------------- problem constants ----------------
#define B_   4
#define S_   2048
#define D_   1024
#define H_   256
#define E_   4
#define F_   4096
#define M_   64
#define BS_  (B_ * S_)          // 8192
#define KSP_ 204                // int(2048*0.1)

// ---------------- scratch (device globals; no allocation allowed) ----------------
__device__ float g_qkv_loc[(size_t)BS_ * 3 * H_];
__device__ float g_qkv_sp [(size_t)BS_ * 3 * H_];
__device__ float g_scores [(size_t)B_ * S_ * S_];
__device__ float g_memcat [(size_t)BS_ * 2 * H_];
__device__ float g_mcr    [(size_t)BS_ * 2 * H_];
__device__ float g_mw     [(size_t)BS_ * M_];
__device__ float g_hydra  [(size_t)BS_ * 4 * H_];
__device__ float g_x2     [(size_t)BS_ * D_];
__device__ float g_x2r    [(size_t)BS_ * D_];
__device__ float g_xr     [(size_t)BS_ * D_];
__device__ float g_pp     [(size_t)BS_ * H_];
__device__ float g_t      [(size_t)BS_ * 2 * H_];
__device__ float g_rw     [(size_t)BS_ * E_];
__device__ float g_h      [(size_t)BS_ * F_];
__device__ float g_vtl    [(size_t)B_ * H_ * S_];
__device__ float g_vts    [(size_t)B_ * H_ * S_];
// transposed+rounded weights [N][K]
__device__ float g_wqkvl_t[(size_t)768 * 1024];
__device__ float g_wqkvs_t[(size_t)768 * 1024];
__device__ float g_wm_t   [(size_t)256 * 1024];
__device__ float g_wo_t   [(size_t)256 * 512];
__device__ float g_wi_t   [(size_t)256 * 1024];
__device__ float g_wp1_t  [(size_t)512 * 256];
__device__ float g_wp2_t  [(size_t)256 * 512];
__device__ float g_wwb_t  [(size_t)1024 * 1024];
__device__ float g_we1_t  [(size_t)E_ * F_ * D_];
__device__ float g_we2_t  [(size_t)E_ * D_ * F_];

__device__ __forceinline__ float gelu_f(float x) {
    return 0.5f * x * (1.0f + erff(x * 0.7071067811865476f));
}
__device__ __forceinline__ uint32_t f2tf32(float f) {
    uint32_t r; asm("cvt.rna.tf32.f32 %0, %1;" : "=r"(r) : "f"(f)); return r;
}
__device__ __forceinline__ float rndf(float f) { return __uint_as_float(f2tf32(f)); }
__device__ __forceinline__ void mma1688(float* c, const uint32_t* a, const uint32_t* b) {
    asm volatile("mma.sync.aligned.m16n8k8.row.col.f32.tf32.tf32.f32 "
                 "{%0,%1,%2,%3}, {%4,%5,%6,%7}, {%8,%9}, {%0,%1,%2,%3};"
                 : "+f"(c[0]), "+f"(c[1]), "+f"(c[2]), "+f"(c[3])
                 : "r"(a[0]), "r"(a[1]), "r"(a[2]), "r"(a[3]), "r"(b[0]), "r"(b[1]));
}
__device__ __forceinline__ void cp16(uint32_t dst, const void* src) {
    asm volatile("cp.async.cg.shared.global [%0], [%1], 16;" :: "r"(dst), "l"(src));
}
#define CP_COMMIT asm volatile("cp.async.commit_group;" ::: "memory")
#define CP_WAIT1  asm volatile("cp.async.wait_group 1;" ::: "memory")
#define CP_WAIT0  asm volatile("cp.async.wait_group 0;" ::: "memory")
__device__ __forceinline__ uint32_t smem_u32(const void* p) {
    uint32_t a;
    asm("{ .reg .u64 t; cvta.to.shared.u64 t, %1; cvt.u32.u64 %0, t; }" : "=r"(a) : "l"(p));
    return a;
}

// ================= tf32 warp-MMA GEMM (NT, pre-rounded, K-major) =================
// CTA tile 128x128, 8 warps (2m x 4n), warp tile 64x32, K-chunks of 32, 2-stage cp.async.
// k axis inside each 8-group permuted (logical fq <-> stored 2fq, fq+4 <-> 2fq+1) so
// fragment loads are LDS.64, conflict-free with PITCH=40 (PITCH % 32 == 8).
// 16 warps/SM (2 CTAs) hide LDS latency via warp parallelism; no frag double-buffer.
// EPI: 0 store(+bias), 1 gelu(+bias), 3 C+=rowscale*v(+bias), 4 triple-write (x2 path)
#define PITCH 40
#define KC 32
#define STAGE_W (2 * 128 * PITCH)
#define TC_SMEM (2 * STAGE_W * 4)             // 81920 bytes

template<int EPI, bool RND>
__global__ void __launch_bounds__(256, 2)
tc_gemm_k(const float* __restrict__ Ag, const float* __restrict__ Bg, float* __restrict__ Cg,
          int K, int lda, int ldb, int ldc,
          long long sA, long long sB, long long sC,
          const float* __restrict__ bias, const float* __restrict__ rowscale,
          int rs_stride, float alpha,
          const float* __restrict__ resid, float* __restrict__ aux1, float* __restrict__ aux2)
{
    extern __shared__ uint32_t sm[];
    const uint32_t smb = smem_u32(sm);
    const int tid = threadIdx.x, lane = tid & 31, wid = tid >> 5;
    const int m0 = blockIdx.y * 128, n0 = blockIdx.x * 128;
    const int wm = (wid >> 2) * 64, wn = (wid & 3) * 32;
    const int arow = tid >> 3, ac4 = (tid & 7) << 2;   // 32 rows x 8 col4 per pass

    const float* A  = Ag + blockIdx.z * sA + (long long)(m0 + arow) * lda + ac4;
    const float* Bp = Bg + blockIdx.z * sB + (long long)(n0 + arow) * ldb + ac4;
    float* C = Cg + blockIdx.z * sC;

    const uint32_t myA = smb + (uint32_t)(arow * PITCH + ac4) * 4;
    const uint32_t myB = myA + 128 * PITCH * 4;

    float acc[4][4][4];
#pragma unroll
    for (int i = 0; i < 4; i++)
#pragma unroll
        for (int j = 0; j < 4; j++)
#pragma unroll
            for (int k = 0; k < 4; k++) acc[i][j][k] = 0.f;

    const int nch = K >> 5;

    auto issue = [&](int c) {
        const int s = c & 1;
        const uint32_t sa = myA + s * (STAGE_W * 4);
        const uint32_t sb = myB + s * (STAGE_W * 4);
        const float* ga = A + c * KC;
        const float* gb = Bp + c * KC;
#pragma unroll
        for (int i = 0; i < 4; i++) {
            cp16(sa + i * (32 * PITCH * 4), ga + (long long)i * 32 * lda);
            cp16(sb + i * (32 * PITCH * 4), gb + (long long)i * 32 * ldb);
        }
    };

    issue(0); CP_COMMIT;

    const int fr = lane >> 2, fq2 = (lane & 3) << 1;   // permuted k base: 2*fq
    uint32_t af[4][4], bf[4][2];

// k-permuted fragment load: logical k {fq, fq+4} <-> stored {2fq, 2fq+1} (LDS.64)
#define LDFRAG(ks) do { \
    const int kb_ = (ks) * 8 + fq2; \
    _Pragma("unroll") \
    for (int mt = 0; mt < 4; mt++) { \
        const uint32_t* p_ = Ab + (wm + mt * 16 + fr) * PITCH + kb_; \
        uint2 lo_ = *(const uint2*)p_; \
        uint2 hi_ = *(const uint2*)(p_ + 8 * PITCH); \
        af[mt][0] = lo_.x; af[mt][1] = hi_.x; af[mt][2] = lo_.y; af[mt][3] = hi_.y; \
    } \
    _Pragma("unroll") \
    for (int nt = 0; nt < 4; nt++) { \
        uint2 v_ = *(const uint2*)(Bb + (wn + nt * 8 + fr) * PITCH + kb_); \
        bf[nt][0] = v_.x; bf[nt][1] = v_.y; \
    } \
} while (0)

#define MMASET() do { \
    _Pragma("unroll") \
    for (int mt = 0; mt < 4; mt++) \
        _Pragma("unroll") \
        for (int nt = 0; nt < 4; nt++) \
            mma1688(acc[mt][nt], af[mt], bf[nt]); \
} while (0)

    for (int c = 0; c < nch; c++) {
        if (c + 1 < nch) { issue(c + 1); CP_COMMIT; CP_WAIT1; }
        else             { CP_WAIT0; }
        __syncthreads();

        const uint32_t* Ab = sm + (c & 1) * STAGE_W;
        const uint32_t* Bb = Ab + 128 * PITCH;

        LDFRAG(0); MMASET();
        LDFRAG(1); MMASET();
        LDFRAG(2); MMASET();
        LDFRAG(3); MMASET();

        __syncthreads();   // protect this buffer before it is overwritten at c+2
    }
#undef LDFRAG
#undef MMASET

    // ---- epilogue ----
    const int cq = (lane & 3) * 2;
#pragma unroll
    for (int mt = 0; mt < 4; mt++) {
        int gr0 = m0 + wm + mt * 16 + fr;
        int gr1 = gr0 + 8;
        float rs0 = 1.f, rs1 = 1.f;
        if (EPI == 3) {
            rs0 = rowscale[(long long)gr0 * rs_stride];
            rs1 = rowscale[(long long)gr1 * rs_stride];
        }
#pragma unroll
        for (int nt = 0; nt < 4; nt++) {
            int gc = n0 + wn + nt * 8 + cq;
            float b0 = bias ? bias[gc] : 0.f;
            float b1 = bias ? bias[gc + 1] : 0.f;
            float v00 = acc[mt][nt][0] * alpha + b0;
            float v01 = acc[mt][nt][1] * alpha + b1;
            float v10 = acc[mt][nt][2] * alpha + b0;
            float v11 = acc[mt][nt][3] * alpha + b1;
            long long o0 = (long long)gr0 * ldc + gc;
            long long o1 = (long long)gr1 * ldc + gc;
            if (EPI == 1) {
                v00 = gelu_f(v00); v01 = gelu_f(v01);
                v10 = gelu_f(v10); v11 = gelu_f(v11);
            }
            if (RND) {
                v00 = rndf(v00); v01 = rndf(v01);
                v10 = rndf(v10); v11 = rndf(v11);
            }
            if (EPI == 0 || EPI == 1) {
                *(float2*)(C + o0) = make_float2(v00, v01);
                *(float2*)(C + o1) = make_float2(v10, v11);
            } else if (EPI == 3) {
                C[o0] += rs0 * v00; C[o0 + 1] += rs0 * v01;
                C[o1] += rs1 * v10; C[o1 + 1] += rs1 * v11;
            } else { // EPI 4: x2 = resid + v; aux1 = rnd(x2); aux2 = x2
                float w00 = resid[o0] + v00, w01 = resid[o0 + 1] + v01;
                float w10 = resid[o1] + v10, w11 = resid[o1 + 1] + v11;
                *(float2*)(C + o0) = make_float2(w00, w01);
                *(float2*)(C + o1) = make_float2(w10, w11);
                *(float2*)(aux1 + o0) = make_float2(rndf(w00), rndf(w01));
                *(float2*)(aux1 + o1) = make_float2(rndf(w10), rndf(w11));
                *(float2*)(aux2 + o0) = make_float2(w00, w01);
                *(float2*)(aux2 + o1) = make_float2(w10, w11);
            }
        }
    }
}

static void tcg(int epi, bool rnd,
                const float* A, const float* Bm, float* C,
                int M, int N, int K, int lda, int ldb, int ldc,
                long long sA, long long sB, long long sC, int batch,
                const float* bias, const float* rowscale, int rs_stride, float alpha,
                const float* resid = nullptr, float* aux1 = nullptr, float* aux2 = nullptr)
{
    dim3 g(N / 128, M / 128, batch), blk(256);
#define LNCH(EP, RN) do { \
    cudaFuncSetAttribute(tc_gemm_k<EP, RN>, cudaFuncAttributeMaxDynamicSharedMemorySize, TC_SMEM); \
    tc_gemm_k<EP, RN><<<g, blk, TC_SMEM>>>(A, Bm, C, K, lda, ldb, ldc, sA, sB, sC, bias, rowscale, rs_stride, alpha, resid, aux1, aux2); \
} while (0)
    if (epi == 0) { if (rnd) LNCH(0, true); else LNCH(0, false); }
    else if (epi == 1) LNCH(1, true);
    else if (epi == 3) LNCH(3, false);
    else LNCH(4, false);
#undef LNCH
}

// ================= weight round + transpose: in[K][N] -> out[N][K] (tf32-rounded) =================
__global__ void roundT_k(const float* __restrict__ in, float* __restrict__ out,
                         int K, int N, long long inS, long long outS)
{
    __shared__ float t[32][33];
    const float* ip = in + blockIdx.z * inS;
    float* op = out + blockIdx.z * outS;
    int n0 = blockIdx.x * 32, k0 = blockIdx.y * 32;
    int tx = threadIdx.x & 31, ty = threadIdx.x >> 5;
#pragma unroll
    for (int i = 0; i < 32; i += 8)
        t[ty + i][tx] = ip[(long long)(k0 + ty + i) * N + n0 + tx];
    __syncthreads();
#pragma unroll
    for (int i = 0; i < 32; i += 8)
        op[(long long)(n0 + ty + i) * K + k0 + tx] = rndf(t[tx][ty + i]);
}

__global__ void round_copy_k(const float* __restrict__ a, float* __restrict__ b, int n) {
    int i = blockIdx.x * 256 + threadIdx.x;
    if (i < n) b[i] = rndf(a[i]);
}

// v transpose: qkv [BS][768] cols 512.. -> vT [B][H][S]
__global__ void vtrans_k(const float* __restrict__ qkv, float* __restrict__ vT) {
    __shared__ float t[32][33];
    int s0 = blockIdx.x * 32, h0 = blockIdx.y * 32, b = blockIdx.z;
    int tx = threadIdx.x & 31, ty = threadIdx.x >> 5;
#pragma unroll
    for (int i = 0; i < 32; i += 8)
        t[ty + i][tx] = qkv[(long long)(b * S_ + s0 + ty + i) * 768 + 512 + h0 + tx];
    __syncthreads();
#pragma unroll
    for (int i = 0; i < 32; i += 8)
        vT[(long long)b * H_ * S_ + (long long)(h0 + ty + i) * S_ + s0 + tx] = t[tx][ty + i];
}

// ================= fallback SIMT GEMM (small fp32 shapes) =================
template<bool TRANSB>
__global__ __launch_bounds__(256, 2)
void gemm_k(const float* __restrict__ Ag, const float* __restrict__ Bg,
            float* __restrict__ Cg,
            int M, int N, int K, int lda, int ldb, int ldc)
{
    __shared__ float As[8][128];
    __shared__ float Bs[8][128];
    const float* A = Ag;
    const float* Bm = Bg;
    float* C = Cg;
    const int m0 = blockIdx.y * 128, n0 = blockIdx.x * 128;
    const int tid = threadIdx.x;
    const int tx = tid & 15, ty = tid >> 4;

    float acc[8][8];
#pragma unroll
    for (int i = 0; i < 8; i++)
#pragma unroll
        for (int j = 0; j < 8; j++) acc[i][j] = 0.f;

    const int am = tid >> 1, ak = (tid & 1) << 2;

    for (int k0 = 0; k0 < K; k0 += 8) {
        float4 av = *(const float4*)(A + (long long)(m0 + am) * lda + k0 + ak);
        As[ak + 0][am] = av.x; As[ak + 1][am] = av.y;
        As[ak + 2][am] = av.z; As[ak + 3][am] = av.w;
        if (!TRANSB) {
            int bk = tid >> 5, bn = (tid & 31) << 2;
            float4 bv = make_float4(0.f, 0.f, 0.f, 0.f);
            if (n0 + bn < N)
                bv = *(const float4*)(Bm + (long long)(k0 + bk) * ldb + n0 + bn);
            *(float4*)&Bs[bk][bn] = bv;
        } else {
            int bn = tid >> 1, bk = (tid & 1) << 2;
            float4 bv = make_float4(0.f, 0.f, 0.f, 0.f);
            if (n0 + bn < N)
                bv = *(const float4*)(Bm + (long long)(n0 + bn) * ldb + k0 + bk);
            Bs[bk + 0][bn] = bv.x; Bs[bk + 1][bn] = bv.y;
            Bs[bk + 2][bn] = bv.z; Bs[bk + 3][bn] = bv.w;
        }
        __syncthreads();
#pragma unroll
        for (int k = 0; k < 8; k++) {
            float4 a0 = *(float4*)&As[k][ty * 4];
            float4 a1 = *(float4*)&As[k][ty * 4 + 64];
            float4 b0 = *(float4*)&Bs[k][tx * 4];
            float4 b1 = *(float4*)&Bs[k][tx * 4 + 64];
            float a[8] = {a0.x, a0.y, a0.z, a0.w, a1.x, a1.y, a1.z, a1.w};
            float b[8] = {b0.x, b0.y, b0.z, b0.w, b1.x, b1.y, b1.z, b1.w};
#pragma unroll
            for (int i = 0; i < 8; i++)
#pragma unroll
                for (int j = 0; j < 8; j++) acc[i][j] += a[i] * b[j];
        }
        __syncthreads();
    }

#pragma unroll
    for (int i = 0; i < 8; i++) {
        int gr = m0 + ty * 4 + (i & 3) + ((i >> 2) << 6);
        float* Crow = C + (long long)gr * ldc;
#pragma unroll
        for (int j = 0; j < 8; j++) {
            int gc = n0 + tx * 4 + (j & 3) + ((j >> 2) << 6);
            if (gc < N) Crow[gc] = acc[i][j];
        }
    }
}

// ---------------- softmax over full rows of 2048 (rounded output) ----------------
__global__ void softmax2048_k(float* __restrict__ Sc) {
    __shared__ float red[256];
    const int tid = threadIdx.x;
    float* p = Sc + (long long)blockIdx.x * 2048;
    float v[8];
    float mx = -3.4e38f;
#pragma unroll
    for (int i = 0; i < 8; i++) { v[i] = p[tid + i * 256]; mx = fmaxf(mx, v[i]); }
    red[tid] = mx; __syncthreads();
    for (int s = 128; s; s >>= 1) { if (tid < s) red[tid] = fmaxf(red[tid], red[tid + s]); __syncthreads(); }
    mx = red[0]; __syncthreads();
    float sum = 0.f;
#pragma unroll
    for (int i = 0; i < 8; i++) { v[i] = expf(v[i] - mx); sum += v[i]; }
    red[tid] = sum; __syncthreads();
    for (int s = 128; s; s >>= 1) { if (tid < s) red[tid] += red[tid + s]; __syncthreads(); }
    float inv = 1.f / red[0];
#pragma unroll
    for (int i = 0; i < 8; i++) p[tid + i * 256] = rndf(v[i] * inv);
}

// ---------------- sparse top-k via exact radix select + masked softmax ----------------
__global__ void sparse_softmax_k(float* __restrict__ Sc) {
    __shared__ uint32_t hist[256];
    __shared__ uint32_t sfx[257];
    __shared__ uint32_t s_prefix, s_k;
    __shared__ float red[256];
    const int tid = threadIdx.x;
    float* p = Sc + (long long)blockIdx.x * 2048;

    float v[8]; uint32_t key[8];
    float mx = -3.4e38f;
#pragma unroll
    for (int i = 0; i < 8; i++) {
        v[i] = p[tid + i * 256];
        mx = fmaxf(mx, v[i]);
        uint32_t u = __float_as_uint(v[i]);
        key[i] = (u & 0x80000000u) ? ~u : (u | 0x80000000u);
    }
    red[tid] = mx; __syncthreads();
    for (int s = 128; s; s >>= 1) { if (tid < s) red[tid] = fmaxf(red[tid], red[tid + s]); __syncthreads(); }
    mx = red[0];

    uint32_t prefix = 0, kk = KSP_;
#pragma unroll 1
    for (int b = 3; b >= 0; b--) {
        const int sh = b * 8;
        const uint32_t pmask = (b == 3) ? 0u : ~((1u << (sh + 8)) - 1u);
        hist[tid] = 0;
        if (tid == 0) sfx[256] = 0;
        __syncthreads();
#pragma unroll
        for (int i = 0; i < 8; i++)
            if ((key[i] & pmask) == prefix)
                atomicAdd(&hist[(key[i] >> sh) & 255u], 1u);
        __syncthreads();
        sfx[tid] = hist[tid];
        __syncthreads();
        for (int off = 1; off < 256; off <<= 1) {
            uint32_t add = (tid + off < 256) ? sfx[tid + off] : 0u;
            __syncthreads();
            sfx[tid] += add;
            __syncthreads();
        }
        if (sfx[tid] >= kk && (tid == 255 || sfx[tid + 1] < kk)) {
            s_prefix = prefix | ((uint32_t)tid << sh);
            s_k = kk - sfx[tid + 1];
        }
        __syncthreads();
        prefix = s_prefix; kk = s_k;
        __syncthreads();
    }
    const uint32_t tk = prefix;
    const float thr = (tk & 0x80000000u) ? __uint_as_float(tk ^ 0x80000000u)
                                         : __uint_as_float(~tk);

    float e[8]; float sum = 0.f;
#pragma unroll
    for (int i = 0; i < 8; i++) {
        float ev = (v[i] >= thr) ? expf(v[i] - mx) : 0.f;
        e[i] = ev; sum += ev;
    }
    red[tid] = sum; __syncthreads();
    for (int s = 128; s; s >>= 1) { if (tid < s) red[tid] += red[tid + s]; __syncthreads(); }
    float inv = 1.f / red[0];
#pragma unroll
    for (int i = 0; i < 8; i++) p[tid + i * 256] = rndf(e[i] * inv);
}

// ---------------- softmax rows of 64 ----------------
__global__ void softmax64_k(float* __restrict__ mw, int rows) {
    int row = (blockIdx.x * blockDim.x + threadIdx.x) >> 5;
    int lane = threadIdx.x & 31;
    if (row >= rows) return;
    float* p = mw + (long long)row * 64;
    float a = p[lane], b = p[lane + 32];
    float mx = fmaxf(a, b);
    for (int o = 16; o; o >>= 1) mx = fmaxf(mx, __shfl_xor_sync(0xffffffffu, mx, o));
    float ea = expf(a - mx), eb = expf(b - mx);
    float s = ea + eb;
    for (int o = 16; o; o >>= 1) s += __shfl_xor_sync(0xffffffffu, s, o);
    float inv = 1.f / s;
    p[lane] = ea * inv; p[lane + 32] = eb * inv;
}

// ---------------- router ----------------
__global__ void router_k(const float* __restrict__ x2, const float* __restrict__ Wr,
                         const float* __restrict__ br, float* __restrict__ rw, int rows) {
    int tok = (blockIdx.x * blockDim.x + threadIdx.x) >> 5;
    int lane = threadIdx.x & 31;
    if (tok >= rows) return;
    const float* xr = x2 + (long long)tok * D_;
    float s0 = 0.f, s1 = 0.f, s2 = 0.f, s3 = 0.f;
    for (int d = lane; d < D_; d += 32) {
        float xv = xr[d];
        const float* w = Wr + d * 4;
        s0 += xv * w[0]; s1 += xv * w[1]; s2 += xv * w[2]; s3 += xv * w[3];
    }
    for (int o = 16; o; o >>= 1) {
        s0 += __shfl_xor_sync(0xffffffffu, s0, o);
        s1 += __shfl_xor_sync(0xffffffffu, s1, o);
        s2 += __shfl_xor_sync(0xffffffffu, s2, o);
        s3 += __shfl_xor_sync(0xffffffffu, s3, o);
    }
    if (lane == 0) {
        s0 += br[0]; s1 += br[1]; s2 += br[2]; s3 += br[3];
        float mx = fmaxf(fmaxf(s0, s1), fmaxf(s2, s3));
        float e0 = expf(s0 - mx), e1 = expf(s1 - mx), e2 = expf(s2 - mx), e3 = expf(s3 - mx);
        float inv = 1.f / (e0 + e1 + e2 + e3);
        float* o4 = rw + (long long)tok * 4;
        o4[0] = e0 * inv; o4[1] = e1 * inv; o4[2] = e2 * inv; o4[3] = e3 * inv;
    }
}

// ---------------- launch ----------------
extern "C" void kernel_launch(void* const* d_in, const int* in_sizes, int n_in,
                              void* d_out, int out_size) {
    const float* x     = (const float*)d_in[0];
    const float* WqkvL = (const float*)d_in[1];
    const float* WqkvS = (const float*)d_in[2];
    const float* memb  = (const float*)d_in[3];
    const float* Wm    = (const float*)d_in[4];
    const float* Wo    = (const float*)d_in[5];
    const float* bo    = (const float*)d_in[6];
    const float* Wi    = (const float*)d_in[7];
    const float* bi    = (const float*)d_in[8];
    const float* Wp1   = (const float*)d_in[9];
    const float* bp1   = (const float*)d_in[10];
    const float* Wp2   = (const float*)d_in[11];
    const float* bp2   = (const float*)d_in[12];
    const float* Wwb   = (const float*)d_in[13];
    const float* bwb   = (const float*)d_in[14];
    const float* Wr    = (const float*)d_in[15];
    const float* br    = (const float*)d_in[16];
    const float* We1   = (const float*)d_in[17];
    const float* be1   = (const float*)d_in[18];
    const float* We2   = (const float*)d_in[19];
    const float* be2   = (const float*)d_in[20];
    float* out = (float*)d_out;

    float *qkvL, *qkvS, *sc, *mc, *mcr, *mw, *hy, *x2, *x2r, *xr, *pp, *tt, *rw, *hh, *vtl, *vts;
    float *wqkvl_t, *wqkvs_t, *wm_t, *wo_t, *wi_t, *wp1_t, *wp2_t, *wwb_t, *we1_t, *we2_t;
    cudaGetSymbolAddress((void**)&qkvL, g_qkv_loc);
    cudaGetSymbolAddress((void**)&qkvS, g_qkv_sp);
    cudaGetSymbolAddress((void**)&sc,   g_scores);
    cudaGetSymbolAddress((void**)&mc,   g_memcat);
    cudaGetSymbolAddress((void**)&mcr,  g_mcr);
    cudaGetSymbolAddress((void**)&mw,   g_mw);
    cudaGetSymbolAddress((void**)&hy,   g_hydra);
    cudaGetSymbolAddress((void**)&x2,   g_x2);
    cudaGetSymbolAddress((void**)&x2r,  g_x2r);
    cudaGetSymbolAddress((void**)&xr,   g_xr);
    cudaGetSymbolAddress((void**)&pp,   g_pp);
    cudaGetSymbolAddress((void**)&tt,   g_t);
    cudaGetSymbolAddress((void**)&rw,   g_rw);
    cudaGetSymbolAddress((void**)&hh,   g_h);
    cudaGetSymbolAddress((void**)&vtl,  g_vtl);
    cudaGetSymbolAddress((void**)&vts,  g_vts);
    cudaGetSymbolAddress((void**)&wqkvl_t, g_wqkvl_t);
    cudaGetSymbolAddress((void**)&wqkvs_t, g_wqkvs_t);
    cudaGetSymbolAddress((void**)&wm_t,  g_wm_t);
    cudaGetSymbolAddress((void**)&wo_t,  g_wo_t);
    cudaGetSymbolAddress((void**)&wi_t,  g_wi_t);
    cudaGetSymbolAddress((void**)&wp1_t, g_wp1_t);
    cudaGetSymbolAddress((void**)&wp2_t, g_wp2_t);
    cudaGetSymbolAddress((void**)&wwb_t, g_wwb_t);
    cudaGetSymbolAddress((void**)&we1_t, g_we1_t);
    cudaGetSymbolAddress((void**)&we2_t, g_we2_t);

    const float scale = 0.0625f; // H^-0.5
    dim3 t256(256);

    // launches 1-5 (then #6 = batched score GEMM, the ncu capture target)
    roundT_k<<<dim3(768 / 32, 1024 / 32, 1), t256>>>(WqkvL, wqkvl_t, 1024, 768, 0, 0);   // 1
    roundT_k<<<dim3(768 / 32, 1024 / 32, 1), t256>>>(WqkvS, wqkvs_t, 1024, 768, 0, 0);   // 2
    round_copy_k<<<(BS_ * D_ + 255) / 256, 256>>>(x, xr, BS_ * D_);                      // 3
    tcg(0, true, xr, wqkvl_t, qkvL, BS_, 768, D_, D_, D_, 768, 0, 0, 0, 1, nullptr, nullptr, 0, 1.f); // 4
    tcg(0, true, xr, wqkvs_t, qkvS, BS_, 768, D_, D_, D_, 768, 0, 0, 0, 1, nullptr, nullptr, 0, 1.f); // 5
    tcg(0, false, qkvL, qkvL + H_, sc, S_, S_, H_, 768, 768, S_,
        (long long)S_ * 768, (long long)S_ * 768, (long long)S_ * S_, B_, nullptr, nullptr, 0, scale); // 6 <- profiled
    vtrans_k<<<dim3(S_ / 32, H_ / 32, B_), t256>>>(qkvL, vtl);
    softmax2048_k<<<BS_, 256>>>(sc);
    tcg(0, true, sc, vtl, hy, S_, H_, S_, S_, S_, 4 * H_,
        (long long)S_ * S_, (long long)H_ * S_, (long long)S_ * 4 * H_, B_, nullptr, nullptr, 0, 1.f);

    // ---- sparse attention ----
    vtrans_k<<<dim3(S_ / 32, H_ / 32, B_), t256>>>(qkvS, vts);
    tcg(0, false, qkvS, qkvS + H_, sc, S_, S_, H_, 768, 768, S_,
        (long long)S_ * 768, (long long)S_ * 768, (long long)S_ * S_, B_, nullptr, nullptr, 0, scale);
    sparse_softmax_k<<<BS_, 256>>>(sc);
    tcg(0, true, sc, vts, hy + H_, S_, H_, S_, S_, S_, 4 * H_,
        (long long)S_ * S_, (long long)H_ * S_, (long long)S_ * 4 * H_, B_, nullptr, nullptr, 0, 1.f);

    // ---- memory branch ----
    roundT_k<<<dim3(256 / 32, 1024 / 32, 1), t256>>>(Wm, wm_t, 1024, 256, 0, 0);
    roundT_k<<<dim3(256 / 32, 512 / 32, 1), t256>>>(Wo, wo_t, 512, 256, 0, 0);
    tcg(0, false, xr, wm_t, mc, BS_, H_, D_, D_, D_, 2 * H_, 0, 0, 0, 1, nullptr, nullptr, 0, 1.f);
    gemm_k<true><<<dim3(1, BS_ / 128, 1), t256>>>(mc, memb, mw, BS_, M_, H_, 2 * H_, H_, M_);
    softmax64_k<<<(BS_ * 32 + 255) / 256, 256>>>(mw, BS_);
    gemm_k<false><<<dim3(2, BS_ / 128, 1), t256>>>(mw, memb, mc + H_, BS_, H_, M_, M_, H_, 2 * H_);
    round_copy_k<<<(BS_ * 2 * H_ + 255) / 256, 256>>>(mc, mcr, BS_ * 2 * H_);
    tcg(0, true, mcr, wo_t, hy + 2 * H_, BS_, H_, 2 * H_, 2 * H_, 2 * H_, 4 * H_, 0, 0, 0, 1, bo, nullptr, 0, 1.f);

    // ---- predictor branch ----
    roundT_k<<<dim3(256 / 32, 1024 / 32, 1), t256>>>(Wi, wi_t, 1024, 256, 0, 0);
    roundT_k<<<dim3(512 / 32, 256 / 32, 1), t256>>>(Wp1, wp1_t, 256, 512, 0, 0);
    roundT_k<<<dim3(256 / 32, 512 / 32, 1), t256>>>(Wp2, wp2_t, 512, 256, 0, 0);
    roundT_k<<<dim3(1024 / 32, 1024 / 32, 1), t256>>>(Wwb, wwb_t, 1024, 1024, 0, 0);
    tcg(0, true, xr, wi_t, pp, BS_, H_, D_, D_, D_, H_, 0, 0, 0, 1, bi, nullptr, 0, 1.f);
    tcg(1, true, pp, wp1_t, tt, BS_, 2 * H_, H_, H_, H_, 2 * H_, 0, 0, 0, 1, bp1, nullptr, 0, 1.f);
    tcg(0, true, tt, wp2_t, hy + 3 * H_, BS_, H_, 2 * H_, 2 * H_, 2 * H_, 4 * H_, 0, 0, 0, 1, bp2, nullptr, 0, 1.f);

    // ---- hydra combine (fused: x2 = x + concat@Wwb + bwb; x2r = rnd(x2); out = x2) ----
    tcg(4, false, hy, wwb_t, x2, BS_, D_, 4 * H_, 4 * H_, 4 * H_, D_, 0, 0, 0, 1, bwb, nullptr, 0, 1.f,
        x, x2r, out);

    // ---- router + MoE ----
    router_k<<<(BS_ * 32 + 255) / 256, 256>>>(x2, Wr, br, rw, BS_);
    roundT_k<<<dim3(F_ / 32, D_ / 32, E_), t256>>>(We1, we1_t, D_, F_, (long long)D_ * F_, (long long)F_ * D_);
    roundT_k<<<dim3(D_ / 32, F_ / 32, E_), t256>>>(We2, we2_t, F_, D_, (long long)F_ * D_, (long long)D_ * F_);
    for (int e = 0; e < E_; e++) {
        tcg(1, true, x2r, we1_t + (long long)e * F_ * D_, hh,
            BS_, F_, D_, D_, D_, F_, 0, 0, 0, 1, be1 + (long long)e * F_, nullptr, 0, 1.f);
        tcg(3, false, hh, we2_t + (long long)e * D_ * F_, out,
            BS_, D_, F_, F_, F_, D_, 0, 0, 0, 1, be2 + (long long)e * D_, rw + e, E_, 1.f);
    }
}

// round 9
// speedup vs baseline: 5.8871x; 1.6310x over previous
#include <cuda_runtime.h>
#include <cuda_fp16.h>
#include <math.h>
#include <stdint.h>

// ---------------- problem constants ----------------
#define B_   4
#define S_   2048
#define D_   1024
#define H_   256
#define E_   4
#define F_   4096
#define M_   64
#define BS_  (B_ * S_)          // 8192
#define KSP_ 204                // int(2048*0.1)

// ---------------- scratch (device globals; no allocation allowed) ----------------
// fp32 buffers
__device__ float g_scores [(size_t)B_ * S_ * S_];
__device__ float g_memcat [(size_t)BS_ * 2 * H_];
__device__ float g_mw     [(size_t)BS_ * M_];
__device__ float g_x2     [(size_t)BS_ * D_];
__device__ float g_rw     [(size_t)BS_ * E_];
// f16 GEMM operand buffers
__device__ __half h_xr    [(size_t)BS_ * D_];
__device__ __half h_qkvl  [(size_t)BS_ * 768];
__device__ __half h_qkvs  [(size_t)BS_ * 768];
__device__ __half h_sch   [(size_t)B_ * S_ * S_];
__device__ __half h_vtl   [(size_t)B_ * H_ * S_];
__device__ __half h_vts   [(size_t)B_ * H_ * S_];
__device__ __half h_hy    [(size_t)BS_ * 4 * H_];
__device__ __half h_mcr   [(size_t)BS_ * 2 * H_];
__device__ __half h_pp    [(size_t)BS_ * H_];
__device__ __half h_tt    [(size_t)BS_ * 2 * H_];
__device__ __half h_x2r   [(size_t)BS_ * D_];
__device__ __half h_hh    [(size_t)BS_ * F_];
// f16 transposed weights [N][K]
__device__ __half h_wqkvl [(size_t)768 * 1024];
__device__ __half h_wqkvs [(size_t)768 * 1024];
__device__ __half h_wm    [(size_t)256 * 1024];
__device__ __half h_wo    [(size_t)256 * 512];
__device__ __half h_wi    [(size_t)256 * 1024];
__device__ __half h_wp1   [(size_t)512 * 256];
__device__ __half h_wp2   [(size_t)256 * 512];
__device__ __half h_wwb   [(size_t)1024 * 1024];
__device__ __half h_we1   [(size_t)E_ * F_ * D_];
__device__ __half h_we2   [(size_t)E_ * D_ * F_];

__device__ __forceinline__ float gelu_f(float x) {
    return 0.5f * x * (1.0f + erff(x * 0.7071067811865476f));
}
__device__ __forceinline__ void mmaf16(float* c, const uint32_t* a, const uint32_t* b) {
    asm volatile("mma.sync.aligned.m16n8k16.row.col.f32.f16.f16.f32 "
                 "{%0,%1,%2,%3}, {%4,%5,%6,%7}, {%8,%9}, {%0,%1,%2,%3};"
                 : "+f"(c[0]), "+f"(c[1]), "+f"(c[2]), "+f"(c[3])
                 : "r"(a[0]), "r"(a[1]), "r"(a[2]), "r"(a[3]), "r"(b[0]), "r"(b[1]));
}
__device__ __forceinline__ void cp16(uint32_t dst, const void* src) {
    asm volatile("cp.async.cg.shared.global [%0], [%1], 16;" :: "r"(dst), "l"(src));
}
#define CP_COMMIT asm volatile("cp.async.commit_group;" ::: "memory")
#define CP_WAIT1  asm volatile("cp.async.wait_group 1;" ::: "memory")
#define CP_WAIT0  asm volatile("cp.async.wait_group 0;" ::: "memory")
__device__ __forceinline__ uint32_t smem_u32(const void* p) {
    uint32_t a;
    asm("{ .reg .u64 t; cvta.to.shared.u64 t, %1; cvt.u32.u64 %0, t; }" : "=r"(a) : "l"(p));
    return a;
}

// ================= f16 warp-MMA GEMM (NT, K-major halves) =================
// CTA tile 128x128, 8 warps (2m x 4n), warp tile 64x32, K-chunks of 64 halves,
// 2-stage cp.async, m16n8k16 f16 MMA, fp32 accumulate.
// Row pitch = 72 halves = 36 words (fr*36+fq mod 32 covers all banks: conflict-free).
// EPI: 0 fp32 store(+bias), 1 f16 store(+bias), 2 f16 gelu(+bias),
//      3 fp32 C+=rowscale*v(+bias), 4 triple-write (x2 path)
#define PITCHW 36
#define KC 64
#define STAGE_W (2 * 128 * PITCHW)
#define TC_SMEM (2 * STAGE_W * 4)             // 73728 bytes

template<int EPI>
__global__ void __launch_bounds__(256, 2)
tc_gemm_k(const __half* __restrict__ Ag, const __half* __restrict__ Bg, void* __restrict__ Cg,
          int K, int lda, int ldb, int ldc,
          long long sA, long long sB, long long sC,
          const float* __restrict__ bias, const float* __restrict__ rowscale,
          int rs_stride, float alpha,
          const float* __restrict__ resid, __half* __restrict__ aux1, float* __restrict__ aux2)
{
    extern __shared__ uint32_t sm[];
    const uint32_t smb = smem_u32(sm);
    const int tid = threadIdx.x, lane = tid & 31, wid = tid >> 5;
    const int m0 = blockIdx.y * 128, n0 = blockIdx.x * 128;
    const int wm = (wid >> 2) * 64, wn = (wid & 3) * 32;
    const int crow = tid >> 3, seg = tid & 7;   // 32 rows x 8 segs of 16B per pass

    const __half* A  = Ag + blockIdx.z * sA + (long long)(m0 + crow) * lda + seg * 8;
    const __half* Bp = Bg + blockIdx.z * sB + (long long)(n0 + crow) * ldb + seg * 8;

    const uint32_t myA = smb + (uint32_t)(crow * 144 + seg * 16);
    const uint32_t myB = myA + 128 * 144;

    float acc[4][4][4];
#pragma unroll
    for (int i = 0; i < 4; i++)
#pragma unroll
        for (int j = 0; j < 4; j++)
#pragma unroll
            for (int k = 0; k < 4; k++) acc[i][j][k] = 0.f;

    const int nch = K >> 6;

    auto issue = [&](int c) {
        const int s = c & 1;
        const uint32_t sa = myA + s * (STAGE_W * 4);
        const uint32_t sb = myB + s * (STAGE_W * 4);
        const __half* ga = A + c * KC;
        const __half* gb = Bp + c * KC;
#pragma unroll
        for (int i = 0; i < 4; i++) {
            cp16(sa + i * (32 * 144), ga + (long long)i * 32 * lda);
            cp16(sb + i * (32 * 144), gb + (long long)i * 32 * ldb);
        }
    };

    issue(0); CP_COMMIT;

    const int fr = lane >> 2, fq = lane & 3;
    uint32_t af[4][4], bf[4][2];

// fragment load for kstep ks (16 halves = 8 words; a: words fq, fq+4 at rows fr, fr+8)
#define LDFRAG(ks) do { \
    const int kw_ = (ks) * 8 + fq; \
    _Pragma("unroll") \
    for (int mt = 0; mt < 4; mt++) { \
        const uint32_t* p_ = Ab + (wm + mt * 16 + fr) * PITCHW + kw_; \
        af[mt][0] = p_[0]; af[mt][1] = p_[8 * PITCHW]; \
        af[mt][2] = p_[4]; af[mt][3] = p_[8 * PITCHW + 4]; \
    } \
    _Pragma("unroll") \
    for (int nt = 0; nt < 4; nt++) { \
        const uint32_t* q_ = Bb + (wn + nt * 8 + fr) * PITCHW + kw_; \
        bf[nt][0] = q_[0]; bf[nt][1] = q_[4]; \
    } \
} while (0)

#define MMASET() do { \
    _Pragma("unroll") \
    for (int mt = 0; mt < 4; mt++) \
        _Pragma("unroll") \
        for (int nt = 0; nt < 4; nt++) \
            mmaf16(acc[mt][nt], af[mt], bf[nt]); \
} while (0)

    for (int c = 0; c < nch; c++) {
        if (c + 1 < nch) { issue(c + 1); CP_COMMIT; CP_WAIT1; }
        else             { CP_WAIT0; }
        __syncthreads();

        const uint32_t* Ab = sm + (c & 1) * STAGE_W;
        const uint32_t* Bb = Ab + 128 * PITCHW;

        LDFRAG(0); MMASET();
        LDFRAG(1); MMASET();
        LDFRAG(2); MMASET();
        LDFRAG(3); MMASET();

        __syncthreads();
    }
#undef LDFRAG
#undef MMASET

    // ---- epilogue ----
    const int cq = (lane & 3) * 2;
#pragma unroll
    for (int mt = 0; mt < 4; mt++) {
        int gr0 = m0 + wm + mt * 16 + fr;
        int gr1 = gr0 + 8;
        float rs0 = 1.f, rs1 = 1.f;
        if (EPI == 3) {
            rs0 = rowscale[(long long)gr0 * rs_stride];
            rs1 = rowscale[(long long)gr1 * rs_stride];
        }
#pragma unroll
        for (int nt = 0; nt < 4; nt++) {
            int gc = n0 + wn + nt * 8 + cq;
            float b0 = bias ? bias[gc] : 0.f;
            float b1 = bias ? bias[gc + 1] : 0.f;
            float v00 = acc[mt][nt][0] * alpha + b0;
            float v01 = acc[mt][nt][1] * alpha + b1;
            float v10 = acc[mt][nt][2] * alpha + b0;
            float v11 = acc[mt][nt][3] * alpha + b1;
            long long o0 = (long long)gr0 * ldc + gc;
            long long o1 = (long long)gr1 * ldc + gc;
            if (EPI == 2) {
                v00 = gelu_f(v00); v01 = gelu_f(v01);
                v10 = gelu_f(v10); v11 = gelu_f(v11);
            }
            if (EPI == 0) {
                float* C = (float*)Cg + blockIdx.z * sC;
                *(float2*)(C + o0) = make_float2(v00, v01);
                *(float2*)(C + o1) = make_float2(v10, v11);
            } else if (EPI == 1 || EPI == 2) {
                __half* C = (__half*)Cg + blockIdx.z * sC;
                *(__half2*)(C + o0) = __floats2half2_rn(v00, v01);
                *(__half2*)(C + o1) = __floats2half2_rn(v10, v11);
            } else if (EPI == 3) {
                float* C = (float*)Cg + blockIdx.z * sC;
                C[o0] += rs0 * v00; C[o0 + 1] += rs0 * v01;
                C[o1] += rs1 * v10; C[o1 + 1] += rs1 * v11;
            } else { // EPI 4: x2 = resid + v (fp32); aux1 = f16(x2); aux2 = x2
                float* C = (float*)Cg;
                float w00 = resid[o0] + v00, w01 = resid[o0 + 1] + v01;
                float w10 = resid[o1] + v10, w11 = resid[o1 + 1] + v11;
                *(float2*)(C + o0) = make_float2(w00, w01);
                *(float2*)(C + o1) = make_float2(w10, w11);
                *(__half2*)(aux1 + o0) = __floats2half2_rn(w00, w01);
                *(__half2*)(aux1 + o1) = __floats2half2_rn(w10, w11);
                *(float2*)(aux2 + o0) = make_float2(w00, w01);
                *(float2*)(aux2 + o1) = make_float2(w10, w11);
            }
        }
    }
}

static void tcg(int epi,
                const __half* A, const __half* Bm, void* C,
                int M, int N, int K, int lda, int ldb, int ldc,
                long long sA, long long sB, long long sC, int batch,
                const float* bias, const float* rowscale, int rs_stride, float alpha,
                const float* resid = nullptr, __half* aux1 = nullptr, float* aux2 = nullptr)
{
    dim3 g(N / 128, M / 128, batch), blk(256);
#define LNCH(EP) do { \
    cudaFuncSetAttribute(tc_gemm_k<EP>, cudaFuncAttributeMaxDynamicSharedMemorySize, TC_SMEM); \
    tc_gemm_k<EP><<<g, blk, TC_SMEM>>>(A, Bm, C, K, lda, ldb, ldc, sA, sB, sC, bias, rowscale, rs_stride, alpha, resid, aux1, aux2); \
} while (0)
    if (epi == 0) LNCH(0);
    else if (epi == 1) LNCH(1);
    else if (epi == 2) LNCH(2);
    else if (epi == 3) LNCH(3);
    else LNCH(4);
#undef LNCH
}

// ================= weight transpose + f16 convert: in[K][N] fp32 -> out[N][K] f16 =================
__global__ void roundTh_k(const float* __restrict__ in, __half* __restrict__ out,
                          int K, int N, long long inS, long long outS)
{
    __shared__ float t[32][33];
    const float* ip = in + blockIdx.z * inS;
    __half* op = out + blockIdx.z * outS;
    int n0 = blockIdx.x * 32, k0 = blockIdx.y * 32;
    int tx = threadIdx.x & 31, ty = threadIdx.x >> 5;
#pragma unroll
    for (int i = 0; i < 32; i += 8)
        t[ty + i][tx] = ip[(long long)(k0 + ty + i) * N + n0 + tx];
    __syncthreads();
#pragma unroll
    for (int i = 0; i < 32; i += 8)
        op[(long long)(n0 + ty + i) * K + k0 + tx] = __float2half_rn(t[tx][ty + i]);
}

__global__ void cvtH_k(const float* __restrict__ a, __half* __restrict__ b, int n) {
    int i = blockIdx.x * 256 + threadIdx.x;
    if (i < n) b[i] = __float2half_rn(a[i]);
}

// v transpose: qkv f16 [BS][768] cols 512.. -> vT f16 [B][H][S]
__global__ void vtrans_k(const __half* __restrict__ qkv, __half* __restrict__ vT) {
    __shared__ __half t[32][34];
    int s0 = blockIdx.x * 32, h0 = blockIdx.y * 32, b = blockIdx.z;
    int tx = threadIdx.x & 31, ty = threadIdx.x >> 5;
#pragma unroll
    for (int i = 0; i < 32; i += 8)
        t[ty + i][tx] = qkv[(long long)(b * S_ + s0 + ty + i) * 768 + 512 + h0 + tx];
    __syncthreads();
#pragma unroll
    for (int i = 0; i < 32; i += 8)
        vT[(long long)b * H_ * S_ + (long long)(h0 + ty + i) * S_ + s0 + tx] = t[tx][ty + i];
}

// ================= fallback SIMT GEMM (small fp32 shapes) =================
template<bool TRANSB>
__global__ __launch_bounds__(256, 2)
void gemm_k(const float* __restrict__ Ag, const float* __restrict__ Bg,
            float* __restrict__ Cg,
            int M, int N, int K, int lda, int ldb, int ldc)
{
    __shared__ float As[8][128];
    __shared__ float Bs[8][128];
    const float* A = Ag;
    const float* Bm = Bg;
    float* C = Cg;
    const int m0 = blockIdx.y * 128, n0 = blockIdx.x * 128;
    const int tid = threadIdx.x;
    const int tx = tid & 15, ty = tid >> 4;

    float acc[8][8];
#pragma unroll
    for (int i = 0; i < 8; i++)
#pragma unroll
        for (int j = 0; j < 8; j++) acc[i][j] = 0.f;

    const int am = tid >> 1, ak = (tid & 1) << 2;

    for (int k0 = 0; k0 < K; k0 += 8) {
        float4 av = *(const float4*)(A + (long long)(m0 + am) * lda + k0 + ak);
        As[ak + 0][am] = av.x; As[ak + 1][am] = av.y;
        As[ak + 2][am] = av.z; As[ak + 3][am] = av.w;
        if (!TRANSB) {
            int bk = tid >> 5, bn = (tid & 31) << 2;
            float4 bv = make_float4(0.f, 0.f, 0.f, 0.f);
            if (n0 + bn < N)
                bv = *(const float4*)(Bm + (long long)(k0 + bk) * ldb + n0 + bn);
            *(float4*)&Bs[bk][bn] = bv;
        } else {
            int bn = tid >> 1, bk = (tid & 1) << 2;
            float4 bv = make_float4(0.f, 0.f, 0.f, 0.f);
            if (n0 + bn < N)
                bv = *(const float4*)(Bm + (long long)(n0 + bn) * ldb + k0 + bk);
            Bs[bk + 0][bn] = bv.x; Bs[bk + 1][bn] = bv.y;
            Bs[bk + 2][bn] = bv.z; Bs[bk + 3][bn] = bv.w;
        }
        __syncthreads();
#pragma unroll
        for (int k = 0; k < 8; k++) {
            float4 a0 = *(float4*)&As[k][ty * 4];
            float4 a1 = *(float4*)&As[k][ty * 4 + 64];
            float4 b0 = *(float4*)&Bs[k][tx * 4];
            float4 b1 = *(float4*)&Bs[k][tx * 4 + 64];
            float a[8] = {a0.x, a0.y, a0.z, a0.w, a1.x, a1.y, a1.z, a1.w};
            float b[8] = {b0.x, b0.y, b0.z, b0.w, b1.x, b1.y, b1.z, b1.w};
#pragma unroll
            for (int i = 0; i < 8; i++)
#pragma unroll
                for (int j = 0; j < 8; j++) acc[i][j] += a[i] * b[j];
        }
        __syncthreads();
    }

#pragma unroll
    for (int i = 0; i < 8; i++) {
        int gr = m0 + ty * 4 + (i & 3) + ((i >> 2) << 6);
        float* Crow = C + (long long)gr * ldc;
#pragma unroll
        for (int j = 0; j < 8; j++) {
            int gc = n0 + tx * 4 + (j & 3) + ((j >> 2) << 6);
            if (gc < N) Crow[gc] = acc[i][j];
        }
    }
}

// ---------------- softmax over full rows of 2048: float in, f16 probs out ----------------
__global__ void softmax2048_k(const float* __restrict__ Sc, __half* __restrict__ P) {
    __shared__ float red[256];
    const int tid = threadIdx.x;
    const float* p = Sc + (long long)blockIdx.x * 2048;
    __half* q = P + (long long)blockIdx.x * 2048;
    float v[8];
    float mx = -3.4e38f;
#pragma unroll
    for (int i = 0; i < 8; i++) { v[i] = p[tid + i * 256]; mx = fmaxf(mx, v[i]); }
    red[tid] = mx; __syncthreads();
    for (int s = 128; s; s >>= 1) { if (tid < s) red[tid] = fmaxf(red[tid], red[tid + s]); __syncthreads(); }
    mx = red[0]; __syncthreads();
    float sum = 0.f;
#pragma unroll
    for (int i = 0; i < 8; i++) { v[i] = expf(v[i] - mx); sum += v[i]; }
    red[tid] = sum; __syncthreads();
    for (int s = 128; s; s >>= 1) { if (tid < s) red[tid] += red[tid + s]; __syncthreads(); }
    float inv = 1.f / red[0];
#pragma unroll
    for (int i = 0; i < 8; i++) q[tid + i * 256] = __float2half_rn(v[i] * inv);
}

// ---------------- sparse top-k via exact radix select + masked softmax (f16 probs out) ----------------
__global__ void sparse_softmax_k(const float* __restrict__ Sc, __half* __restrict__ P) {
    __shared__ uint32_t hist[256];
    __shared__ uint32_t sfx[257];
    __shared__ uint32_t s_prefix, s_k;
    __shared__ float red[256];
    const int tid = threadIdx.x;
    const float* p = Sc + (long long)blockIdx.x * 2048;
    __half* q = P + (long long)blockIdx.x * 2048;

    float v[8]; uint32_t key[8];
    float mx = -3.4e38f;
#pragma unroll
    for (int i = 0; i < 8; i++) {
        v[i] = p[tid + i * 256];
        mx = fmaxf(mx, v[i]);
        uint32_t u = __float_as_uint(v[i]);
        key[i] = (u & 0x80000000u) ? ~u : (u | 0x80000000u);
    }
    red[tid] = mx; __syncthreads();
    for (int s = 128; s; s >>= 1) { if (tid < s) red[tid] = fmaxf(red[tid], red[tid + s]); __syncthreads(); }
    mx = red[0];

    uint32_t prefix = 0, kk = KSP_;
#pragma unroll 1
    for (int b = 3; b >= 0; b--) {
        const int sh = b * 8;
        const uint32_t pmask = (b == 3) ? 0u : ~((1u << (sh + 8)) - 1u);
        hist[tid] = 0;
        if (tid == 0) sfx[256] = 0;
        __syncthreads();
#pragma unroll
        for (int i = 0; i < 8; i++)
            if ((key[i] & pmask) == prefix)
                atomicAdd(&hist[(key[i] >> sh) & 255u], 1u);
        __syncthreads();
        sfx[tid] = hist[tid];
        __syncthreads();
        for (int off = 1; off < 256; off <<= 1) {
            uint32_t add = (tid + off < 256) ? sfx[tid + off] : 0u;
            __syncthreads();
            sfx[tid] += add;
            __syncthreads();
        }
        if (sfx[tid] >= kk && (tid == 255 || sfx[tid + 1] < kk)) {
            s_prefix = prefix | ((uint32_t)tid << sh);
            s_k = kk - sfx[tid + 1];
        }
        __syncthreads();
        prefix = s_prefix; kk = s_k;
        __syncthreads();
    }
    const uint32_t tk = prefix;
    const float thr = (tk & 0x80000000u) ? __uint_as_float(tk ^ 0x80000000u)
                                         : __uint_as_float(~tk);

    float e[8]; float sum = 0.f;
#pragma unroll
    for (int i = 0; i < 8; i++) {
        float ev = (v[i] >= thr) ? expf(v[i] - mx) : 0.f;
        e[i] = ev; sum += ev;
    }
    red[tid] = sum; __syncthreads();
    for (int s = 128; s; s >>= 1) { if (tid < s) red[tid] += red[tid + s]; __syncthreads(); }
    float inv = 1.f / red[0];
#pragma unroll
    for (int i = 0; i < 8; i++) q[tid + i * 256] = __float2half_rn(e[i] * inv);
}

// ---------------- softmax rows of 64 ----------------
__global__ void softmax64_k(float* __restrict__ mw, int rows) {
    int row = (blockIdx.x * blockDim.x + threadIdx.x) >> 5;
    int lane = threadIdx.x & 31;
    if (row >= rows) return;
    float* p = mw + (long long)row * 64;
    float a = p[lane], b = p[lane + 32];
    float mx = fmaxf(a, b);
    for (int o = 16; o; o >>= 1) mx = fmaxf(mx, __shfl_xor_sync(0xffffffffu, mx, o));
    float ea = expf(a - mx), eb = expf(b - mx);
    float s = ea + eb;
    for (int o = 16; o; o >>= 1) s += __shfl_xor_sync(0xffffffffu, s, o);
    float inv = 1.f / s;
    p[lane] = ea * inv; p[lane + 32] = eb * inv;
}

// ---------------- router ----------------
__global__ void router_k(const float* __restrict__ x2, const float* __restrict__ Wr,
                         const float* __restrict__ br, float* __restrict__ rw, int rows) {
    int tok = (blockIdx.x * blockDim.x + threadIdx.x) >> 5;
    int lane = threadIdx.x & 31;
    if (tok >= rows) return;
    const float* xr = x2 + (long long)tok * D_;
    float s0 = 0.f, s1 = 0.f, s2 = 0.f, s3 = 0.f;
    for (int d = lane; d < D_; d += 32) {
        float xv = xr[d];
        const float* w = Wr + d * 4;
        s0 += xv * w[0]; s1 += xv * w[1]; s2 += xv * w[2]; s3 += xv * w[3];
    }
    for (int o = 16; o; o >>= 1) {
        s0 += __shfl_xor_sync(0xffffffffu, s0, o);
        s1 += __shfl_xor_sync(0xffffffffu, s1, o);
        s2 += __shfl_xor_sync(0xffffffffu, s2, o);
        s3 += __shfl_xor_sync(0xffffffffu, s3, o);
    }
    if (lane == 0) {
        s0 += br[0]; s1 += br[1]; s2 += br[2]; s3 += br[3];
        float mx = fmaxf(fmaxf(s0, s1), fmaxf(s2, s3));
        float e0 = expf(s0 - mx), e1 = expf(s1 - mx), e2 = expf(s2 - mx), e3 = expf(s3 - mx);
        float inv = 1.f / (e0 + e1 + e2 + e3);
        float* o4 = rw + (long long)tok * 4;
        o4[0] = e0 * inv; o4[1] = e1 * inv; o4[2] = e2 * inv; o4[3] = e3 * inv;
    }
}

// ---------------- launch ----------------
extern "C" void kernel_launch(void* const* d_in, const int* in_sizes, int n_in,
                              void* d_out, int out_size) {
    const float* x     = (const float*)d_in[0];
    const float* WqkvL = (const float*)d_in[1];
    const float* WqkvS = (const float*)d_in[2];
    const float* memb  = (const float*)d_in[3];
    const float* Wm    = (const float*)d_in[4];
    const float* Wo    = (const float*)d_in[5];
    const float* bo    = (const float*)d_in[6];
    const float* Wi    = (const float*)d_in[7];
    const float* bi    = (const float*)d_in[8];
    const float* Wp1   = (const float*)d_in[9];
    const float* bp1   = (const float*)d_in[10];
    const float* Wp2   = (const float*)d_in[11];
    const float* bp2   = (const float*)d_in[12];
    const float* Wwb   = (const float*)d_in[13];
    const float* bwb   = (const float*)d_in[14];
    const float* Wr    = (const float*)d_in[15];
    const float* br    = (const float*)d_in[16];
    const float* We1   = (const float*)d_in[17];
    const float* be1   = (const float*)d_in[18];
    const float* We2   = (const float*)d_in[19];
    const float* be2   = (const float*)d_in[20];
    float* out = (float*)d_out;

    float *sc, *mc, *mw, *x2, *rw;
    __half *xr, *qkvl, *qkvs, *sch, *vtl, *vts, *hy, *mcr, *pp, *tt, *x2r, *hh;
    __half *wqkvl, *wqkvs, *wm, *wo, *wi, *wp1, *wp2, *wwb, *we1, *we2;
    cudaGetSymbolAddress((void**)&sc,  g_scores);
    cudaGetSymbolAddress((void**)&mc,  g_memcat);
    cudaGetSymbolAddress((void**)&mw,  g_mw);
    cudaGetSymbolAddress((void**)&x2,  g_x2);
    cudaGetSymbolAddress((void**)&rw,  g_rw);
    cudaGetSymbolAddress((void**)&xr,  h_xr);
    cudaGetSymbolAddress((void**)&qkvl, h_qkvl);
    cudaGetSymbolAddress((void**)&qkvs, h_qkvs);
    cudaGetSymbolAddress((void**)&sch, h_sch);
    cudaGetSymbolAddress((void**)&vtl, h_vtl);
    cudaGetSymbolAddress((void**)&vts, h_vts);
    cudaGetSymbolAddress((void**)&hy,  h_hy);
    cudaGetSymbolAddress((void**)&mcr, h_mcr);
    cudaGetSymbolAddress((void**)&pp,  h_pp);
    cudaGetSymbolAddress((void**)&tt,  h_tt);
    cudaGetSymbolAddress((void**)&x2r, h_x2r);
    cudaGetSymbolAddress((void**)&hh,  h_hh);
    cudaGetSymbolAddress((void**)&wqkvl, h_wqkvl);
    cudaGetSymbolAddress((void**)&wqkvs, h_wqkvs);
    cudaGetSymbolAddress((void**)&wm,  h_wm);
    cudaGetSymbolAddress((void**)&wo,  h_wo);
    cudaGetSymbolAddress((void**)&wi,  h_wi);
    cudaGetSymbolAddress((void**)&wp1, h_wp1);
    cudaGetSymbolAddress((void**)&wp2, h_wp2);
    cudaGetSymbolAddress((void**)&wwb, h_wwb);
    cudaGetSymbolAddress((void**)&we1, h_we1);
    cudaGetSymbolAddress((void**)&we2, h_we2);

    const float scale = 0.0625f; // H^-0.5
    dim3 t256(256);

    // ---- pre-pass (launch #6 = batched score GEMM for ncu) ----
    roundTh_k<<<dim3(768 / 32, 1024 / 32, 1), t256>>>(WqkvL, wqkvl, 1024, 768, 0, 0);  // 1
    roundTh_k<<<dim3(768 / 32, 1024 / 32, 1), t256>>>(WqkvS, wqkvs, 1024, 768, 0, 0);  // 2
    cvtH_k<<<(BS_ * D_ + 255) / 256, 256>>>(x, xr, BS_ * D_);                          // 3
    tcg(1, xr, wqkvl, qkvl, BS_, 768, D_, D_, D_, 768, 0, 0, 0, 1, nullptr, nullptr, 0, 1.f); // 4
    tcg(1, xr, wqkvs, qkvs, BS_, 768, D_, D_, D_, 768, 0, 0, 0, 1, nullptr, nullptr, 0, 1.f); // 5
    tcg(0, qkvl, qkvl + H_, sc, S_, S_, H_, 768, 768, S_,
        (long long)S_ * 768, (long long)S_ * 768, (long long)S_ * S_, B_,
        nullptr, nullptr, 0, scale);                                                    // 6 <- profiled
    vtrans_k<<<dim3(S_ / 32, H_ / 32, B_), t256>>>(qkvl, vtl);
    softmax2048_k<<<BS_, 256>>>(sc, sch);
    tcg(1, sch, vtl, hy, S_, H_, S_, S_, S_, 4 * H_,
        (long long)S_ * S_, (long long)H_ * S_, (long long)S_ * 4 * H_, B_, nullptr, nullptr, 0, 1.f);

    // ---- sparse attention ----
    vtrans_k<<<dim3(S_ / 32, H_ / 32, B_), t256>>>(qkvs, vts);
    tcg(0, qkvs, qkvs + H_, sc, S_, S_, H_, 768, 768, S_,
        (long long)S_ * 768, (long long)S_ * 768, (long long)S_ * S_, B_,
        nullptr, nullptr, 0, scale);
    sparse_softmax_k<<<BS_, 256>>>(sc, sch);
    tcg(1, sch, vts, hy + H_, S_, H_, S_, S_, S_, 4 * H_,
        (long long)S_ * S_, (long long)H_ * S_, (long long)S_ * 4 * H_, B_, nullptr, nullptr, 0, 1.f);

    // ---- memory branch ----
    roundTh_k<<<dim3(256 / 32, 1024 / 32, 1), t256>>>(Wm, wm, 1024, 256, 0, 0);
    roundTh_k<<<dim3(256 / 32, 512 / 32, 1), t256>>>(Wo, wo, 512, 256, 0, 0);
    tcg(0, xr, wm, mc, BS_, H_, D_, D_, D_, 2 * H_, 0, 0, 0, 1, nullptr, nullptr, 0, 1.f);
    gemm_k<true><<<dim3(1, BS_ / 128, 1), t256>>>(mc, memb, mw, BS_, M_, H_, 2 * H_, H_, M_);
    softmax64_k<<<(BS_ * 32 + 255) / 256, 256>>>(mw, BS_);
    gemm_k<false><<<dim3(2, BS_ / 128, 1), t256>>>(mw, memb, mc + H_, BS_, H_, M_, M_, H_, 2 * H_);
    cvtH_k<<<(BS_ * 2 * H_ + 255) / 256, 256>>>(mc, mcr, BS_ * 2 * H_);
    tcg(1, mcr, wo, hy + 2 * H_, BS_, H_, 2 * H_, 2 * H_, 2 * H_, 4 * H_, 0, 0, 0, 1, bo, nullptr, 0, 1.f);

    // ---- predictor branch ----
    roundTh_k<<<dim3(256 / 32, 1024 / 32, 1), t256>>>(Wi, wi, 1024, 256, 0, 0);
    roundTh_k<<<dim3(512 / 32, 256 / 32, 1), t256>>>(Wp1, wp1, 256, 512, 0, 0);
    roundTh_k<<<dim3(256 / 32, 512 / 32, 1), t256>>>(Wp2, wp2, 512, 256, 0, 0);
    roundTh_k<<<dim3(1024 / 32, 1024 / 32, 1), t256>>>(Wwb, wwb, 1024, 1024, 0, 0);
    tcg(1, xr, wi, pp, BS_, H_, D_, D_, D_, H_, 0, 0, 0, 1, bi, nullptr, 0, 1.f);
    tcg(2, pp, wp1, tt, BS_, 2 * H_, H_, H_, H_, 2 * H_, 0, 0, 0, 1, bp1, nullptr, 0, 1.f);
    tcg(1, tt, wp2, hy + 3 * H_, BS_, H_, 2 * H_, 2 * H_, 2 * H_, 4 * H_, 0, 0, 0, 1, bp2, nullptr, 0, 1.f);

    // ---- hydra combine (fused: x2 = x + concat@Wwb + bwb; x2r = f16(x2); out = x2) ----
    tcg(4, hy, wwb, x2, BS_, D_, 4 * H_, 4 * H_, 4 * H_, D_, 0, 0, 0, 1, bwb, nullptr, 0, 1.f,
        x, x2r, out);

    // ---- router + MoE ----
    router_k<<<(BS_ * 32 + 255) / 256, 256>>>(x2, Wr, br, rw, BS_);
    roundTh_k<<<dim3(F_ / 32, D_ / 32, E_), t256>>>(We1, we1, D_, F_, (long long)D_ * F_, (long long)F_ * D_);
    roundTh_k<<<dim3(D_ / 32, F_ / 32, E_), t256>>>(We2, we2, F_, D_, (long long)F_ * D_, (long long)D_ * F_);
    for (int e = 0; e < E_; e++) {
        tcg(2, x2r, we1 + (long long)e * F_ * D_, hh,
            BS_, F_, D_, D_, D_, F_, 0, 0, 0, 1, be1 + (long long)e * F_, nullptr, 0, 1.f);
        tcg(3, hh, we2 + (long long)e * D_ * F_, out,
            BS_, D_, F_, F_, F_, D_, 0, 0, 0, 1, be2 + (long long)e * D_, rw + e, E_, 1.f);
    }
}